// round 9
// baseline (speedup 1.0000x reference)
#include <cuda_runtime.h>
#include <cuda_bf16.h>
#include <cstdint>

// ---------------------------------------------------------------------------
// Galerkin linear attention, restructured:
//   [fused] k,v = x @ w_{k,v};  instance-norm rows;  part = k-hat^T v-hat
//   dots = sum_chunks part ; A2 = blockdiag(dots)@w_out ; Wf[b]=w_q@A2[b]/n
//   out[b] = x[b] @ Wf[b] + b_out     (tf32 TC, BN=256 single-pass over x)
// ---------------------------------------------------------------------------

#define BATCH   4
#define NTOK    8192
#define DIM     256
#define HEADS   8
#define DH      64
#define INNER   512
#define TCH     128                 // tokens per fused chunk
#define NCH     (NTOK / TCH)        // 64
#define KSEG    4                   // split-K segments for Wf

__device__ float g_part[32 * NCH * DH * DH];   // 33.5 MB partial dots
__device__ float g_dots[32 * DH * DH];
__device__ float g_A2[BATCH * INNER * DIM];
__device__ float g_WfP[KSEG * BATCH * DIM * DIM];
__device__ float g_Wf[BATCH * DIM * DIM];

__device__ __forceinline__ uint32_t f2tf32(float f) {
    uint32_t r;
    asm("cvt.rna.tf32.f32 %0, %1;" : "=r"(r) : "f"(f));
    return r;
}

// round-to-nearest tf32 split via integer ops (ALU pipe, not convert pipe)
__device__ __forceinline__ void split_tf32(float f, uint32_t& hi, uint32_t& lo) {
    uint32_t b = __float_as_uint(f);
    hi = (b + 0x1000u) & 0xFFFFE000u;
    lo = __float_as_uint(f - __uint_as_float(hi));
}

__device__ __forceinline__ void mma_tf32(float* d, const uint32_t* a, const uint32_t* b) {
    asm volatile(
        "mma.sync.aligned.m16n8k8.row.col.f32.tf32.tf32.f32 "
        "{%0,%1,%2,%3}, {%4,%5,%6,%7}, {%8,%9}, {%0,%1,%2,%3};"
        : "+f"(d[0]), "+f"(d[1]), "+f"(d[2]), "+f"(d[3])
        : "r"(a[0]), "r"(a[1]), "r"(a[2]), "r"(a[3]), "r"(b[0]), "r"(b[1]));
}

// ===========================================================================
// Fused: k/v projection (tf32 mma) + in-register instance norm + split-tf32
// partial dots. grid(NCH, 32), 256 threads, dynamic smem.
// smem layout: staging (As|Bk|Bv, 35840 B) is ALIASED by sk/sv (73728 B);
// staging is dead after phase 1 (guarded by __syncthreads).
// ===========================================================================
#define PA 136     // As pitch (8*tg+g conflict-free)
#define PB 72      // Bk/Bv pitch
#define PS 72      // sk/sv pitch
#define FUSED_SMEM (2 * TCH * PS * 4)   // 73728 B (>= staging 35840 B)

__global__ __launch_bounds__(256) void fused_kv_dots(
    const float* __restrict__ x, const float* __restrict__ w_qkv,
    float* __restrict__ part)
{
    extern __shared__ unsigned char smraw[];
    uint32_t* As = (uint32_t*)smraw;           // [2][16][PA]  (x tile, tf32, [k][m])
    uint32_t* Bk = As + 2 * 16 * PA;           // [2][16][PB]
    uint32_t* Bv = Bk + 2 * 16 * PB;
    float* sk = (float*)smraw;                 // [TCH][PS] (aliases staging, used later)
    float* sv = sk + TCH * PS;

    const int tid = threadIdx.x;
    const int chunk = blockIdx.x, bh = blockIdx.y;
    const int b = bh >> 3, h = bh & 7;

    const float* xA  = x + ((long long)b * NTOK + (long long)chunk * TCH) * DIM;
    const float* wkp = w_qkv + INNER + h * DH;        // stride 3*INNER
    const float* wvp = w_qkv + 2 * INNER + h * DH;

    const int xRow = tid >> 1, xC = (tid & 1) * 8;    // x: 128 rows x 16 cols
    const int wR = tid >> 4, wC = (tid & 15) * 4;     // w: 16 rows x 64 cols

    const int lane = tid & 31, wid = tid >> 5;
    const int g = lane >> 2, tg = lane & 3;
    const bool isV = (wid >= 4);
    const int warpM = (isV ? wid - 4 : wid) * 32;

    float acc[2][8][4];
    #pragma unroll
    for (int i = 0; i < 2; ++i)
        #pragma unroll
        for (int j = 0; j < 8; ++j)
            #pragma unroll
            for (int c = 0; c < 4; ++c) acc[i][j][c] = 0.f;

    // ---- phase 1: k/v = x @ w (K=256, 16 tiles of 16, double-buffered) ----
    float4 pa0, pa1, pk4, pv4;
    {
        pa0 = *(const float4*)&xA[(long long)xRow * DIM + xC];
        pa1 = *(const float4*)&xA[(long long)xRow * DIM + xC + 4];
        pk4 = *(const float4*)&wkp[(long long)wR * (3 * INNER) + wC];
        pv4 = *(const float4*)&wvp[(long long)wR * (3 * INNER) + wC];
    }
    As[(xC + 0) * PA + xRow] = f2tf32(pa0.x);
    As[(xC + 1) * PA + xRow] = f2tf32(pa0.y);
    As[(xC + 2) * PA + xRow] = f2tf32(pa0.z);
    As[(xC + 3) * PA + xRow] = f2tf32(pa0.w);
    As[(xC + 4) * PA + xRow] = f2tf32(pa1.x);
    As[(xC + 5) * PA + xRow] = f2tf32(pa1.y);
    As[(xC + 6) * PA + xRow] = f2tf32(pa1.z);
    As[(xC + 7) * PA + xRow] = f2tf32(pa1.w);
    {
        uint4 uk = { f2tf32(pk4.x), f2tf32(pk4.y), f2tf32(pk4.z), f2tf32(pk4.w) };
        uint4 uv = { f2tf32(pv4.x), f2tf32(pv4.y), f2tf32(pv4.z), f2tf32(pv4.w) };
        *(uint4*)&Bk[wR * PB + wC] = uk;
        *(uint4*)&Bv[wR * PB + wC] = uv;
    }
    __syncthreads();

    const uint32_t* Bsel = isV ? Bv : Bk;

    for (int kt = 0; kt < 16; ++kt) {
        const int buf = kt & 1;
        if (kt + 1 < 16) {
            const int k0 = (kt + 1) * 16;
            pa0 = *(const float4*)&xA[(long long)xRow * DIM + k0 + xC];
            pa1 = *(const float4*)&xA[(long long)xRow * DIM + k0 + xC + 4];
            pk4 = *(const float4*)&wkp[(long long)(k0 + wR) * (3 * INNER) + wC];
            pv4 = *(const float4*)&wvp[(long long)(k0 + wR) * (3 * INNER) + wC];
        }

        #pragma unroll
        for (int kk = 0; kk < 16; kk += 8) {
            uint32_t af[2][4], bf[8][2];
            #pragma unroll
            for (int mt = 0; mt < 2; ++mt) {
                const int m = warpM + mt * 16;
                af[mt][0] = As[(buf * 16 + kk + tg) * PA + m + g];
                af[mt][1] = As[(buf * 16 + kk + tg) * PA + m + g + 8];
                af[mt][2] = As[(buf * 16 + kk + tg + 4) * PA + m + g];
                af[mt][3] = As[(buf * 16 + kk + tg + 4) * PA + m + g + 8];
            }
            #pragma unroll
            for (int nt = 0; nt < 8; ++nt) {
                bf[nt][0] = Bsel[(buf * 16 + kk + tg) * PB + nt * 8 + g];
                bf[nt][1] = Bsel[(buf * 16 + kk + tg + 4) * PB + nt * 8 + g];
            }
            #pragma unroll
            for (int mt = 0; mt < 2; ++mt)
                #pragma unroll
                for (int nt = 0; nt < 8; ++nt)
                    mma_tf32(acc[mt][nt], af[mt], bf[nt]);
        }

        if (kt + 1 < 16) {
            const int nb = 1 - buf;
            As[(nb * 16 + xC + 0) * PA + xRow] = f2tf32(pa0.x);
            As[(nb * 16 + xC + 1) * PA + xRow] = f2tf32(pa0.y);
            As[(nb * 16 + xC + 2) * PA + xRow] = f2tf32(pa0.z);
            As[(nb * 16 + xC + 3) * PA + xRow] = f2tf32(pa0.w);
            As[(nb * 16 + xC + 4) * PA + xRow] = f2tf32(pa1.x);
            As[(nb * 16 + xC + 5) * PA + xRow] = f2tf32(pa1.y);
            As[(nb * 16 + xC + 6) * PA + xRow] = f2tf32(pa1.z);
            As[(nb * 16 + xC + 7) * PA + xRow] = f2tf32(pa1.w);
            uint4 uk = { f2tf32(pk4.x), f2tf32(pk4.y), f2tf32(pk4.z), f2tf32(pk4.w) };
            uint4 uv = { f2tf32(pv4.x), f2tf32(pv4.y), f2tf32(pv4.z), f2tf32(pv4.w) };
            *(uint4*)&Bk[(nb * 16 + wR) * PB + wC] = uk;
            *(uint4*)&Bv[(nb * 16 + wR) * PB + wC] = uv;
            __syncthreads();
        }
    }

    // staging region is about to be overwritten by sk/sv.
    __syncthreads();

    // ---- phase 2: in-register instance norm (rows spread over 4 lanes tg) ----
    float* sdst = isV ? sv : sk;
    #pragma unroll
    for (int mt = 0; mt < 2; ++mt) {
        #pragma unroll
        for (int rr = 0; rr < 2; ++rr) {
            float s = 0.f, q = 0.f;
            #pragma unroll
            for (int nt = 0; nt < 8; ++nt) {
                float v0 = acc[mt][nt][2 * rr], v1 = acc[mt][nt][2 * rr + 1];
                s += v0 + v1;
                q += v0 * v0 + v1 * v1;
            }
            s += __shfl_xor_sync(0xFFFFFFFFu, s, 1);
            s += __shfl_xor_sync(0xFFFFFFFFu, s, 2);
            q += __shfl_xor_sync(0xFFFFFFFFu, q, 1);
            q += __shfl_xor_sync(0xFFFFFFFFu, q, 2);
            const float mu  = s * (1.0f / 64.0f);
            const float var = q * (1.0f / 64.0f) - mu * mu;
            const float inv = rsqrtf(var + 1e-5f);
            const int row = warpM + mt * 16 + g + rr * 8;
            #pragma unroll
            for (int nt = 0; nt < 8; ++nt) {
                float2 o = { (acc[mt][nt][2 * rr] - mu) * inv,
                             (acc[mt][nt][2 * rr + 1] - mu) * inv };
                *(float2*)&sdst[row * PS + nt * 8 + 2 * tg] = o;
            }
        }
    }
    __syncthreads();

    // ---- phase 3: partial dots = k-hat^T @ v-hat  (split tf32: hh+hl+lh) ----
    const int n0 = wid * 8;
    float d[4][4];
    #pragma unroll
    for (int mt = 0; mt < 4; ++mt)
        #pragma unroll
        for (int c = 0; c < 4; ++c) d[mt][c] = 0.f;

    for (int kk = 0; kk < TCH; kk += 8) {
        uint32_t ah[4][4], al[4][4], bhv[2], blv[2];
        #pragma unroll
        for (int mt = 0; mt < 4; ++mt) {
            const int m = mt * 16;
            float f0 = sk[(kk + tg) * PS + m + g];
            float f1 = sk[(kk + tg) * PS + m + g + 8];
            float f2 = sk[(kk + tg + 4) * PS + m + g];
            float f3 = sk[(kk + tg + 4) * PS + m + g + 8];
            split_tf32(f0, ah[mt][0], al[mt][0]);
            split_tf32(f1, ah[mt][1], al[mt][1]);
            split_tf32(f2, ah[mt][2], al[mt][2]);
            split_tf32(f3, ah[mt][3], al[mt][3]);
        }
        {
            float e0 = sv[(kk + tg) * PS + n0 + g];
            float e1 = sv[(kk + tg + 4) * PS + n0 + g];
            split_tf32(e0, bhv[0], blv[0]);
            split_tf32(e1, bhv[1], blv[1]);
        }
        #pragma unroll
        for (int mt = 0; mt < 4; ++mt) mma_tf32(d[mt], ah[mt], bhv);
        #pragma unroll
        for (int mt = 0; mt < 4; ++mt) mma_tf32(d[mt], ah[mt], blv);
        #pragma unroll
        for (int mt = 0; mt < 4; ++mt) mma_tf32(d[mt], al[mt], bhv);
    }

    float* op = part + (long long)(bh * NCH + chunk) * (DH * DH);
    #pragma unroll
    for (int mt = 0; mt < 4; ++mt) {
        const int e = mt * 16 + g;
        float2 lo = { d[mt][0], d[mt][1] };
        float2 hi = { d[mt][2], d[mt][3] };
        *(float2*)&op[e * DH + n0 + 2 * tg] = lo;
        *(float2*)&op[(e + 8) * DH + n0 + 2 * tg] = hi;
    }
}

// ===========================================================================
__global__ __launch_bounds__(256) void reduce_dots(
    const float* __restrict__ part, float* __restrict__ dots)
{
    const int bh = blockIdx.x, seg = blockIdx.y;   // grid (32,4)
    #pragma unroll
    for (int j = 0; j < 4; ++j) {
        const int idx = seg * 1024 + j * 256 + threadIdx.x;
        float s = 0.f;
        #pragma unroll 8
        for (int c = 0; c < NCH; ++c)
            s += part[(long long)(bh * NCH + c) * (DH * DH) + idx];
        dots[bh * DH * DH + idx] = s;
    }
}

// A2[b, h*64+e, j] = sum_f dots[b,h][e,f] * w_out[h*64+f, j]; grid (32, 8)
__global__ __launch_bounds__(256) void dots_wout(
    const float* __restrict__ dots, const float* __restrict__ w_out,
    float* __restrict__ A2)
{
    const int bh = blockIdx.x, jt = blockIdx.y;
    const int b = bh >> 3, h = bh & 7;
    __shared__ float sd[DH * DH];
    __shared__ float sw[DH][33];
    for (int i = threadIdx.x; i < DH * DH; i += 256) sd[i] = dots[bh * DH * DH + i];
    for (int i = threadIdx.x; i < DH * 32; i += 256) {
        const int f = i >> 5, j = i & 31;
        sw[f][j] = w_out[(h * DH + f) * DIM + jt * 32 + j];
    }
    __syncthreads();
    for (int idx = threadIdx.x; idx < DH * 32; idx += 256) {
        const int e = idx >> 5, j = idx & 31;
        float s = 0.f;
        #pragma unroll 8
        for (int f = 0; f < DH; ++f) s += sd[e * DH + f] * sw[f][j];
        A2[((long long)b * INNER + h * DH + e) * DIM + jt * 32 + j] = s;
    }
}

// ===========================================================================
// WfP[seg][b] = w_q[:, seg*128:(seg+1)*128] @ A2[b][seg*128:(seg+1)*128, :]
// ===========================================================================
__global__ __launch_bounds__(256) void wf_gemm_splitk(
    const float* __restrict__ w_qkv, const float* __restrict__ A2,
    float* __restrict__ WfP)
{
    __shared__ float sA[16][68];
    __shared__ float sB[16][68];

    const int tid = threadIdx.x;
    const int m0 = blockIdx.y * 64, j0 = blockIdx.x * 64;
    const int bz = blockIdx.z;
    const int b = bz >> 2, seg = bz & 3;
    const int kbase = seg * (INNER / KSEG);

    const float* Bb = A2 + (long long)b * INNER * DIM;

    const int am = tid >> 2, akq = (tid & 3) * 4;
    const int bk = tid >> 4, bj = (tid & 15) * 4;
    const int ty = (tid >> 4) << 2;
    const int tx = (tid & 15) << 2;

    float acc[4][4] = {};

    for (int k0 = 0; k0 < INNER / KSEG; k0 += 16) {
        float4 a4 = *(const float4*)&w_qkv[(long long)(m0 + am) * (3 * INNER) + kbase + k0 + akq];
        sA[akq + 0][am] = a4.x;
        sA[akq + 1][am] = a4.y;
        sA[akq + 2][am] = a4.z;
        sA[akq + 3][am] = a4.w;
        float4 b4 = *(const float4*)&Bb[(long long)(kbase + k0 + bk) * DIM + j0 + bj];
        *(float4*)&sB[bk][bj] = b4;
        __syncthreads();
        #pragma unroll
        for (int kk = 0; kk < 16; ++kk) {
            float a[4], bb[4];
            #pragma unroll
            for (int i = 0; i < 4; ++i) a[i] = sA[kk][ty + i];
            #pragma unroll
            for (int j = 0; j < 4; ++j) bb[j] = sB[kk][tx + j];
            #pragma unroll
            for (int i = 0; i < 4; ++i)
                #pragma unroll
                for (int j = 0; j < 4; ++j) acc[i][j] += a[i] * bb[j];
        }
        __syncthreads();
    }

    float* C = WfP + ((long long)bz) * DIM * DIM;
    #pragma unroll
    for (int i = 0; i < 4; ++i) {
        float4 o = { acc[i][0], acc[i][1], acc[i][2], acc[i][3] };
        *(float4*)&C[(long long)(m0 + ty + i) * DIM + j0 + tx] = o;
    }
}

__global__ __launch_bounds__(256) void wf_reduce(
    const float* __restrict__ WfP, float* __restrict__ Wf)
{
    const int idx = blockIdx.x * 256 + threadIdx.x;
    const int b = idx / (DIM * DIM);
    const int r = idx % (DIM * DIM);
    float s = 0.f;
    #pragma unroll
    for (int seg = 0; seg < KSEG; ++seg)
        s += WfP[((long long)(b * KSEG + seg)) * DIM * DIM + r];
    Wf[idx] = s * (1.0f / (float)NTOK);
}

// ===========================================================================
// Final: out[b] = x[b] @ Wf[b] + b_out.  BM=64, BN=256 (full N in one pass
// over x -> 268 MB total traffic instead of 400 MB). grid (128, BATCH).
// ===========================================================================
#define PBX 260

__global__ __launch_bounds__(256) void gemm_xwf(
    const float* __restrict__ x, const float* __restrict__ Wf,
    const float* __restrict__ bias, float* __restrict__ out)
{
    __shared__ uint32_t As[2][16][68];
    __shared__ uint32_t Bs[2][16][PBX];

    const int tid = threadIdx.x;
    const int m0 = blockIdx.x * 64;
    const int b  = blockIdx.y;

    const float* A = x + (long long)b * NTOK * DIM + (long long)m0 * DIM;
    const float* B = Wf + (long long)b * DIM * DIM;
    float* C = out + (long long)b * NTOK * DIM + (long long)m0 * DIM;

    const int aRow = tid >> 2, aCol = (tid & 3) * 4;   // 64 rows x 16 cols
    const int bRow = tid >> 4, bCol = (tid & 15) * 16; // 16 rows x 256 cols

    const int lane = tid & 31, wid = tid >> 5;
    const int warpM = (wid >> 2) * 32;     // 0 or 32
    const int warpN = (wid & 3) * 64;      // 0,64,128,192
    const int g = lane >> 2, tg = lane & 3;

    float acc[2][8][4];
    #pragma unroll
    for (int i = 0; i < 2; ++i)
        #pragma unroll
        for (int j = 0; j < 8; ++j)
            #pragma unroll
            for (int c = 0; c < 4; ++c) acc[i][j][c] = 0.f;

    // prologue: tile 0
    {
        float4 a4 = *(const float4*)&A[(long long)aRow * DIM + aCol];
        As[0][aCol + 0][aRow] = f2tf32(a4.x);
        As[0][aCol + 1][aRow] = f2tf32(a4.y);
        As[0][aCol + 2][aRow] = f2tf32(a4.z);
        As[0][aCol + 3][aRow] = f2tf32(a4.w);
        #pragma unroll
        for (int i = 0; i < 4; ++i) {
            float4 b4 = *(const float4*)&B[(long long)bRow * DIM + bCol + i * 4];
            uint4 u = { f2tf32(b4.x), f2tf32(b4.y), f2tf32(b4.z), f2tf32(b4.w) };
            *(uint4*)&Bs[0][bRow][bCol + i * 4] = u;
        }
    }
    __syncthreads();

    for (int kt = 0; kt < 16; ++kt) {
        const int buf = kt & 1;
        float4 pa, pb[4];
        if (kt + 1 < 16) {
            const int k0 = (kt + 1) * 16;
            pa = *(const float4*)&A[(long long)aRow * DIM + k0 + aCol];
            #pragma unroll
            for (int i = 0; i < 4; ++i)
                pb[i] = *(const float4*)&B[(long long)(k0 + bRow) * DIM + bCol + i * 4];
        }

        #pragma unroll
        for (int kk = 0; kk < 16; kk += 8) {
            uint32_t af[2][4], bf[8][2];
            #pragma unroll
            for (int mt = 0; mt < 2; ++mt) {
                const int m = warpM + mt * 16;
                af[mt][0] = As[buf][kk + tg][m + g];
                af[mt][1] = As[buf][kk + tg][m + g + 8];
                af[mt][2] = As[buf][kk + tg + 4][m + g];
                af[mt][3] = As[buf][kk + tg + 4][m + g + 8];
            }
            #pragma unroll
            for (int nt = 0; nt < 8; ++nt) {
                const int n = warpN + nt * 8;
                bf[nt][0] = Bs[buf][kk + tg][n + g];
                bf[nt][1] = Bs[buf][kk + tg + 4][n + g];
            }
            #pragma unroll
            for (int mt = 0; mt < 2; ++mt)
                #pragma unroll
                for (int nt = 0; nt < 8; ++nt)
                    mma_tf32(acc[mt][nt], af[mt], bf[nt]);
        }

        if (kt + 1 < 16) {
            const int nb = 1 - buf;
            As[nb][aCol + 0][aRow] = f2tf32(pa.x);
            As[nb][aCol + 1][aRow] = f2tf32(pa.y);
            As[nb][aCol + 2][aRow] = f2tf32(pa.z);
            As[nb][aCol + 3][aRow] = f2tf32(pa.w);
            #pragma unroll
            for (int i = 0; i < 4; ++i) {
                uint4 u = { f2tf32(pb[i].x), f2tf32(pb[i].y),
                            f2tf32(pb[i].z), f2tf32(pb[i].w) };
                *(uint4*)&Bs[nb][bRow][bCol + i * 4] = u;
            }
            __syncthreads();
        }
    }

    #pragma unroll
    for (int mt = 0; mt < 2; ++mt) {
        const int r0 = warpM + mt * 16 + g;
        #pragma unroll
        for (int nt = 0; nt < 8; ++nt) {
            const int c0 = warpN + nt * 8 + 2 * tg;
            const float bx0 = bias[c0], bx1 = bias[c0 + 1];
            float2 lo = { acc[mt][nt][0] + bx0, acc[mt][nt][1] + bx1 };
            float2 hi = { acc[mt][nt][2] + bx0, acc[mt][nt][3] + bx1 };
            *(float2*)&C[(long long)r0 * DIM + c0] = lo;
            *(float2*)&C[(long long)(r0 + 8) * DIM + c0] = hi;
        }
    }
}

// ---------------------------------------------------------------------------
extern "C" void kernel_launch(void* const* d_in, const int* in_sizes, int n_in,
                              void* d_out, int out_size)
{
    const float* x      = (const float*)d_in[0];  // [4, 8192, 256]
    const float* w_qkv  = (const float*)d_in[1];  // [256, 1536]
    const float* w_out  = (const float*)d_in[2];  // [512, 256]
    const float* b_out  = (const float*)d_in[3];  // [256]
    float*       out    = (float*)d_out;          // [4, 8192, 256]

    float *part, *dots, *A2, *WfP, *Wf;
    cudaGetSymbolAddress((void**)&part, g_part);
    cudaGetSymbolAddress((void**)&dots, g_dots);
    cudaGetSymbolAddress((void**)&A2,   g_A2);
    cudaGetSymbolAddress((void**)&WfP,  g_WfP);
    cudaGetSymbolAddress((void**)&Wf,   g_Wf);

    cudaFuncSetAttribute(fused_kv_dots,
                         cudaFuncAttributeMaxDynamicSharedMemorySize, FUSED_SMEM);

    // 1) fused: k/v projection + instance norm + partial dots
    fused_kv_dots<<<dim3(NCH, 32), 256, FUSED_SMEM>>>(x, w_qkv, part);

    // 2) deterministic chunk reduction
    reduce_dots<<<dim3(32, 4), 256>>>(part, dots);

    // 3) A2 = blockdiag(dots) @ w_out ; Wf[b] = w_q @ A2[b] / n (split-K)
    dots_wout<<<dim3(32, 8), 256>>>(dots, w_out, A2);
    wf_gemm_splitk<<<dim3(4, 4, BATCH * KSEG), 256>>>(w_qkv, A2, WfP);
    wf_reduce<<<(BATCH * DIM * DIM) / 256, 256>>>(WfP, Wf);

    // 4) out[b] = x[b] @ Wf[b] + b_out  (BN=256, one pass over x)
    gemm_xwf<<<dim3(NTOK / 64, BATCH), 256>>>(x, Wf, b_out, out);
}

// round 10
// speedup vs baseline: 1.0945x; 1.0945x over previous
#include <cuda_runtime.h>
#include <cuda_bf16.h>
#include <cstdint>

// ---------------------------------------------------------------------------
// Galerkin linear attention, restructured:
//   [fused] k,v = x @ w_{k,v};  instance-norm rows;  part = k-hat^T v-hat
//   dots = sum_chunks part ; A2 = blockdiag(dots)@w_out ; Wf[b]=w_q@A2[b]/n
//   out[b] = x[b] @ Wf[b] + b_out     (tf32 tensor-core GEMM)
// Round-10: identical to the 292.8us champion EXCEPT fused grid is (32, NCH)
// so co-scheduled blocks share the same x chunk slice (L2 reuse across heads).
// ---------------------------------------------------------------------------

#define BATCH   4
#define NTOK    8192
#define DIM     256
#define HEADS   8
#define DH      64
#define INNER   512
#define TCH     128                 // tokens per fused chunk
#define NCH     (NTOK / TCH)        // 64
#define KSEG    4                   // split-K segments for Wf

__device__ float g_part[32 * NCH * DH * DH];   // 33.5 MB partial dots
__device__ float g_dots[32 * DH * DH];
__device__ float g_A2[BATCH * INNER * DIM];
__device__ float g_WfP[KSEG * BATCH * DIM * DIM];
__device__ float g_Wf[BATCH * DIM * DIM];

__device__ __forceinline__ uint32_t f2tf32(float f) {
    uint32_t r;
    asm("cvt.rna.tf32.f32 %0, %1;" : "=r"(r) : "f"(f));
    return r;
}

// round-to-nearest tf32 split via integer ops (ALU pipe, not convert pipe)
__device__ __forceinline__ void split_tf32(float f, uint32_t& hi, uint32_t& lo) {
    uint32_t b = __float_as_uint(f);
    hi = (b + 0x1000u) & 0xFFFFE000u;
    lo = __float_as_uint(f - __uint_as_float(hi));
}

__device__ __forceinline__ void mma_tf32(float* d, const uint32_t* a, const uint32_t* b) {
    asm volatile(
        "mma.sync.aligned.m16n8k8.row.col.f32.tf32.tf32.f32 "
        "{%0,%1,%2,%3}, {%4,%5,%6,%7}, {%8,%9}, {%0,%1,%2,%3};"
        : "+f"(d[0]), "+f"(d[1]), "+f"(d[2]), "+f"(d[3])
        : "r"(a[0]), "r"(a[1]), "r"(a[2]), "r"(a[3]), "r"(b[0]), "r"(b[1]));
}

// ===========================================================================
// Fused: k/v projection (tf32 mma) + in-register instance norm + split-tf32
// partial dots. grid(32, NCH), 256 threads, dynamic smem.
// smem layout: staging (As|Bk|Bv, 35840 B) is ALIASED by sk/sv (73728 B);
// staging is dead after phase 1 (guarded by __syncthreads).
// ===========================================================================
#define PA 136     // As pitch (8*tg+g conflict-free)
#define PB 72      // Bk/Bv pitch
#define PS 72      // sk/sv pitch
#define FUSED_SMEM (2 * TCH * PS * 4)   // 73728 B (>= staging 35840 B)

__global__ __launch_bounds__(256) void fused_kv_dots(
    const float* __restrict__ x, const float* __restrict__ w_qkv,
    float* __restrict__ part)
{
    extern __shared__ unsigned char smraw[];
    uint32_t* As = (uint32_t*)smraw;           // [2][16][PA]  (x tile, tf32, [k][m])
    uint32_t* Bk = As + 2 * 16 * PA;           // [2][16][PB]
    uint32_t* Bv = Bk + 2 * 16 * PB;
    float* sk = (float*)smraw;                 // [TCH][PS] (aliases staging, used later)
    float* sv = sk + TCH * PS;

    const int tid = threadIdx.x;
    const int bh = blockIdx.x, chunk = blockIdx.y;   // bh fastest: same-chunk blocks co-scheduled
    const int b = bh >> 3, h = bh & 7;

    const float* xA  = x + ((long long)b * NTOK + (long long)chunk * TCH) * DIM;
    const float* wkp = w_qkv + INNER + h * DH;        // stride 3*INNER
    const float* wvp = w_qkv + 2 * INNER + h * DH;

    const int xRow = tid >> 1, xC = (tid & 1) * 8;    // x: 128 rows x 16 cols
    const int wR = tid >> 4, wC = (tid & 15) * 4;     // w: 16 rows x 64 cols

    const int lane = tid & 31, wid = tid >> 5;
    const int g = lane >> 2, tg = lane & 3;
    const bool isV = (wid >= 4);
    const int warpM = (isV ? wid - 4 : wid) * 32;

    float acc[2][8][4];
    #pragma unroll
    for (int i = 0; i < 2; ++i)
        #pragma unroll
        for (int j = 0; j < 8; ++j)
            #pragma unroll
            for (int c = 0; c < 4; ++c) acc[i][j][c] = 0.f;

    // ---- phase 1: k/v = x @ w (K=256, 16 tiles of 16, double-buffered) ----
    float4 pa0, pa1, pk4, pv4;
    {
        pa0 = *(const float4*)&xA[(long long)xRow * DIM + xC];
        pa1 = *(const float4*)&xA[(long long)xRow * DIM + xC + 4];
        pk4 = *(const float4*)&wkp[(long long)wR * (3 * INNER) + wC];
        pv4 = *(const float4*)&wvp[(long long)wR * (3 * INNER) + wC];
    }
    As[(xC + 0) * PA + xRow] = f2tf32(pa0.x);
    As[(xC + 1) * PA + xRow] = f2tf32(pa0.y);
    As[(xC + 2) * PA + xRow] = f2tf32(pa0.z);
    As[(xC + 3) * PA + xRow] = f2tf32(pa0.w);
    As[(xC + 4) * PA + xRow] = f2tf32(pa1.x);
    As[(xC + 5) * PA + xRow] = f2tf32(pa1.y);
    As[(xC + 6) * PA + xRow] = f2tf32(pa1.z);
    As[(xC + 7) * PA + xRow] = f2tf32(pa1.w);
    {
        uint4 uk = { f2tf32(pk4.x), f2tf32(pk4.y), f2tf32(pk4.z), f2tf32(pk4.w) };
        uint4 uv = { f2tf32(pv4.x), f2tf32(pv4.y), f2tf32(pv4.z), f2tf32(pv4.w) };
        *(uint4*)&Bk[wR * PB + wC] = uk;
        *(uint4*)&Bv[wR * PB + wC] = uv;
    }
    __syncthreads();

    const uint32_t* Bsel = isV ? Bv : Bk;

    for (int kt = 0; kt < 16; ++kt) {
        const int buf = kt & 1;
        if (kt + 1 < 16) {
            const int k0 = (kt + 1) * 16;
            pa0 = *(const float4*)&xA[(long long)xRow * DIM + k0 + xC];
            pa1 = *(const float4*)&xA[(long long)xRow * DIM + k0 + xC + 4];
            pk4 = *(const float4*)&wkp[(long long)(k0 + wR) * (3 * INNER) + wC];
            pv4 = *(const float4*)&wvp[(long long)(k0 + wR) * (3 * INNER) + wC];
        }

        #pragma unroll
        for (int kk = 0; kk < 16; kk += 8) {
            uint32_t af[2][4], bf[8][2];
            #pragma unroll
            for (int mt = 0; mt < 2; ++mt) {
                const int m = warpM + mt * 16;
                af[mt][0] = As[(buf * 16 + kk + tg) * PA + m + g];
                af[mt][1] = As[(buf * 16 + kk + tg) * PA + m + g + 8];
                af[mt][2] = As[(buf * 16 + kk + tg + 4) * PA + m + g];
                af[mt][3] = As[(buf * 16 + kk + tg + 4) * PA + m + g + 8];
            }
            #pragma unroll
            for (int nt = 0; nt < 8; ++nt) {
                bf[nt][0] = Bsel[(buf * 16 + kk + tg) * PB + nt * 8 + g];
                bf[nt][1] = Bsel[(buf * 16 + kk + tg + 4) * PB + nt * 8 + g];
            }
            #pragma unroll
            for (int mt = 0; mt < 2; ++mt)
                #pragma unroll
                for (int nt = 0; nt < 8; ++nt)
                    mma_tf32(acc[mt][nt], af[mt], bf[nt]);
        }

        if (kt + 1 < 16) {
            const int nb = 1 - buf;
            As[(nb * 16 + xC + 0) * PA + xRow] = f2tf32(pa0.x);
            As[(nb * 16 + xC + 1) * PA + xRow] = f2tf32(pa0.y);
            As[(nb * 16 + xC + 2) * PA + xRow] = f2tf32(pa0.z);
            As[(nb * 16 + xC + 3) * PA + xRow] = f2tf32(pa0.w);
            As[(nb * 16 + xC + 4) * PA + xRow] = f2tf32(pa1.x);
            As[(nb * 16 + xC + 5) * PA + xRow] = f2tf32(pa1.y);
            As[(nb * 16 + xC + 6) * PA + xRow] = f2tf32(pa1.z);
            As[(nb * 16 + xC + 7) * PA + xRow] = f2tf32(pa1.w);
            uint4 uk = { f2tf32(pk4.x), f2tf32(pk4.y), f2tf32(pk4.z), f2tf32(pk4.w) };
            uint4 uv = { f2tf32(pv4.x), f2tf32(pv4.y), f2tf32(pv4.z), f2tf32(pv4.w) };
            *(uint4*)&Bk[(nb * 16 + wR) * PB + wC] = uk;
            *(uint4*)&Bv[(nb * 16 + wR) * PB + wC] = uv;
            __syncthreads();
        }
    }

    // staging region is about to be overwritten by sk/sv.
    __syncthreads();

    // ---- phase 2: in-register instance norm (rows spread over 4 lanes tg) ----
    float* sdst = isV ? sv : sk;
    #pragma unroll
    for (int mt = 0; mt < 2; ++mt) {
        #pragma unroll
        for (int rr = 0; rr < 2; ++rr) {
            float s = 0.f, q = 0.f;
            #pragma unroll
            for (int nt = 0; nt < 8; ++nt) {
                float v0 = acc[mt][nt][2 * rr], v1 = acc[mt][nt][2 * rr + 1];
                s += v0 + v1;
                q += v0 * v0 + v1 * v1;
            }
            s += __shfl_xor_sync(0xFFFFFFFFu, s, 1);
            s += __shfl_xor_sync(0xFFFFFFFFu, s, 2);
            q += __shfl_xor_sync(0xFFFFFFFFu, q, 1);
            q += __shfl_xor_sync(0xFFFFFFFFu, q, 2);
            const float mu  = s * (1.0f / 64.0f);
            const float var = q * (1.0f / 64.0f) - mu * mu;
            const float inv = rsqrtf(var + 1e-5f);
            const int row = warpM + mt * 16 + g + rr * 8;
            #pragma unroll
            for (int nt = 0; nt < 8; ++nt) {
                float2 o = { (acc[mt][nt][2 * rr] - mu) * inv,
                             (acc[mt][nt][2 * rr + 1] - mu) * inv };
                *(float2*)&sdst[row * PS + nt * 8 + 2 * tg] = o;
            }
        }
    }
    __syncthreads();

    // ---- phase 3: partial dots = k-hat^T @ v-hat  (split tf32: hh+hl+lh) ----
    const int n0 = wid * 8;
    float d[4][4];
    #pragma unroll
    for (int mt = 0; mt < 4; ++mt)
        #pragma unroll
        for (int c = 0; c < 4; ++c) d[mt][c] = 0.f;

    for (int kk = 0; kk < TCH; kk += 8) {
        uint32_t ah[4][4], al[4][4], bhv[2], blv[2];
        #pragma unroll
        for (int mt = 0; mt < 4; ++mt) {
            const int m = mt * 16;
            float f0 = sk[(kk + tg) * PS + m + g];
            float f1 = sk[(kk + tg) * PS + m + g + 8];
            float f2 = sk[(kk + tg + 4) * PS + m + g];
            float f3 = sk[(kk + tg + 4) * PS + m + g + 8];
            split_tf32(f0, ah[mt][0], al[mt][0]);
            split_tf32(f1, ah[mt][1], al[mt][1]);
            split_tf32(f2, ah[mt][2], al[mt][2]);
            split_tf32(f3, ah[mt][3], al[mt][3]);
        }
        {
            float e0 = sv[(kk + tg) * PS + n0 + g];
            float e1 = sv[(kk + tg + 4) * PS + n0 + g];
            split_tf32(e0, bhv[0], blv[0]);
            split_tf32(e1, bhv[1], blv[1]);
        }
        #pragma unroll
        for (int mt = 0; mt < 4; ++mt) mma_tf32(d[mt], ah[mt], bhv);
        #pragma unroll
        for (int mt = 0; mt < 4; ++mt) mma_tf32(d[mt], ah[mt], blv);
        #pragma unroll
        for (int mt = 0; mt < 4; ++mt) mma_tf32(d[mt], al[mt], bhv);
    }

    float* op = part + (long long)(bh * NCH + chunk) * (DH * DH);
    #pragma unroll
    for (int mt = 0; mt < 4; ++mt) {
        const int e = mt * 16 + g;
        float2 lo = { d[mt][0], d[mt][1] };
        float2 hi = { d[mt][2], d[mt][3] };
        *(float2*)&op[e * DH + n0 + 2 * tg] = lo;
        *(float2*)&op[(e + 8) * DH + n0 + 2 * tg] = hi;
    }
}

// ===========================================================================
__global__ __launch_bounds__(256) void reduce_dots(
    const float* __restrict__ part, float* __restrict__ dots)
{
    const int bh = blockIdx.x, seg = blockIdx.y;   // grid (32,4)
    #pragma unroll
    for (int j = 0; j < 4; ++j) {
        const int idx = seg * 1024 + j * 256 + threadIdx.x;
        float s = 0.f;
        #pragma unroll 8
        for (int c = 0; c < NCH; ++c)
            s += part[(long long)(bh * NCH + c) * (DH * DH) + idx];
        dots[bh * DH * DH + idx] = s;
    }
}

// A2[b, h*64+e, j] = sum_f dots[b,h][e,f] * w_out[h*64+f, j]; grid (32, 8)
__global__ __launch_bounds__(256) void dots_wout(
    const float* __restrict__ dots, const float* __restrict__ w_out,
    float* __restrict__ A2)
{
    const int bh = blockIdx.x, jt = blockIdx.y;
    const int b = bh >> 3, h = bh & 7;
    __shared__ float sd[DH * DH];
    __shared__ float sw[DH][33];
    for (int i = threadIdx.x; i < DH * DH; i += 256) sd[i] = dots[bh * DH * DH + i];
    for (int i = threadIdx.x; i < DH * 32; i += 256) {
        const int f = i >> 5, j = i & 31;
        sw[f][j] = w_out[(h * DH + f) * DIM + jt * 32 + j];
    }
    __syncthreads();
    for (int idx = threadIdx.x; idx < DH * 32; idx += 256) {
        const int e = idx >> 5, j = idx & 31;
        float s = 0.f;
        #pragma unroll 8
        for (int f = 0; f < DH; ++f) s += sd[e * DH + f] * sw[f][j];
        A2[((long long)b * INNER + h * DH + e) * DIM + jt * 32 + j] = s;
    }
}

// ===========================================================================
// WfP[seg][b] = w_q[:, seg*128:(seg+1)*128] @ A2[b][seg*128:(seg+1)*128, :]
// ===========================================================================
__global__ __launch_bounds__(256) void wf_gemm_splitk(
    const float* __restrict__ w_qkv, const float* __restrict__ A2,
    float* __restrict__ WfP)
{
    __shared__ float sA[16][68];
    __shared__ float sB[16][68];

    const int tid = threadIdx.x;
    const int m0 = blockIdx.y * 64, j0 = blockIdx.x * 64;
    const int bz = blockIdx.z;
    const int b = bz >> 2, seg = bz & 3;
    const int kbase = seg * (INNER / KSEG);

    const float* Bb = A2 + (long long)b * INNER * DIM;

    const int am = tid >> 2, akq = (tid & 3) * 4;
    const int bk = tid >> 4, bj = (tid & 15) * 4;
    const int ty = (tid >> 4) << 2;
    const int tx = (tid & 15) << 2;

    float acc[4][4] = {};

    for (int k0 = 0; k0 < INNER / KSEG; k0 += 16) {
        float4 a4 = *(const float4*)&w_qkv[(long long)(m0 + am) * (3 * INNER) + kbase + k0 + akq];
        sA[akq + 0][am] = a4.x;
        sA[akq + 1][am] = a4.y;
        sA[akq + 2][am] = a4.z;
        sA[akq + 3][am] = a4.w;
        float4 b4 = *(const float4*)&Bb[(long long)(kbase + k0 + bk) * DIM + j0 + bj];
        *(float4*)&sB[bk][bj] = b4;
        __syncthreads();
        #pragma unroll
        for (int kk = 0; kk < 16; ++kk) {
            float a[4], bb[4];
            #pragma unroll
            for (int i = 0; i < 4; ++i) a[i] = sA[kk][ty + i];
            #pragma unroll
            for (int j = 0; j < 4; ++j) bb[j] = sB[kk][tx + j];
            #pragma unroll
            for (int i = 0; i < 4; ++i)
                #pragma unroll
                for (int j = 0; j < 4; ++j) acc[i][j] += a[i] * bb[j];
        }
        __syncthreads();
    }

    float* C = WfP + ((long long)bz) * DIM * DIM;
    #pragma unroll
    for (int i = 0; i < 4; ++i) {
        float4 o = { acc[i][0], acc[i][1], acc[i][2], acc[i][3] };
        *(float4*)&C[(long long)(m0 + ty + i) * DIM + j0 + tx] = o;
    }
}

__global__ __launch_bounds__(256) void wf_reduce(
    const float* __restrict__ WfP, float* __restrict__ Wf)
{
    const int idx = blockIdx.x * 256 + threadIdx.x;
    const int b = idx / (DIM * DIM);
    const int r = idx % (DIM * DIM);
    float s = 0.f;
    #pragma unroll
    for (int seg = 0; seg < KSEG; ++seg)
        s += WfP[((long long)(b * KSEG + seg)) * DIM * DIM + r];
    Wf[idx] = s * (1.0f / (float)NTOK);
}

// ===========================================================================
// TF32 tensor-core GEMM for the final out = x @ Wf + b_out
// ===========================================================================
__global__ __launch_bounds__(256) void gemm_tf32(
    const float* __restrict__ A, int lda, long long sA,
    const float* __restrict__ B, int ldb, long long sB,
    float* __restrict__ C, int ldc, long long sC,
    int K, const float* __restrict__ bias, float alpha)
{
    __shared__ uint32_t As[2][16][132];
    __shared__ uint32_t Bs[2][16][132];

    const int tid = threadIdx.x;
    const int bx = blockIdx.x, by = blockIdx.y, bz = blockIdx.z;

    A += (long long)bz * sA + (long long)by * 128 * lda;
    B += (long long)bz * sB + (long long)bx * 128;
    C += (long long)bz * sC + (long long)by * 128 * ldc + (long long)bx * 128;

    const int aRow = tid >> 2, aCol = (tid & 3) << 2;
    const int bRow = tid >> 5, bCol = (tid & 31) << 2;

    const int lane = tid & 31, wid = tid >> 5;
    const int warpM = (wid >> 2) * 64;
    const int warpN = (wid & 3) * 32;
    const int g = lane >> 2, tg = lane & 3;

    float acc[4][4][4];
    #pragma unroll
    for (int i = 0; i < 4; ++i)
        #pragma unroll
        for (int j = 0; j < 4; ++j)
            #pragma unroll
            for (int c = 0; c < 4; ++c) acc[i][j][c] = 0.f;

    const int KT = K / 16;

    {
        float4 a0 = *reinterpret_cast<const float4*>(&A[(long long)aRow * lda + aCol]);
        float4 a1 = *reinterpret_cast<const float4*>(&A[(long long)(aRow + 64) * lda + aCol]);
        As[0][aCol + 0][aRow] = f2tf32(a0.x);
        As[0][aCol + 1][aRow] = f2tf32(a0.y);
        As[0][aCol + 2][aRow] = f2tf32(a0.z);
        As[0][aCol + 3][aRow] = f2tf32(a0.w);
        As[0][aCol + 0][aRow + 64] = f2tf32(a1.x);
        As[0][aCol + 1][aRow + 64] = f2tf32(a1.y);
        As[0][aCol + 2][aRow + 64] = f2tf32(a1.z);
        As[0][aCol + 3][aRow + 64] = f2tf32(a1.w);
        float4 b0 = *reinterpret_cast<const float4*>(&B[(long long)bRow * ldb + bCol]);
        float4 b1 = *reinterpret_cast<const float4*>(&B[(long long)(bRow + 8) * ldb + bCol]);
        uint4 u0 = { f2tf32(b0.x), f2tf32(b0.y), f2tf32(b0.z), f2tf32(b0.w) };
        uint4 u1 = { f2tf32(b1.x), f2tf32(b1.y), f2tf32(b1.z), f2tf32(b1.w) };
        *(uint4*)&Bs[0][bRow][bCol] = u0;
        *(uint4*)&Bs[0][bRow + 8][bCol] = u1;
    }
    __syncthreads();

    for (int kt = 0; kt < KT; ++kt) {
        const int buf = kt & 1;
        float4 pa0, pa1, pb0, pb1;
        if (kt + 1 < KT) {
            const int k0 = (kt + 1) * 16;
            pa0 = *reinterpret_cast<const float4*>(&A[(long long)aRow * lda + k0 + aCol]);
            pa1 = *reinterpret_cast<const float4*>(&A[(long long)(aRow + 64) * lda + k0 + aCol]);
            pb0 = *reinterpret_cast<const float4*>(&B[(long long)(k0 + bRow) * ldb + bCol]);
            pb1 = *reinterpret_cast<const float4*>(&B[(long long)(k0 + bRow + 8) * ldb + bCol]);
        }

        #pragma unroll
        for (int kk = 0; kk < 16; kk += 8) {
            uint32_t af[4][4], bf[4][2];
            #pragma unroll
            for (int mt = 0; mt < 4; ++mt) {
                const int m = warpM + mt * 16;
                af[mt][0] = As[buf][kk + tg][m + g];
                af[mt][1] = As[buf][kk + tg][m + g + 8];
                af[mt][2] = As[buf][kk + tg + 4][m + g];
                af[mt][3] = As[buf][kk + tg + 4][m + g + 8];
            }
            #pragma unroll
            for (int nt = 0; nt < 4; ++nt) {
                const int n = warpN + nt * 8;
                bf[nt][0] = Bs[buf][kk + tg][n + g];
                bf[nt][1] = Bs[buf][kk + tg + 4][n + g];
            }
            #pragma unroll
            for (int mt = 0; mt < 4; ++mt)
                #pragma unroll
                for (int nt = 0; nt < 4; ++nt)
                    mma_tf32(acc[mt][nt], af[mt], bf[nt]);
        }

        if (kt + 1 < KT) {
            const int nb = 1 - buf;
            As[nb][aCol + 0][aRow] = f2tf32(pa0.x);
            As[nb][aCol + 1][aRow] = f2tf32(pa0.y);
            As[nb][aCol + 2][aRow] = f2tf32(pa0.z);
            As[nb][aCol + 3][aRow] = f2tf32(pa0.w);
            As[nb][aCol + 0][aRow + 64] = f2tf32(pa1.x);
            As[nb][aCol + 1][aRow + 64] = f2tf32(pa1.y);
            As[nb][aCol + 2][aRow + 64] = f2tf32(pa1.z);
            As[nb][aCol + 3][aRow + 64] = f2tf32(pa1.w);
            uint4 u0 = { f2tf32(pb0.x), f2tf32(pb0.y), f2tf32(pb0.z), f2tf32(pb0.w) };
            uint4 u1 = { f2tf32(pb1.x), f2tf32(pb1.y), f2tf32(pb1.z), f2tf32(pb1.w) };
            *(uint4*)&Bs[nb][bRow][bCol] = u0;
            *(uint4*)&Bs[nb][bRow + 8][bCol] = u1;
            __syncthreads();
        }
    }

    #pragma unroll
    for (int mt = 0; mt < 4; ++mt) {
        const int r0 = warpM + mt * 16 + g;
        #pragma unroll
        for (int nt = 0; nt < 4; ++nt) {
            const int c0 = warpN + nt * 8 + 2 * tg;
            float bx0 = 0.f, bx1 = 0.f;
            if (bias) {
                const int gcol = blockIdx.x * 128 + c0;
                bx0 = bias[gcol];
                bx1 = bias[gcol + 1];
            }
            float2 lo = { alpha * acc[mt][nt][0] + bx0, alpha * acc[mt][nt][1] + bx1 };
            float2 hi = { alpha * acc[mt][nt][2] + bx0, alpha * acc[mt][nt][3] + bx1 };
            *reinterpret_cast<float2*>(&C[(long long)r0 * ldc + c0]) = lo;
            *reinterpret_cast<float2*>(&C[(long long)(r0 + 8) * ldc + c0]) = hi;
        }
    }
}

// ---------------------------------------------------------------------------
extern "C" void kernel_launch(void* const* d_in, const int* in_sizes, int n_in,
                              void* d_out, int out_size)
{
    const float* x      = (const float*)d_in[0];  // [4, 8192, 256]
    const float* w_qkv  = (const float*)d_in[1];  // [256, 1536]
    const float* w_out  = (const float*)d_in[2];  // [512, 256]
    const float* b_out  = (const float*)d_in[3];  // [256]
    float*       out    = (float*)d_out;          // [4, 8192, 256]

    float *part, *dots, *A2, *WfP, *Wf;
    cudaGetSymbolAddress((void**)&part, g_part);
    cudaGetSymbolAddress((void**)&dots, g_dots);
    cudaGetSymbolAddress((void**)&A2,   g_A2);
    cudaGetSymbolAddress((void**)&WfP,  g_WfP);
    cudaGetSymbolAddress((void**)&Wf,   g_Wf);

    cudaFuncSetAttribute(fused_kv_dots,
                         cudaFuncAttributeMaxDynamicSharedMemorySize, FUSED_SMEM);

    // 1) fused: k/v projection + instance norm + partial dots
    //    grid (bh fastest, chunk slow) -> co-resident blocks share x slice in L2
    fused_kv_dots<<<dim3(32, NCH), 256, FUSED_SMEM>>>(x, w_qkv, part);

    // 2) deterministic chunk reduction
    reduce_dots<<<dim3(32, 4), 256>>>(part, dots);

    // 3) A2 = blockdiag(dots) @ w_out ; Wf[b] = w_q @ A2[b] / n (split-K)
    dots_wout<<<dim3(32, 8), 256>>>(dots, w_out, A2);
    wf_gemm_splitk<<<dim3(4, 4, BATCH * KSEG), 256>>>(w_qkv, A2, WfP);
    wf_reduce<<<(BATCH * DIM * DIM) / 256, 256>>>(WfP, Wf);

    // 4) out[b] = x[b] @ Wf[b] + b_out  (tf32 TC)
    gemm_tf32<<<dim3(DIM / 128, NTOK / 128, BATCH), 256>>>(
        x, DIM, (long long)NTOK * DIM,
        Wf, DIM, (long long)DIM * DIM,
        out, DIM, (long long)NTOK * DIM,
        DIM, b_out, 1.0f);
}

// round 11
// speedup vs baseline: 1.3353x; 1.2201x over previous
#include <cuda_runtime.h>
#include <cuda_fp16.h>
#include <cuda_bf16.h>
#include <cstdint>

// ---------------------------------------------------------------------------
// Galerkin linear attention, restructured:
//   [fused] k,v = x @ w_{k,v} (fp16 m16n8k16 mma, fp32 accum);
//           in-register instance norm; partial dots (split-tf32 3-pass)
//   dots = sum_chunks part ; A2 = blockdiag(dots)@w_out ; Wf[b]=w_q@A2[b]/n
//   out[b] = x[b] @ Wf[b] + b_out     (tf32 tensor-core GEMM)
// Round-11: phase-1 tf32 k8 -> fp16 k16 (same 11-bit significand, half the
// HMMA/LDS/STS). Everything else identical to the 288.3us champion.
// ---------------------------------------------------------------------------

#define BATCH   4
#define NTOK    8192
#define DIM     256
#define HEADS   8
#define DH      64
#define INNER   512
#define TCH     128                 // tokens per fused chunk
#define NCH     (NTOK / TCH)        // 64
#define KSEG    4                   // split-K segments for Wf

__device__ float g_part[32 * NCH * DH * DH];   // 33.5 MB partial dots
__device__ float g_dots[32 * DH * DH];
__device__ float g_A2[BATCH * INNER * DIM];
__device__ float g_WfP[KSEG * BATCH * DIM * DIM];
__device__ float g_Wf[BATCH * DIM * DIM];

__device__ __forceinline__ uint32_t f2tf32(float f) {
    uint32_t r;
    asm("cvt.rna.tf32.f32 %0, %1;" : "=r"(r) : "f"(f));
    return r;
}

// round-to-nearest tf32 split via integer ops (ALU pipe, not convert pipe)
__device__ __forceinline__ void split_tf32(float f, uint32_t& hi, uint32_t& lo) {
    uint32_t b = __float_as_uint(f);
    hi = (b + 0x1000u) & 0xFFFFE000u;
    lo = __float_as_uint(f - __uint_as_float(hi));
}

__device__ __forceinline__ uint32_t pack_h2(float a, float b) {
    __half2 h = __floats2half2_rn(a, b);   // a -> low half (element 0)
    return *reinterpret_cast<uint32_t*>(&h);
}

__device__ __forceinline__ void mma_tf32(float* d, const uint32_t* a, const uint32_t* b) {
    asm volatile(
        "mma.sync.aligned.m16n8k8.row.col.f32.tf32.tf32.f32 "
        "{%0,%1,%2,%3}, {%4,%5,%6,%7}, {%8,%9}, {%0,%1,%2,%3};"
        : "+f"(d[0]), "+f"(d[1]), "+f"(d[2]), "+f"(d[3])
        : "r"(a[0]), "r"(a[1]), "r"(a[2]), "r"(a[3]), "r"(b[0]), "r"(b[1]));
}

__device__ __forceinline__ void mma_f16(float* d, const uint32_t* a, const uint32_t* b) {
    asm volatile(
        "mma.sync.aligned.m16n8k16.row.col.f32.f16.f16.f32 "
        "{%0,%1,%2,%3}, {%4,%5,%6,%7}, {%8,%9}, {%0,%1,%2,%3};"
        : "+f"(d[0]), "+f"(d[1]), "+f"(d[2]), "+f"(d[3])
        : "r"(a[0]), "r"(a[1]), "r"(a[2]), "r"(a[3]), "r"(b[0]), "r"(b[1]));
}

// ===========================================================================
// Fused: k/v projection (fp16 k16 mma) + in-register instance norm +
// split-tf32 partial dots. grid(32, NCH), 256 threads, dynamic smem.
// Phase-1 smem (half2 words, [kpair][*]): As [2][8][PA], Bk/Bv [2][8][PB].
// Aliased by sk/sv (fp32) after phase 1.
// ===========================================================================
#define PA 136     // As pitch (conflict pattern same as champion)
#define PB 72      // Bk/Bv pitch
#define PS 72      // sk/sv pitch
#define FUSED_SMEM (2 * TCH * PS * 4)   // 73728 B (>= staging)

__global__ __launch_bounds__(256) void fused_kv_dots(
    const float* __restrict__ x, const float* __restrict__ w_qkv,
    float* __restrict__ part)
{
    extern __shared__ unsigned char smraw[];
    uint32_t* As = (uint32_t*)smraw;           // [2][8][PA]  (x tile, half2 kpairs)
    uint32_t* Bk = As + 2 * 8 * PA;            // [2][8][PB]
    uint32_t* Bv = Bk + 2 * 8 * PB;
    float* sk = (float*)smraw;                 // [TCH][PS] (aliases staging)
    float* sv = sk + TCH * PS;

    const int tid = threadIdx.x;
    const int bh = blockIdx.x, chunk = blockIdx.y;   // bh fastest (L2 x reuse)
    const int b = bh >> 3, h = bh & 7;

    const float* xA  = x + ((long long)b * NTOK + (long long)chunk * TCH) * DIM;
    const float* wkp = w_qkv + INNER + h * DH;        // stride 3*INNER
    const float* wvp = w_qkv + 2 * INNER + h * DH;

    // A staging: row xRow (0..127), 8 consecutive k -> 4 kpairs
    const int xRow = tid >> 1, xC = (tid & 1) * 8;    // k base within tile
    const int xKP = (tid & 1) * 4;                    // kpair base
    // B staging: kpair wKP = tid>>5 (0..7), 2 cols c..c+1
    const int wKP = tid >> 5;
    const int wCc = (tid & 31) * 2;

    const int lane = tid & 31, wid = tid >> 5;
    const int g = lane >> 2, tg = lane & 3;
    const bool isV = (wid >= 4);
    const int warpM = (isV ? wid - 4 : wid) * 32;

    float acc[2][8][4];
    #pragma unroll
    for (int i = 0; i < 2; ++i)
        #pragma unroll
        for (int j = 0; j < 8; ++j)
            #pragma unroll
            for (int c = 0; c < 4; ++c) acc[i][j][c] = 0.f;

    // ---- phase 1: k/v = x @ w (K=256, 16 tiles of 16, double-buffered, fp16)
    float4 pa0, pa1;
    float2 pk0, pk1, pv0, pv1;
    {
        pa0 = *(const float4*)&xA[(long long)xRow * DIM + xC];
        pa1 = *(const float4*)&xA[(long long)xRow * DIM + xC + 4];
        pk0 = *(const float2*)&wkp[(long long)(2 * wKP) * (3 * INNER) + wCc];
        pk1 = *(const float2*)&wkp[(long long)(2 * wKP + 1) * (3 * INNER) + wCc];
        pv0 = *(const float2*)&wvp[(long long)(2 * wKP) * (3 * INNER) + wCc];
        pv1 = *(const float2*)&wvp[(long long)(2 * wKP + 1) * (3 * INNER) + wCc];
    }
    As[(xKP + 0) * PA + xRow] = pack_h2(pa0.x, pa0.y);
    As[(xKP + 1) * PA + xRow] = pack_h2(pa0.z, pa0.w);
    As[(xKP + 2) * PA + xRow] = pack_h2(pa1.x, pa1.y);
    As[(xKP + 3) * PA + xRow] = pack_h2(pa1.z, pa1.w);
    {
        uint2 uk = { pack_h2(pk0.x, pk1.x), pack_h2(pk0.y, pk1.y) };
        uint2 uv = { pack_h2(pv0.x, pv1.x), pack_h2(pv0.y, pv1.y) };
        *(uint2*)&Bk[wKP * PB + wCc] = uk;
        *(uint2*)&Bv[wKP * PB + wCc] = uv;
    }
    __syncthreads();

    const uint32_t* Bsel = isV ? Bv : Bk;

    for (int kt = 0; kt < 16; ++kt) {
        const int buf = kt & 1;
        if (kt + 1 < 16) {
            const int k0 = (kt + 1) * 16;
            pa0 = *(const float4*)&xA[(long long)xRow * DIM + k0 + xC];
            pa1 = *(const float4*)&xA[(long long)xRow * DIM + k0 + xC + 4];
            pk0 = *(const float2*)&wkp[(long long)(k0 + 2 * wKP) * (3 * INNER) + wCc];
            pk1 = *(const float2*)&wkp[(long long)(k0 + 2 * wKP + 1) * (3 * INNER) + wCc];
            pv0 = *(const float2*)&wvp[(long long)(k0 + 2 * wKP) * (3 * INNER) + wCc];
            pv1 = *(const float2*)&wvp[(long long)(k0 + 2 * wKP + 1) * (3 * INNER) + wCc];
        }

        // single fp16 k16 pass over this K-tile (8 kpairs)
        {
            uint32_t af[2][4], bf[8][2];
            #pragma unroll
            for (int mt = 0; mt < 2; ++mt) {
                const int m = warpM + mt * 16;
                af[mt][0] = As[(buf * 8 + tg) * PA + m + g];
                af[mt][1] = As[(buf * 8 + tg) * PA + m + g + 8];
                af[mt][2] = As[(buf * 8 + tg + 4) * PA + m + g];
                af[mt][3] = As[(buf * 8 + tg + 4) * PA + m + g + 8];
            }
            #pragma unroll
            for (int nt = 0; nt < 8; ++nt) {
                bf[nt][0] = Bsel[(buf * 8 + tg) * PB + nt * 8 + g];
                bf[nt][1] = Bsel[(buf * 8 + tg + 4) * PB + nt * 8 + g];
            }
            #pragma unroll
            for (int mt = 0; mt < 2; ++mt)
                #pragma unroll
                for (int nt = 0; nt < 8; ++nt)
                    mma_f16(acc[mt][nt], af[mt], bf[nt]);
        }

        if (kt + 1 < 16) {
            const int nb = 1 - buf;
            As[(nb * 8 + xKP + 0) * PA + xRow] = pack_h2(pa0.x, pa0.y);
            As[(nb * 8 + xKP + 1) * PA + xRow] = pack_h2(pa0.z, pa0.w);
            As[(nb * 8 + xKP + 2) * PA + xRow] = pack_h2(pa1.x, pa1.y);
            As[(nb * 8 + xKP + 3) * PA + xRow] = pack_h2(pa1.z, pa1.w);
            uint2 uk = { pack_h2(pk0.x, pk1.x), pack_h2(pk0.y, pk1.y) };
            uint2 uv = { pack_h2(pv0.x, pv1.x), pack_h2(pv0.y, pv1.y) };
            *(uint2*)&Bk[(nb * 8 + wKP) * PB + wCc] = uk;
            *(uint2*)&Bv[(nb * 8 + wKP) * PB + wCc] = uv;
            __syncthreads();
        }
    }

    // staging region is about to be overwritten by sk/sv.
    __syncthreads();

    // ---- phase 2: in-register instance norm (rows spread over 4 lanes tg) ----
    float* sdst = isV ? sv : sk;
    #pragma unroll
    for (int mt = 0; mt < 2; ++mt) {
        #pragma unroll
        for (int rr = 0; rr < 2; ++rr) {
            float s = 0.f, q = 0.f;
            #pragma unroll
            for (int nt = 0; nt < 8; ++nt) {
                float v0 = acc[mt][nt][2 * rr], v1 = acc[mt][nt][2 * rr + 1];
                s += v0 + v1;
                q += v0 * v0 + v1 * v1;
            }
            s += __shfl_xor_sync(0xFFFFFFFFu, s, 1);
            s += __shfl_xor_sync(0xFFFFFFFFu, s, 2);
            q += __shfl_xor_sync(0xFFFFFFFFu, q, 1);
            q += __shfl_xor_sync(0xFFFFFFFFu, q, 2);
            const float mu  = s * (1.0f / 64.0f);
            const float var = q * (1.0f / 64.0f) - mu * mu;
            const float inv = rsqrtf(var + 1e-5f);
            const int row = warpM + mt * 16 + g + rr * 8;
            #pragma unroll
            for (int nt = 0; nt < 8; ++nt) {
                float2 o = { (acc[mt][nt][2 * rr] - mu) * inv,
                             (acc[mt][nt][2 * rr + 1] - mu) * inv };
                *(float2*)&sdst[row * PS + nt * 8 + 2 * tg] = o;
            }
        }
    }
    __syncthreads();

    // ---- phase 3: partial dots = k-hat^T @ v-hat  (split tf32: hh+hl+lh) ----
    const int n0 = wid * 8;
    float d[4][4];
    #pragma unroll
    for (int mt = 0; mt < 4; ++mt)
        #pragma unroll
        for (int c = 0; c < 4; ++c) d[mt][c] = 0.f;

    for (int kk = 0; kk < TCH; kk += 8) {
        uint32_t ah[4][4], al[4][4], bhv[2], blv[2];
        #pragma unroll
        for (int mt = 0; mt < 4; ++mt) {
            const int m = mt * 16;
            float f0 = sk[(kk + tg) * PS + m + g];
            float f1 = sk[(kk + tg) * PS + m + g + 8];
            float f2 = sk[(kk + tg + 4) * PS + m + g];
            float f3 = sk[(kk + tg + 4) * PS + m + g + 8];
            split_tf32(f0, ah[mt][0], al[mt][0]);
            split_tf32(f1, ah[mt][1], al[mt][1]);
            split_tf32(f2, ah[mt][2], al[mt][2]);
            split_tf32(f3, ah[mt][3], al[mt][3]);
        }
        {
            float e0 = sv[(kk + tg) * PS + n0 + g];
            float e1 = sv[(kk + tg + 4) * PS + n0 + g];
            split_tf32(e0, bhv[0], blv[0]);
            split_tf32(e1, bhv[1], blv[1]);
        }
        #pragma unroll
        for (int mt = 0; mt < 4; ++mt) mma_tf32(d[mt], ah[mt], bhv);
        #pragma unroll
        for (int mt = 0; mt < 4; ++mt) mma_tf32(d[mt], ah[mt], blv);
        #pragma unroll
        for (int mt = 0; mt < 4; ++mt) mma_tf32(d[mt], al[mt], bhv);
    }

    float* op = part + (long long)(bh * NCH + chunk) * (DH * DH);
    #pragma unroll
    for (int mt = 0; mt < 4; ++mt) {
        const int e = mt * 16 + g;
        float2 lo = { d[mt][0], d[mt][1] };
        float2 hi = { d[mt][2], d[mt][3] };
        *(float2*)&op[e * DH + n0 + 2 * tg] = lo;
        *(float2*)&op[(e + 8) * DH + n0 + 2 * tg] = hi;
    }
}

// ===========================================================================
__global__ __launch_bounds__(256) void reduce_dots(
    const float* __restrict__ part, float* __restrict__ dots)
{
    const int bh = blockIdx.x, seg = blockIdx.y;   // grid (32,4)
    #pragma unroll
    for (int j = 0; j < 4; ++j) {
        const int idx = seg * 1024 + j * 256 + threadIdx.x;
        float s = 0.f;
        #pragma unroll 8
        for (int c = 0; c < NCH; ++c)
            s += part[(long long)(bh * NCH + c) * (DH * DH) + idx];
        dots[bh * DH * DH + idx] = s;
    }
}

// A2[b, h*64+e, j] = sum_f dots[b,h][e,f] * w_out[h*64+f, j]; grid (32, 8)
__global__ __launch_bounds__(256) void dots_wout(
    const float* __restrict__ dots, const float* __restrict__ w_out,
    float* __restrict__ A2)
{
    const int bh = blockIdx.x, jt = blockIdx.y;
    const int b = bh >> 3, h = bh & 7;
    __shared__ float sd[DH * DH];
    __shared__ float sw[DH][33];
    for (int i = threadIdx.x; i < DH * DH; i += 256) sd[i] = dots[bh * DH * DH + i];
    for (int i = threadIdx.x; i < DH * 32; i += 256) {
        const int f = i >> 5, j = i & 31;
        sw[f][j] = w_out[(h * DH + f) * DIM + jt * 32 + j];
    }
    __syncthreads();
    for (int idx = threadIdx.x; idx < DH * 32; idx += 256) {
        const int e = idx >> 5, j = idx & 31;
        float s = 0.f;
        #pragma unroll 8
        for (int f = 0; f < DH; ++f) s += sd[e * DH + f] * sw[f][j];
        A2[((long long)b * INNER + h * DH + e) * DIM + jt * 32 + j] = s;
    }
}

// ===========================================================================
// WfP[seg][b] = w_q[:, seg*128:(seg+1)*128] @ A2[b][seg*128:(seg+1)*128, :]
// ===========================================================================
__global__ __launch_bounds__(256) void wf_gemm_splitk(
    const float* __restrict__ w_qkv, const float* __restrict__ A2,
    float* __restrict__ WfP)
{
    __shared__ float sA[16][68];
    __shared__ float sB[16][68];

    const int tid = threadIdx.x;
    const int m0 = blockIdx.y * 64, j0 = blockIdx.x * 64;
    const int bz = blockIdx.z;
    const int b = bz >> 2, seg = bz & 3;
    const int kbase = seg * (INNER / KSEG);

    const float* Bb = A2 + (long long)b * INNER * DIM;

    const int am = tid >> 2, akq = (tid & 3) * 4;
    const int bk = tid >> 4, bj = (tid & 15) * 4;
    const int ty = (tid >> 4) << 2;
    const int tx = (tid & 15) << 2;

    float acc[4][4] = {};

    for (int k0 = 0; k0 < INNER / KSEG; k0 += 16) {
        float4 a4 = *(const float4*)&w_qkv[(long long)(m0 + am) * (3 * INNER) + kbase + k0 + akq];
        sA[akq + 0][am] = a4.x;
        sA[akq + 1][am] = a4.y;
        sA[akq + 2][am] = a4.z;
        sA[akq + 3][am] = a4.w;
        float4 b4 = *(const float4*)&Bb[(long long)(kbase + k0 + bk) * DIM + j0 + bj];
        *(float4*)&sB[bk][bj] = b4;
        __syncthreads();
        #pragma unroll
        for (int kk = 0; kk < 16; ++kk) {
            float a[4], bb[4];
            #pragma unroll
            for (int i = 0; i < 4; ++i) a[i] = sA[kk][ty + i];
            #pragma unroll
            for (int j = 0; j < 4; ++j) bb[j] = sB[kk][tx + j];
            #pragma unroll
            for (int i = 0; i < 4; ++i)
                #pragma unroll
                for (int j = 0; j < 4; ++j) acc[i][j] += a[i] * bb[j];
        }
        __syncthreads();
    }

    float* C = WfP + ((long long)bz) * DIM * DIM;
    #pragma unroll
    for (int i = 0; i < 4; ++i) {
        float4 o = { acc[i][0], acc[i][1], acc[i][2], acc[i][3] };
        *(float4*)&C[(long long)(m0 + ty + i) * DIM + j0 + tx] = o;
    }
}

__global__ __launch_bounds__(256) void wf_reduce(
    const float* __restrict__ WfP, float* __restrict__ Wf)
{
    const int idx = blockIdx.x * 256 + threadIdx.x;
    const int b = idx / (DIM * DIM);
    const int r = idx % (DIM * DIM);
    float s = 0.f;
    #pragma unroll
    for (int seg = 0; seg < KSEG; ++seg)
        s += WfP[((long long)(b * KSEG + seg)) * DIM * DIM + r];
    Wf[idx] = s * (1.0f / (float)NTOK);
}

// ===========================================================================
// TF32 tensor-core GEMM for the final out = x @ Wf + b_out
// ===========================================================================
__global__ __launch_bounds__(256) void gemm_tf32(
    const float* __restrict__ A, int lda, long long sA,
    const float* __restrict__ B, int ldb, long long sB,
    float* __restrict__ C, int ldc, long long sC,
    int K, const float* __restrict__ bias, float alpha)
{
    __shared__ uint32_t As[2][16][132];
    __shared__ uint32_t Bs[2][16][132];

    const int tid = threadIdx.x;
    const int bx = blockIdx.x, by = blockIdx.y, bz = blockIdx.z;

    A += (long long)bz * sA + (long long)by * 128 * lda;
    B += (long long)bz * sB + (long long)bx * 128;
    C += (long long)bz * sC + (long long)by * 128 * ldc + (long long)bx * 128;

    const int aRow = tid >> 2, aCol = (tid & 3) << 2;
    const int bRow = tid >> 5, bCol = (tid & 31) << 2;

    const int lane = tid & 31, wid = tid >> 5;
    const int warpM = (wid >> 2) * 64;
    const int warpN = (wid & 3) * 32;
    const int g = lane >> 2, tg = lane & 3;

    float acc[4][4][4];
    #pragma unroll
    for (int i = 0; i < 4; ++i)
        #pragma unroll
        for (int j = 0; j < 4; ++j)
            #pragma unroll
            for (int c = 0; c < 4; ++c) acc[i][j][c] = 0.f;

    const int KT = K / 16;

    {
        float4 a0 = *reinterpret_cast<const float4*>(&A[(long long)aRow * lda + aCol]);
        float4 a1 = *reinterpret_cast<const float4*>(&A[(long long)(aRow + 64) * lda + aCol]);
        As[0][aCol + 0][aRow] = f2tf32(a0.x);
        As[0][aCol + 1][aRow] = f2tf32(a0.y);
        As[0][aCol + 2][aRow] = f2tf32(a0.z);
        As[0][aCol + 3][aRow] = f2tf32(a0.w);
        As[0][aCol + 0][aRow + 64] = f2tf32(a1.x);
        As[0][aCol + 1][aRow + 64] = f2tf32(a1.y);
        As[0][aCol + 2][aRow + 64] = f2tf32(a1.z);
        As[0][aCol + 3][aRow + 64] = f2tf32(a1.w);
        float4 b0 = *reinterpret_cast<const float4*>(&B[(long long)bRow * ldb + bCol]);
        float4 b1 = *reinterpret_cast<const float4*>(&B[(long long)(bRow + 8) * ldb + bCol]);
        uint4 u0 = { f2tf32(b0.x), f2tf32(b0.y), f2tf32(b0.z), f2tf32(b0.w) };
        uint4 u1 = { f2tf32(b1.x), f2tf32(b1.y), f2tf32(b1.z), f2tf32(b1.w) };
        *(uint4*)&Bs[0][bRow][bCol] = u0;
        *(uint4*)&Bs[0][bRow + 8][bCol] = u1;
    }
    __syncthreads();

    for (int kt = 0; kt < KT; ++kt) {
        const int buf = kt & 1;
        float4 pa0, pa1, pb0, pb1;
        if (kt + 1 < KT) {
            const int k0 = (kt + 1) * 16;
            pa0 = *reinterpret_cast<const float4*>(&A[(long long)aRow * lda + k0 + aCol]);
            pa1 = *reinterpret_cast<const float4*>(&A[(long long)(aRow + 64) * lda + k0 + aCol]);
            pb0 = *reinterpret_cast<const float4*>(&B[(long long)(k0 + bRow) * ldb + bCol]);
            pb1 = *reinterpret_cast<const float4*>(&B[(long long)(k0 + bRow + 8) * ldb + bCol]);
        }

        #pragma unroll
        for (int kk = 0; kk < 16; kk += 8) {
            uint32_t af[4][4], bf[4][2];
            #pragma unroll
            for (int mt = 0; mt < 4; ++mt) {
                const int m = warpM + mt * 16;
                af[mt][0] = As[buf][kk + tg][m + g];
                af[mt][1] = As[buf][kk + tg][m + g + 8];
                af[mt][2] = As[buf][kk + tg + 4][m + g];
                af[mt][3] = As[buf][kk + tg + 4][m + g + 8];
            }
            #pragma unroll
            for (int nt = 0; nt < 4; ++nt) {
                const int n = warpN + nt * 8;
                bf[nt][0] = Bs[buf][kk + tg][n + g];
                bf[nt][1] = Bs[buf][kk + tg + 4][n + g];
            }
            #pragma unroll
            for (int mt = 0; mt < 4; ++mt)
                #pragma unroll
                for (int nt = 0; nt < 4; ++nt)
                    mma_tf32(acc[mt][nt], af[mt], bf[nt]);
        }

        if (kt + 1 < KT) {
            const int nb = 1 - buf;
            As[nb][aCol + 0][aRow] = f2tf32(pa0.x);
            As[nb][aCol + 1][aRow] = f2tf32(pa0.y);
            As[nb][aCol + 2][aRow] = f2tf32(pa0.z);
            As[nb][aCol + 3][aRow] = f2tf32(pa0.w);
            As[nb][aCol + 0][aRow + 64] = f2tf32(pa1.x);
            As[nb][aCol + 1][aRow + 64] = f2tf32(pa1.y);
            As[nb][aCol + 2][aRow + 64] = f2tf32(pa1.z);
            As[nb][aCol + 3][aRow + 64] = f2tf32(pa1.w);
            uint4 u0 = { f2tf32(pb0.x), f2tf32(pb0.y), f2tf32(pb0.z), f2tf32(pb0.w) };
            uint4 u1 = { f2tf32(pb1.x), f2tf32(pb1.y), f2tf32(pb1.z), f2tf32(pb1.w) };
            *(uint4*)&Bs[nb][bRow][bCol] = u0;
            *(uint4*)&Bs[nb][bRow + 8][bCol] = u1;
            __syncthreads();
        }
    }

    #pragma unroll
    for (int mt = 0; mt < 4; ++mt) {
        const int r0 = warpM + mt * 16 + g;
        #pragma unroll
        for (int nt = 0; nt < 4; ++nt) {
            const int c0 = warpN + nt * 8 + 2 * tg;
            float bx0 = 0.f, bx1 = 0.f;
            if (bias) {
                const int gcol = blockIdx.x * 128 + c0;
                bx0 = bias[gcol];
                bx1 = bias[gcol + 1];
            }
            float2 lo = { alpha * acc[mt][nt][0] + bx0, alpha * acc[mt][nt][1] + bx1 };
            float2 hi = { alpha * acc[mt][nt][2] + bx0, alpha * acc[mt][nt][3] + bx1 };
            *reinterpret_cast<float2*>(&C[(long long)r0 * ldc + c0]) = lo;
            *reinterpret_cast<float2*>(&C[(long long)(r0 + 8) * ldc + c0]) = hi;
        }
    }
}

// ---------------------------------------------------------------------------
extern "C" void kernel_launch(void* const* d_in, const int* in_sizes, int n_in,
                              void* d_out, int out_size)
{
    const float* x      = (const float*)d_in[0];  // [4, 8192, 256]
    const float* w_qkv  = (const float*)d_in[1];  // [256, 1536]
    const float* w_out  = (const float*)d_in[2];  // [512, 256]
    const float* b_out  = (const float*)d_in[3];  // [256]
    float*       out    = (float*)d_out;          // [4, 8192, 256]

    float *part, *dots, *A2, *WfP, *Wf;
    cudaGetSymbolAddress((void**)&part, g_part);
    cudaGetSymbolAddress((void**)&dots, g_dots);
    cudaGetSymbolAddress((void**)&A2,   g_A2);
    cudaGetSymbolAddress((void**)&WfP,  g_WfP);
    cudaGetSymbolAddress((void**)&Wf,   g_Wf);

    cudaFuncSetAttribute(fused_kv_dots,
                         cudaFuncAttributeMaxDynamicSharedMemorySize, FUSED_SMEM);

    // 1) fused: k/v projection + instance norm + partial dots
    fused_kv_dots<<<dim3(32, NCH), 256, FUSED_SMEM>>>(x, w_qkv, part);

    // 2) deterministic chunk reduction
    reduce_dots<<<dim3(32, 4), 256>>>(part, dots);

    // 3) A2 = blockdiag(dots) @ w_out ; Wf[b] = w_q @ A2[b] / n (split-K)
    dots_wout<<<dim3(32, 8), 256>>>(dots, w_out, A2);
    wf_gemm_splitk<<<dim3(4, 4, BATCH * KSEG), 256>>>(w_qkv, A2, WfP);
    wf_reduce<<<(BATCH * DIM * DIM) / 256, 256>>>(WfP, Wf);

    // 4) out[b] = x[b] @ Wf[b] + b_out  (tf32 TC)
    gemm_tf32<<<dim3(DIM / 128, NTOK / 128, BATCH), 256>>>(
        x, DIM, (long long)NTOK * DIM,
        Wf, DIM, (long long)DIM * DIM,
        out, DIM, (long long)NTOK * DIM,
        DIM, b_out, 1.0f);
}

// round 12
// speedup vs baseline: 1.4350x; 1.0747x over previous
#include <cuda_runtime.h>
#include <cuda_fp16.h>
#include <cuda_bf16.h>
#include <cstdint>

// ---------------------------------------------------------------------------
// Galerkin linear attention, restructured:
//   [fused] k,v = x @ w_{k,v} (fp16 m16n8k16 mma, fp32 accum);
//           in-register instance norm; partial dots (split-tf32 3-pass)
//   dots = sum_chunks part ; A2 = blockdiag(dots)@w_out ; Wf[b]=w_q@A2[b]/n
//   out[b] = x[b] @ Wf[b] + b_out     (fp16 m16n8k16 mma, fp32 accum)
// Round-12: final GEMM tf32 k8 -> fp16 k16 (same transform that won round 11).
// ---------------------------------------------------------------------------

#define BATCH   4
#define NTOK    8192
#define DIM     256
#define HEADS   8
#define DH      64
#define INNER   512
#define TCH     128                 // tokens per fused chunk
#define NCH     (NTOK / TCH)        // 64
#define KSEG    4                   // split-K segments for Wf

__device__ float g_part[32 * NCH * DH * DH];   // 33.5 MB partial dots
__device__ float g_dots[32 * DH * DH];
__device__ float g_A2[BATCH * INNER * DIM];
__device__ float g_WfP[KSEG * BATCH * DIM * DIM];
__device__ float g_Wf[BATCH * DIM * DIM];

__device__ __forceinline__ uint32_t f2tf32(float f) {
    uint32_t r;
    asm("cvt.rna.tf32.f32 %0, %1;" : "=r"(r) : "f"(f));
    return r;
}

// round-to-nearest tf32 split via integer ops (ALU pipe, not convert pipe)
__device__ __forceinline__ void split_tf32(float f, uint32_t& hi, uint32_t& lo) {
    uint32_t b = __float_as_uint(f);
    hi = (b + 0x1000u) & 0xFFFFE000u;
    lo = __float_as_uint(f - __uint_as_float(hi));
}

__device__ __forceinline__ uint32_t pack_h2(float a, float b) {
    __half2 h = __floats2half2_rn(a, b);   // a -> low half (element 0)
    return *reinterpret_cast<uint32_t*>(&h);
}

__device__ __forceinline__ void mma_tf32(float* d, const uint32_t* a, const uint32_t* b) {
    asm volatile(
        "mma.sync.aligned.m16n8k8.row.col.f32.tf32.tf32.f32 "
        "{%0,%1,%2,%3}, {%4,%5,%6,%7}, {%8,%9}, {%0,%1,%2,%3};"
        : "+f"(d[0]), "+f"(d[1]), "+f"(d[2]), "+f"(d[3])
        : "r"(a[0]), "r"(a[1]), "r"(a[2]), "r"(a[3]), "r"(b[0]), "r"(b[1]));
}

__device__ __forceinline__ void mma_f16(float* d, const uint32_t* a, const uint32_t* b) {
    asm volatile(
        "mma.sync.aligned.m16n8k16.row.col.f32.f16.f16.f32 "
        "{%0,%1,%2,%3}, {%4,%5,%6,%7}, {%8,%9}, {%0,%1,%2,%3};"
        : "+f"(d[0]), "+f"(d[1]), "+f"(d[2]), "+f"(d[3])
        : "r"(a[0]), "r"(a[1]), "r"(a[2]), "r"(a[3]), "r"(b[0]), "r"(b[1]));
}

// ===========================================================================
// Fused: k/v projection (fp16 k16 mma) + in-register instance norm +
// split-tf32 partial dots. grid(32, NCH), 256 threads, dynamic smem.
// ===========================================================================
#define PA 136
#define PB 72
#define PS 72
#define FUSED_SMEM (2 * TCH * PS * 4)   // 73728 B (>= staging)

__global__ __launch_bounds__(256) void fused_kv_dots(
    const float* __restrict__ x, const float* __restrict__ w_qkv,
    float* __restrict__ part)
{
    extern __shared__ unsigned char smraw[];
    uint32_t* As = (uint32_t*)smraw;           // [2][8][PA]  (x tile, half2 kpairs)
    uint32_t* Bk = As + 2 * 8 * PA;            // [2][8][PB]
    uint32_t* Bv = Bk + 2 * 8 * PB;
    float* sk = (float*)smraw;                 // [TCH][PS] (aliases staging)
    float* sv = sk + TCH * PS;

    const int tid = threadIdx.x;
    const int bh = blockIdx.x, chunk = blockIdx.y;   // bh fastest (L2 x reuse)
    const int b = bh >> 3, h = bh & 7;

    const float* xA  = x + ((long long)b * NTOK + (long long)chunk * TCH) * DIM;
    const float* wkp = w_qkv + INNER + h * DH;        // stride 3*INNER
    const float* wvp = w_qkv + 2 * INNER + h * DH;

    const int xRow = tid >> 1, xC = (tid & 1) * 8;
    const int xKP = (tid & 1) * 4;
    const int wKP = tid >> 5;
    const int wCc = (tid & 31) * 2;

    const int lane = tid & 31, wid = tid >> 5;
    const int g = lane >> 2, tg = lane & 3;
    const bool isV = (wid >= 4);
    const int warpM = (isV ? wid - 4 : wid) * 32;

    float acc[2][8][4];
    #pragma unroll
    for (int i = 0; i < 2; ++i)
        #pragma unroll
        for (int j = 0; j < 8; ++j)
            #pragma unroll
            for (int c = 0; c < 4; ++c) acc[i][j][c] = 0.f;

    // ---- phase 1: k/v = x @ w (K=256, 16 tiles of 16, double-buffered, fp16)
    float4 pa0, pa1;
    float2 pk0, pk1, pv0, pv1;
    {
        pa0 = *(const float4*)&xA[(long long)xRow * DIM + xC];
        pa1 = *(const float4*)&xA[(long long)xRow * DIM + xC + 4];
        pk0 = *(const float2*)&wkp[(long long)(2 * wKP) * (3 * INNER) + wCc];
        pk1 = *(const float2*)&wkp[(long long)(2 * wKP + 1) * (3 * INNER) + wCc];
        pv0 = *(const float2*)&wvp[(long long)(2 * wKP) * (3 * INNER) + wCc];
        pv1 = *(const float2*)&wvp[(long long)(2 * wKP + 1) * (3 * INNER) + wCc];
    }
    As[(xKP + 0) * PA + xRow] = pack_h2(pa0.x, pa0.y);
    As[(xKP + 1) * PA + xRow] = pack_h2(pa0.z, pa0.w);
    As[(xKP + 2) * PA + xRow] = pack_h2(pa1.x, pa1.y);
    As[(xKP + 3) * PA + xRow] = pack_h2(pa1.z, pa1.w);
    {
        uint2 uk = { pack_h2(pk0.x, pk1.x), pack_h2(pk0.y, pk1.y) };
        uint2 uv = { pack_h2(pv0.x, pv1.x), pack_h2(pv0.y, pv1.y) };
        *(uint2*)&Bk[wKP * PB + wCc] = uk;
        *(uint2*)&Bv[wKP * PB + wCc] = uv;
    }
    __syncthreads();

    const uint32_t* Bsel = isV ? Bv : Bk;

    for (int kt = 0; kt < 16; ++kt) {
        const int buf = kt & 1;
        if (kt + 1 < 16) {
            const int k0 = (kt + 1) * 16;
            pa0 = *(const float4*)&xA[(long long)xRow * DIM + k0 + xC];
            pa1 = *(const float4*)&xA[(long long)xRow * DIM + k0 + xC + 4];
            pk0 = *(const float2*)&wkp[(long long)(k0 + 2 * wKP) * (3 * INNER) + wCc];
            pk1 = *(const float2*)&wkp[(long long)(k0 + 2 * wKP + 1) * (3 * INNER) + wCc];
            pv0 = *(const float2*)&wvp[(long long)(k0 + 2 * wKP) * (3 * INNER) + wCc];
            pv1 = *(const float2*)&wvp[(long long)(k0 + 2 * wKP + 1) * (3 * INNER) + wCc];
        }

        {
            uint32_t af[2][4], bf[8][2];
            #pragma unroll
            for (int mt = 0; mt < 2; ++mt) {
                const int m = warpM + mt * 16;
                af[mt][0] = As[(buf * 8 + tg) * PA + m + g];
                af[mt][1] = As[(buf * 8 + tg) * PA + m + g + 8];
                af[mt][2] = As[(buf * 8 + tg + 4) * PA + m + g];
                af[mt][3] = As[(buf * 8 + tg + 4) * PA + m + g + 8];
            }
            #pragma unroll
            for (int nt = 0; nt < 8; ++nt) {
                bf[nt][0] = Bsel[(buf * 8 + tg) * PB + nt * 8 + g];
                bf[nt][1] = Bsel[(buf * 8 + tg + 4) * PB + nt * 8 + g];
            }
            #pragma unroll
            for (int mt = 0; mt < 2; ++mt)
                #pragma unroll
                for (int nt = 0; nt < 8; ++nt)
                    mma_f16(acc[mt][nt], af[mt], bf[nt]);
        }

        if (kt + 1 < 16) {
            const int nb = 1 - buf;
            As[(nb * 8 + xKP + 0) * PA + xRow] = pack_h2(pa0.x, pa0.y);
            As[(nb * 8 + xKP + 1) * PA + xRow] = pack_h2(pa0.z, pa0.w);
            As[(nb * 8 + xKP + 2) * PA + xRow] = pack_h2(pa1.x, pa1.y);
            As[(nb * 8 + xKP + 3) * PA + xRow] = pack_h2(pa1.z, pa1.w);
            uint2 uk = { pack_h2(pk0.x, pk1.x), pack_h2(pk0.y, pk1.y) };
            uint2 uv = { pack_h2(pv0.x, pv1.x), pack_h2(pv0.y, pv1.y) };
            *(uint2*)&Bk[(nb * 8 + wKP) * PB + wCc] = uk;
            *(uint2*)&Bv[(nb * 8 + wKP) * PB + wCc] = uv;
            __syncthreads();
        }
    }

    __syncthreads();

    // ---- phase 2: in-register instance norm ----
    float* sdst = isV ? sv : sk;
    #pragma unroll
    for (int mt = 0; mt < 2; ++mt) {
        #pragma unroll
        for (int rr = 0; rr < 2; ++rr) {
            float s = 0.f, q = 0.f;
            #pragma unroll
            for (int nt = 0; nt < 8; ++nt) {
                float v0 = acc[mt][nt][2 * rr], v1 = acc[mt][nt][2 * rr + 1];
                s += v0 + v1;
                q += v0 * v0 + v1 * v1;
            }
            s += __shfl_xor_sync(0xFFFFFFFFu, s, 1);
            s += __shfl_xor_sync(0xFFFFFFFFu, s, 2);
            q += __shfl_xor_sync(0xFFFFFFFFu, q, 1);
            q += __shfl_xor_sync(0xFFFFFFFFu, q, 2);
            const float mu  = s * (1.0f / 64.0f);
            const float var = q * (1.0f / 64.0f) - mu * mu;
            const float inv = rsqrtf(var + 1e-5f);
            const int row = warpM + mt * 16 + g + rr * 8;
            #pragma unroll
            for (int nt = 0; nt < 8; ++nt) {
                float2 o = { (acc[mt][nt][2 * rr] - mu) * inv,
                             (acc[mt][nt][2 * rr + 1] - mu) * inv };
                *(float2*)&sdst[row * PS + nt * 8 + 2 * tg] = o;
            }
        }
    }
    __syncthreads();

    // ---- phase 3: partial dots = k-hat^T @ v-hat (split tf32: hh+hl+lh) ----
    const int n0 = wid * 8;
    float d[4][4];
    #pragma unroll
    for (int mt = 0; mt < 4; ++mt)
        #pragma unroll
        for (int c = 0; c < 4; ++c) d[mt][c] = 0.f;

    for (int kk = 0; kk < TCH; kk += 8) {
        uint32_t ah[4][4], al[4][4], bhv[2], blv[2];
        #pragma unroll
        for (int mt = 0; mt < 4; ++mt) {
            const int m = mt * 16;
            float f0 = sk[(kk + tg) * PS + m + g];
            float f1 = sk[(kk + tg) * PS + m + g + 8];
            float f2 = sk[(kk + tg + 4) * PS + m + g];
            float f3 = sk[(kk + tg + 4) * PS + m + g + 8];
            split_tf32(f0, ah[mt][0], al[mt][0]);
            split_tf32(f1, ah[mt][1], al[mt][1]);
            split_tf32(f2, ah[mt][2], al[mt][2]);
            split_tf32(f3, ah[mt][3], al[mt][3]);
        }
        {
            float e0 = sv[(kk + tg) * PS + n0 + g];
            float e1 = sv[(kk + tg + 4) * PS + n0 + g];
            split_tf32(e0, bhv[0], blv[0]);
            split_tf32(e1, bhv[1], blv[1]);
        }
        #pragma unroll
        for (int mt = 0; mt < 4; ++mt) mma_tf32(d[mt], ah[mt], bhv);
        #pragma unroll
        for (int mt = 0; mt < 4; ++mt) mma_tf32(d[mt], ah[mt], blv);
        #pragma unroll
        for (int mt = 0; mt < 4; ++mt) mma_tf32(d[mt], al[mt], bhv);
    }

    float* op = part + (long long)(bh * NCH + chunk) * (DH * DH);
    #pragma unroll
    for (int mt = 0; mt < 4; ++mt) {
        const int e = mt * 16 + g;
        float2 lo = { d[mt][0], d[mt][1] };
        float2 hi = { d[mt][2], d[mt][3] };
        *(float2*)&op[e * DH + n0 + 2 * tg] = lo;
        *(float2*)&op[(e + 8) * DH + n0 + 2 * tg] = hi;
    }
}

// ===========================================================================
__global__ __launch_bounds__(256) void reduce_dots(
    const float* __restrict__ part, float* __restrict__ dots)
{
    const int bh = blockIdx.x, seg = blockIdx.y;   // grid (32,4)
    #pragma unroll
    for (int j = 0; j < 4; ++j) {
        const int idx = seg * 1024 + j * 256 + threadIdx.x;
        float s = 0.f;
        #pragma unroll 8
        for (int c = 0; c < NCH; ++c)
            s += part[(long long)(bh * NCH + c) * (DH * DH) + idx];
        dots[bh * DH * DH + idx] = s;
    }
}

// A2[b, h*64+e, j] = sum_f dots[b,h][e,f] * w_out[h*64+f, j]; grid (32, 8)
__global__ __launch_bounds__(256) void dots_wout(
    const float* __restrict__ dots, const float* __restrict__ w_out,
    float* __restrict__ A2)
{
    const int bh = blockIdx.x, jt = blockIdx.y;
    const int b = bh >> 3, h = bh & 7;
    __shared__ float sd[DH * DH];
    __shared__ float sw[DH][33];
    for (int i = threadIdx.x; i < DH * DH; i += 256) sd[i] = dots[bh * DH * DH + i];
    for (int i = threadIdx.x; i < DH * 32; i += 256) {
        const int f = i >> 5, j = i & 31;
        sw[f][j] = w_out[(h * DH + f) * DIM + jt * 32 + j];
    }
    __syncthreads();
    for (int idx = threadIdx.x; idx < DH * 32; idx += 256) {
        const int e = idx >> 5, j = idx & 31;
        float s = 0.f;
        #pragma unroll 8
        for (int f = 0; f < DH; ++f) s += sd[e * DH + f] * sw[f][j];
        A2[((long long)b * INNER + h * DH + e) * DIM + jt * 32 + j] = s;
    }
}

// ===========================================================================
// WfP[seg][b] = w_q[:, seg*128:(seg+1)*128] @ A2[b][seg*128:(seg+1)*128, :]
// ===========================================================================
__global__ __launch_bounds__(256) void wf_gemm_splitk(
    const float* __restrict__ w_qkv, const float* __restrict__ A2,
    float* __restrict__ WfP)
{
    __shared__ float sA[16][68];
    __shared__ float sB[16][68];

    const int tid = threadIdx.x;
    const int m0 = blockIdx.y * 64, j0 = blockIdx.x * 64;
    const int bz = blockIdx.z;
    const int b = bz >> 2, seg = bz & 3;
    const int kbase = seg * (INNER / KSEG);

    const float* Bb = A2 + (long long)b * INNER * DIM;

    const int am = tid >> 2, akq = (tid & 3) * 4;
    const int bk = tid >> 4, bj = (tid & 15) * 4;
    const int ty = (tid >> 4) << 2;
    const int tx = (tid & 15) << 2;

    float acc[4][4] = {};

    for (int k0 = 0; k0 < INNER / KSEG; k0 += 16) {
        float4 a4 = *(const float4*)&w_qkv[(long long)(m0 + am) * (3 * INNER) + kbase + k0 + akq];
        sA[akq + 0][am] = a4.x;
        sA[akq + 1][am] = a4.y;
        sA[akq + 2][am] = a4.z;
        sA[akq + 3][am] = a4.w;
        float4 b4 = *(const float4*)&Bb[(long long)(kbase + k0 + bk) * DIM + j0 + bj];
        *(float4*)&sB[bk][bj] = b4;
        __syncthreads();
        #pragma unroll
        for (int kk = 0; kk < 16; ++kk) {
            float a[4], bb[4];
            #pragma unroll
            for (int i = 0; i < 4; ++i) a[i] = sA[kk][ty + i];
            #pragma unroll
            for (int j = 0; j < 4; ++j) bb[j] = sB[kk][tx + j];
            #pragma unroll
            for (int i = 0; i < 4; ++i)
                #pragma unroll
                for (int j = 0; j < 4; ++j) acc[i][j] += a[i] * bb[j];
        }
        __syncthreads();
    }

    float* C = WfP + ((long long)bz) * DIM * DIM;
    #pragma unroll
    for (int i = 0; i < 4; ++i) {
        float4 o = { acc[i][0], acc[i][1], acc[i][2], acc[i][3] };
        *(float4*)&C[(long long)(m0 + ty + i) * DIM + j0 + tx] = o;
    }
}

__global__ __launch_bounds__(256) void wf_reduce(
    const float* __restrict__ WfP, float* __restrict__ Wf)
{
    const int idx = blockIdx.x * 256 + threadIdx.x;
    const int b = idx / (DIM * DIM);
    const int r = idx % (DIM * DIM);
    float s = 0.f;
    #pragma unroll
    for (int seg = 0; seg < KSEG; ++seg)
        s += WfP[((long long)(b * KSEG + seg)) * DIM * DIM + r];
    Wf[idx] = s * (1.0f / (float)NTOK);
}

// ===========================================================================
// Final GEMM: out[b] = x[b] @ Wf[b] + b_out  (fp16 m16n8k16, fp32 accum)
// 128x128 tile, grid (2, 64, BATCH). Staging packs half2 k-pairs.
// ===========================================================================
__global__ __launch_bounds__(256) void gemm_f16(
    const float* __restrict__ x, const float* __restrict__ Wf,
    const float* __restrict__ bias, float* __restrict__ out)
{
    __shared__ uint32_t As[2][8][132];   // [kpair][m]
    __shared__ uint32_t Bs[2][8][132];   // [kpair][n]

    const int tid = threadIdx.x;
    const int bx = blockIdx.x, by = blockIdx.y, bz = blockIdx.z;

    const float* A = x + (long long)bz * NTOK * DIM + (long long)by * 128 * DIM;
    const float* B = Wf + (long long)bz * DIM * DIM + (long long)bx * 128;
    float* C = out + (long long)bz * NTOK * DIM + (long long)by * 128 * DIM
                   + (long long)bx * 128;

    // A staging: row aRow (0..63, +64), kpair base akp=(tid&3)*2, 4 k each
    const int aRow = tid >> 2, aCol = (tid & 3) * 4, aKP = (tid & 3) * 2;
    // B staging: kpair bKP = tid>>5 (0..7), 4 cols
    const int bKP = tid >> 5, bCol = (tid & 31) * 4;

    const int lane = tid & 31, wid = tid >> 5;
    const int warpM = (wid >> 2) * 64;
    const int warpN = (wid & 3) * 32;
    const int g = lane >> 2, tg = lane & 3;

    float acc[4][4][4];
    #pragma unroll
    for (int i = 0; i < 4; ++i)
        #pragma unroll
        for (int j = 0; j < 4; ++j)
            #pragma unroll
            for (int c = 0; c < 4; ++c) acc[i][j][c] = 0.f;

    // prologue
    {
        float4 a0 = *(const float4*)&A[(long long)aRow * DIM + aCol];
        float4 a1 = *(const float4*)&A[(long long)(aRow + 64) * DIM + aCol];
        As[0][aKP + 0][aRow] = pack_h2(a0.x, a0.y);
        As[0][aKP + 1][aRow] = pack_h2(a0.z, a0.w);
        As[0][aKP + 0][aRow + 64] = pack_h2(a1.x, a1.y);
        As[0][aKP + 1][aRow + 64] = pack_h2(a1.z, a1.w);
        float4 b0 = *(const float4*)&B[(long long)(2 * bKP) * DIM + bCol];
        float4 b1 = *(const float4*)&B[(long long)(2 * bKP + 1) * DIM + bCol];
        uint4 u = { pack_h2(b0.x, b1.x), pack_h2(b0.y, b1.y),
                    pack_h2(b0.z, b1.z), pack_h2(b0.w, b1.w) };
        *(uint4*)&Bs[0][bKP][bCol] = u;
    }
    __syncthreads();

    for (int kt = 0; kt < 16; ++kt) {
        const int buf = kt & 1;
        float4 pa0, pa1, pb0, pb1;
        if (kt + 1 < 16) {
            const int k0 = (kt + 1) * 16;
            pa0 = *(const float4*)&A[(long long)aRow * DIM + k0 + aCol];
            pa1 = *(const float4*)&A[(long long)(aRow + 64) * DIM + k0 + aCol];
            pb0 = *(const float4*)&B[(long long)(k0 + 2 * bKP) * DIM + bCol];
            pb1 = *(const float4*)&B[(long long)(k0 + 2 * bKP + 1) * DIM + bCol];
        }

        {
            uint32_t af[4][4], bf[4][2];
            #pragma unroll
            for (int mt = 0; mt < 4; ++mt) {
                const int m = warpM + mt * 16;
                af[mt][0] = As[buf][tg][m + g];
                af[mt][1] = As[buf][tg][m + g + 8];
                af[mt][2] = As[buf][tg + 4][m + g];
                af[mt][3] = As[buf][tg + 4][m + g + 8];
            }
            #pragma unroll
            for (int nt = 0; nt < 4; ++nt) {
                const int n = warpN + nt * 8;
                bf[nt][0] = Bs[buf][tg][n + g];
                bf[nt][1] = Bs[buf][tg + 4][n + g];
            }
            #pragma unroll
            for (int mt = 0; mt < 4; ++mt)
                #pragma unroll
                for (int nt = 0; nt < 4; ++nt)
                    mma_f16(acc[mt][nt], af[mt], bf[nt]);
        }

        if (kt + 1 < 16) {
            const int nb = 1 - buf;
            As[nb][aKP + 0][aRow] = pack_h2(pa0.x, pa0.y);
            As[nb][aKP + 1][aRow] = pack_h2(pa0.z, pa0.w);
            As[nb][aKP + 0][aRow + 64] = pack_h2(pa1.x, pa1.y);
            As[nb][aKP + 1][aRow + 64] = pack_h2(pa1.z, pa1.w);
            uint4 u = { pack_h2(pb0.x, pb1.x), pack_h2(pb0.y, pb1.y),
                        pack_h2(pb0.z, pb1.z), pack_h2(pb0.w, pb1.w) };
            *(uint4*)&Bs[nb][bKP][bCol] = u;
            __syncthreads();
        }
    }

    #pragma unroll
    for (int mt = 0; mt < 4; ++mt) {
        const int r0 = warpM + mt * 16 + g;
        #pragma unroll
        for (int nt = 0; nt < 4; ++nt) {
            const int c0 = warpN + nt * 8 + 2 * tg;
            const int gcol = bx * 128 + c0;
            const float bx0 = bias[gcol], bx1 = bias[gcol + 1];
            float2 lo = { acc[mt][nt][0] + bx0, acc[mt][nt][1] + bx1 };
            float2 hi = { acc[mt][nt][2] + bx0, acc[mt][nt][3] + bx1 };
            *(float2*)&C[(long long)r0 * DIM + c0] = lo;
            *(float2*)&C[(long long)(r0 + 8) * DIM + c0] = hi;
        }
    }
}

// ---------------------------------------------------------------------------
extern "C" void kernel_launch(void* const* d_in, const int* in_sizes, int n_in,
                              void* d_out, int out_size)
{
    const float* x      = (const float*)d_in[0];  // [4, 8192, 256]
    const float* w_qkv  = (const float*)d_in[1];  // [256, 1536]
    const float* w_out  = (const float*)d_in[2];  // [512, 256]
    const float* b_out  = (const float*)d_in[3];  // [256]
    float*       out    = (float*)d_out;          // [4, 8192, 256]

    float *part, *dots, *A2, *WfP, *Wf;
    cudaGetSymbolAddress((void**)&part, g_part);
    cudaGetSymbolAddress((void**)&dots, g_dots);
    cudaGetSymbolAddress((void**)&A2,   g_A2);
    cudaGetSymbolAddress((void**)&WfP,  g_WfP);
    cudaGetSymbolAddress((void**)&Wf,   g_Wf);

    cudaFuncSetAttribute(fused_kv_dots,
                         cudaFuncAttributeMaxDynamicSharedMemorySize, FUSED_SMEM);

    // 1) fused: k/v projection + instance norm + partial dots
    fused_kv_dots<<<dim3(32, NCH), 256, FUSED_SMEM>>>(x, w_qkv, part);

    // 2) deterministic chunk reduction
    reduce_dots<<<dim3(32, 4), 256>>>(part, dots);

    // 3) A2 = blockdiag(dots) @ w_out ; Wf[b] = w_q @ A2[b] / n (split-K)
    dots_wout<<<dim3(32, 8), 256>>>(dots, w_out, A2);
    wf_gemm_splitk<<<dim3(4, 4, BATCH * KSEG), 256>>>(w_qkv, A2, WfP);
    wf_reduce<<<(BATCH * DIM * DIM) / 256, 256>>>(WfP, Wf);

    // 4) out[b] = x[b] @ Wf[b] + b_out  (fp16 k16 TC)
    gemm_f16<<<dim3(DIM / 128, NTOK / 128, BATCH), 256>>>(x, Wf, b_out, out);
}

// round 13
// speedup vs baseline: 1.4921x; 1.0398x over previous
#include <cuda_runtime.h>
#include <cuda_fp16.h>
#include <cuda_bf16.h>
#include <cstdint>

// ---------------------------------------------------------------------------
// Galerkin linear attention, restructured:
//   [fused] k,v = x @ w_{k,v} (fp16 m16n8k16 mma, fp32 accum);
//           in-register instance norm; partial dots (split-tf32 3-pass)
//   dots = sum_chunks part ; A2 = blockdiag(dots)@w_out ; Wf[b]=w_q@A2[b]/n
//   out[b] = x[b] @ Wf[b] + b_out     (fp16 m16n8k16 mma, fp32 accum)
// Round-13: __launch_bounds__(256, 2) on fused_kv_dots and gemm_f16 to force
// 2 CTAs/SM (reg cap 128). Everything else identical to the 219.9us champion.
// ---------------------------------------------------------------------------

#define BATCH   4
#define NTOK    8192
#define DIM     256
#define HEADS   8
#define DH      64
#define INNER   512
#define TCH     128                 // tokens per fused chunk
#define NCH     (NTOK / TCH)        // 64
#define KSEG    4                   // split-K segments for Wf

__device__ float g_part[32 * NCH * DH * DH];   // 33.5 MB partial dots
__device__ float g_dots[32 * DH * DH];
__device__ float g_A2[BATCH * INNER * DIM];
__device__ float g_WfP[KSEG * BATCH * DIM * DIM];
__device__ float g_Wf[BATCH * DIM * DIM];

__device__ __forceinline__ uint32_t f2tf32(float f) {
    uint32_t r;
    asm("cvt.rna.tf32.f32 %0, %1;" : "=r"(r) : "f"(f));
    return r;
}

// round-to-nearest tf32 split via integer ops (ALU pipe, not convert pipe)
__device__ __forceinline__ void split_tf32(float f, uint32_t& hi, uint32_t& lo) {
    uint32_t b = __float_as_uint(f);
    hi = (b + 0x1000u) & 0xFFFFE000u;
    lo = __float_as_uint(f - __uint_as_float(hi));
}

__device__ __forceinline__ uint32_t pack_h2(float a, float b) {
    __half2 h = __floats2half2_rn(a, b);   // a -> low half (element 0)
    return *reinterpret_cast<uint32_t*>(&h);
}

__device__ __forceinline__ void mma_tf32(float* d, const uint32_t* a, const uint32_t* b) {
    asm volatile(
        "mma.sync.aligned.m16n8k8.row.col.f32.tf32.tf32.f32 "
        "{%0,%1,%2,%3}, {%4,%5,%6,%7}, {%8,%9}, {%0,%1,%2,%3};"
        : "+f"(d[0]), "+f"(d[1]), "+f"(d[2]), "+f"(d[3])
        : "r"(a[0]), "r"(a[1]), "r"(a[2]), "r"(a[3]), "r"(b[0]), "r"(b[1]));
}

__device__ __forceinline__ void mma_f16(float* d, const uint32_t* a, const uint32_t* b) {
    asm volatile(
        "mma.sync.aligned.m16n8k16.row.col.f32.f16.f16.f32 "
        "{%0,%1,%2,%3}, {%4,%5,%6,%7}, {%8,%9}, {%0,%1,%2,%3};"
        : "+f"(d[0]), "+f"(d[1]), "+f"(d[2]), "+f"(d[3])
        : "r"(a[0]), "r"(a[1]), "r"(a[2]), "r"(a[3]), "r"(b[0]), "r"(b[1]));
}

// ===========================================================================
// Fused: k/v projection (fp16 k16 mma) + in-register instance norm +
// split-tf32 partial dots. grid(32, NCH), 256 threads, dynamic smem.
// ===========================================================================
#define PA 136
#define PB 72
#define PS 72
#define FUSED_SMEM (2 * TCH * PS * 4)   // 73728 B (>= staging)

__global__ __launch_bounds__(256, 2) void fused_kv_dots(
    const float* __restrict__ x, const float* __restrict__ w_qkv,
    float* __restrict__ part)
{
    extern __shared__ unsigned char smraw[];
    uint32_t* As = (uint32_t*)smraw;           // [2][8][PA]  (x tile, half2 kpairs)
    uint32_t* Bk = As + 2 * 8 * PA;            // [2][8][PB]
    uint32_t* Bv = Bk + 2 * 8 * PB;
    float* sk = (float*)smraw;                 // [TCH][PS] (aliases staging)
    float* sv = sk + TCH * PS;

    const int tid = threadIdx.x;
    const int bh = blockIdx.x, chunk = blockIdx.y;   // bh fastest (L2 x reuse)
    const int b = bh >> 3, h = bh & 7;

    const float* xA  = x + ((long long)b * NTOK + (long long)chunk * TCH) * DIM;
    const float* wkp = w_qkv + INNER + h * DH;        // stride 3*INNER
    const float* wvp = w_qkv + 2 * INNER + h * DH;

    const int xRow = tid >> 1, xC = (tid & 1) * 8;
    const int xKP = (tid & 1) * 4;
    const int wKP = tid >> 5;
    const int wCc = (tid & 31) * 2;

    const int lane = tid & 31, wid = tid >> 5;
    const int g = lane >> 2, tg = lane & 3;
    const bool isV = (wid >= 4);
    const int warpM = (isV ? wid - 4 : wid) * 32;

    float acc[2][8][4];
    #pragma unroll
    for (int i = 0; i < 2; ++i)
        #pragma unroll
        for (int j = 0; j < 8; ++j)
            #pragma unroll
            for (int c = 0; c < 4; ++c) acc[i][j][c] = 0.f;

    // ---- phase 1: k/v = x @ w (K=256, 16 tiles of 16, double-buffered, fp16)
    float4 pa0, pa1;
    float2 pk0, pk1, pv0, pv1;
    {
        pa0 = *(const float4*)&xA[(long long)xRow * DIM + xC];
        pa1 = *(const float4*)&xA[(long long)xRow * DIM + xC + 4];
        pk0 = *(const float2*)&wkp[(long long)(2 * wKP) * (3 * INNER) + wCc];
        pk1 = *(const float2*)&wkp[(long long)(2 * wKP + 1) * (3 * INNER) + wCc];
        pv0 = *(const float2*)&wvp[(long long)(2 * wKP) * (3 * INNER) + wCc];
        pv1 = *(const float2*)&wvp[(long long)(2 * wKP + 1) * (3 * INNER) + wCc];
    }
    As[(xKP + 0) * PA + xRow] = pack_h2(pa0.x, pa0.y);
    As[(xKP + 1) * PA + xRow] = pack_h2(pa0.z, pa0.w);
    As[(xKP + 2) * PA + xRow] = pack_h2(pa1.x, pa1.y);
    As[(xKP + 3) * PA + xRow] = pack_h2(pa1.z, pa1.w);
    {
        uint2 uk = { pack_h2(pk0.x, pk1.x), pack_h2(pk0.y, pk1.y) };
        uint2 uv = { pack_h2(pv0.x, pv1.x), pack_h2(pv0.y, pv1.y) };
        *(uint2*)&Bk[wKP * PB + wCc] = uk;
        *(uint2*)&Bv[wKP * PB + wCc] = uv;
    }
    __syncthreads();

    const uint32_t* Bsel = isV ? Bv : Bk;

    for (int kt = 0; kt < 16; ++kt) {
        const int buf = kt & 1;
        if (kt + 1 < 16) {
            const int k0 = (kt + 1) * 16;
            pa0 = *(const float4*)&xA[(long long)xRow * DIM + k0 + xC];
            pa1 = *(const float4*)&xA[(long long)xRow * DIM + k0 + xC + 4];
            pk0 = *(const float2*)&wkp[(long long)(k0 + 2 * wKP) * (3 * INNER) + wCc];
            pk1 = *(const float2*)&wkp[(long long)(k0 + 2 * wKP + 1) * (3 * INNER) + wCc];
            pv0 = *(const float2*)&wvp[(long long)(k0 + 2 * wKP) * (3 * INNER) + wCc];
            pv1 = *(const float2*)&wvp[(long long)(k0 + 2 * wKP + 1) * (3 * INNER) + wCc];
        }

        {
            uint32_t af[2][4], bf[8][2];
            #pragma unroll
            for (int mt = 0; mt < 2; ++mt) {
                const int m = warpM + mt * 16;
                af[mt][0] = As[(buf * 8 + tg) * PA + m + g];
                af[mt][1] = As[(buf * 8 + tg) * PA + m + g + 8];
                af[mt][2] = As[(buf * 8 + tg + 4) * PA + m + g];
                af[mt][3] = As[(buf * 8 + tg + 4) * PA + m + g + 8];
            }
            #pragma unroll
            for (int nt = 0; nt < 8; ++nt) {
                bf[nt][0] = Bsel[(buf * 8 + tg) * PB + nt * 8 + g];
                bf[nt][1] = Bsel[(buf * 8 + tg + 4) * PB + nt * 8 + g];
            }
            #pragma unroll
            for (int mt = 0; mt < 2; ++mt)
                #pragma unroll
                for (int nt = 0; nt < 8; ++nt)
                    mma_f16(acc[mt][nt], af[mt], bf[nt]);
        }

        if (kt + 1 < 16) {
            const int nb = 1 - buf;
            As[(nb * 8 + xKP + 0) * PA + xRow] = pack_h2(pa0.x, pa0.y);
            As[(nb * 8 + xKP + 1) * PA + xRow] = pack_h2(pa0.z, pa0.w);
            As[(nb * 8 + xKP + 2) * PA + xRow] = pack_h2(pa1.x, pa1.y);
            As[(nb * 8 + xKP + 3) * PA + xRow] = pack_h2(pa1.z, pa1.w);
            uint2 uk = { pack_h2(pk0.x, pk1.x), pack_h2(pk0.y, pk1.y) };
            uint2 uv = { pack_h2(pv0.x, pv1.x), pack_h2(pv0.y, pv1.y) };
            *(uint2*)&Bk[(nb * 8 + wKP) * PB + wCc] = uk;
            *(uint2*)&Bv[(nb * 8 + wKP) * PB + wCc] = uv;
            __syncthreads();
        }
    }

    __syncthreads();

    // ---- phase 2: in-register instance norm ----
    float* sdst = isV ? sv : sk;
    #pragma unroll
    for (int mt = 0; mt < 2; ++mt) {
        #pragma unroll
        for (int rr = 0; rr < 2; ++rr) {
            float s = 0.f, q = 0.f;
            #pragma unroll
            for (int nt = 0; nt < 8; ++nt) {
                float v0 = acc[mt][nt][2 * rr], v1 = acc[mt][nt][2 * rr + 1];
                s += v0 + v1;
                q += v0 * v0 + v1 * v1;
            }
            s += __shfl_xor_sync(0xFFFFFFFFu, s, 1);
            s += __shfl_xor_sync(0xFFFFFFFFu, s, 2);
            q += __shfl_xor_sync(0xFFFFFFFFu, q, 1);
            q += __shfl_xor_sync(0xFFFFFFFFu, q, 2);
            const float mu  = s * (1.0f / 64.0f);
            const float var = q * (1.0f / 64.0f) - mu * mu;
            const float inv = rsqrtf(var + 1e-5f);
            const int row = warpM + mt * 16 + g + rr * 8;
            #pragma unroll
            for (int nt = 0; nt < 8; ++nt) {
                float2 o = { (acc[mt][nt][2 * rr] - mu) * inv,
                             (acc[mt][nt][2 * rr + 1] - mu) * inv };
                *(float2*)&sdst[row * PS + nt * 8 + 2 * tg] = o;
            }
        }
    }
    __syncthreads();

    // ---- phase 3: partial dots = k-hat^T @ v-hat (split tf32: hh+hl+lh) ----
    const int n0 = wid * 8;
    float d[4][4];
    #pragma unroll
    for (int mt = 0; mt < 4; ++mt)
        #pragma unroll
        for (int c = 0; c < 4; ++c) d[mt][c] = 0.f;

    for (int kk = 0; kk < TCH; kk += 8) {
        uint32_t ah[4][4], al[4][4], bhv[2], blv[2];
        #pragma unroll
        for (int mt = 0; mt < 4; ++mt) {
            const int m = mt * 16;
            float f0 = sk[(kk + tg) * PS + m + g];
            float f1 = sk[(kk + tg) * PS + m + g + 8];
            float f2 = sk[(kk + tg + 4) * PS + m + g];
            float f3 = sk[(kk + tg + 4) * PS + m + g + 8];
            split_tf32(f0, ah[mt][0], al[mt][0]);
            split_tf32(f1, ah[mt][1], al[mt][1]);
            split_tf32(f2, ah[mt][2], al[mt][2]);
            split_tf32(f3, ah[mt][3], al[mt][3]);
        }
        {
            float e0 = sv[(kk + tg) * PS + n0 + g];
            float e1 = sv[(kk + tg + 4) * PS + n0 + g];
            split_tf32(e0, bhv[0], blv[0]);
            split_tf32(e1, bhv[1], blv[1]);
        }
        #pragma unroll
        for (int mt = 0; mt < 4; ++mt) mma_tf32(d[mt], ah[mt], bhv);
        #pragma unroll
        for (int mt = 0; mt < 4; ++mt) mma_tf32(d[mt], ah[mt], blv);
        #pragma unroll
        for (int mt = 0; mt < 4; ++mt) mma_tf32(d[mt], al[mt], bhv);
    }

    float* op = part + (long long)(bh * NCH + chunk) * (DH * DH);
    #pragma unroll
    for (int mt = 0; mt < 4; ++mt) {
        const int e = mt * 16 + g;
        float2 lo = { d[mt][0], d[mt][1] };
        float2 hi = { d[mt][2], d[mt][3] };
        *(float2*)&op[e * DH + n0 + 2 * tg] = lo;
        *(float2*)&op[(e + 8) * DH + n0 + 2 * tg] = hi;
    }
}

// ===========================================================================
__global__ __launch_bounds__(256) void reduce_dots(
    const float* __restrict__ part, float* __restrict__ dots)
{
    const int bh = blockIdx.x, seg = blockIdx.y;   // grid (32,4)
    #pragma unroll
    for (int j = 0; j < 4; ++j) {
        const int idx = seg * 1024 + j * 256 + threadIdx.x;
        float s = 0.f;
        #pragma unroll 8
        for (int c = 0; c < NCH; ++c)
            s += part[(long long)(bh * NCH + c) * (DH * DH) + idx];
        dots[bh * DH * DH + idx] = s;
    }
}

// A2[b, h*64+e, j] = sum_f dots[b,h][e,f] * w_out[h*64+f, j]; grid (32, 8)
__global__ __launch_bounds__(256) void dots_wout(
    const float* __restrict__ dots, const float* __restrict__ w_out,
    float* __restrict__ A2)
{
    const int bh = blockIdx.x, jt = blockIdx.y;
    const int b = bh >> 3, h = bh & 7;
    __shared__ float sd[DH * DH];
    __shared__ float sw[DH][33];
    for (int i = threadIdx.x; i < DH * DH; i += 256) sd[i] = dots[bh * DH * DH + i];
    for (int i = threadIdx.x; i < DH * 32; i += 256) {
        const int f = i >> 5, j = i & 31;
        sw[f][j] = w_out[(h * DH + f) * DIM + jt * 32 + j];
    }
    __syncthreads();
    for (int idx = threadIdx.x; idx < DH * 32; idx += 256) {
        const int e = idx >> 5, j = idx & 31;
        float s = 0.f;
        #pragma unroll 8
        for (int f = 0; f < DH; ++f) s += sd[e * DH + f] * sw[f][j];
        A2[((long long)b * INNER + h * DH + e) * DIM + jt * 32 + j] = s;
    }
}

// ===========================================================================
// WfP[seg][b] = w_q[:, seg*128:(seg+1)*128] @ A2[b][seg*128:(seg+1)*128, :]
// ===========================================================================
__global__ __launch_bounds__(256) void wf_gemm_splitk(
    const float* __restrict__ w_qkv, const float* __restrict__ A2,
    float* __restrict__ WfP)
{
    __shared__ float sA[16][68];
    __shared__ float sB[16][68];

    const int tid = threadIdx.x;
    const int m0 = blockIdx.y * 64, j0 = blockIdx.x * 64;
    const int bz = blockIdx.z;
    const int b = bz >> 2, seg = bz & 3;
    const int kbase = seg * (INNER / KSEG);

    const float* Bb = A2 + (long long)b * INNER * DIM;

    const int am = tid >> 2, akq = (tid & 3) * 4;
    const int bk = tid >> 4, bj = (tid & 15) * 4;
    const int ty = (tid >> 4) << 2;
    const int tx = (tid & 15) << 2;

    float acc[4][4] = {};

    for (int k0 = 0; k0 < INNER / KSEG; k0 += 16) {
        float4 a4 = *(const float4*)&w_qkv[(long long)(m0 + am) * (3 * INNER) + kbase + k0 + akq];
        sA[akq + 0][am] = a4.x;
        sA[akq + 1][am] = a4.y;
        sA[akq + 2][am] = a4.z;
        sA[akq + 3][am] = a4.w;
        float4 b4 = *(const float4*)&Bb[(long long)(kbase + k0 + bk) * DIM + j0 + bj];
        *(float4*)&sB[bk][bj] = b4;
        __syncthreads();
        #pragma unroll
        for (int kk = 0; kk < 16; ++kk) {
            float a[4], bb[4];
            #pragma unroll
            for (int i = 0; i < 4; ++i) a[i] = sA[kk][ty + i];
            #pragma unroll
            for (int j = 0; j < 4; ++j) bb[j] = sB[kk][tx + j];
            #pragma unroll
            for (int i = 0; i < 4; ++i)
                #pragma unroll
                for (int j = 0; j < 4; ++j) acc[i][j] += a[i] * bb[j];
        }
        __syncthreads();
    }

    float* C = WfP + ((long long)bz) * DIM * DIM;
    #pragma unroll
    for (int i = 0; i < 4; ++i) {
        float4 o = { acc[i][0], acc[i][1], acc[i][2], acc[i][3] };
        *(float4*)&C[(long long)(m0 + ty + i) * DIM + j0 + tx] = o;
    }
}

__global__ __launch_bounds__(256) void wf_reduce(
    const float* __restrict__ WfP, float* __restrict__ Wf)
{
    const int idx = blockIdx.x * 256 + threadIdx.x;
    const int b = idx / (DIM * DIM);
    const int r = idx % (DIM * DIM);
    float s = 0.f;
    #pragma unroll
    for (int seg = 0; seg < KSEG; ++seg)
        s += WfP[((long long)(b * KSEG + seg)) * DIM * DIM + r];
    Wf[idx] = s * (1.0f / (float)NTOK);
}

// ===========================================================================
// Final GEMM: out[b] = x[b] @ Wf[b] + b_out  (fp16 m16n8k16, fp32 accum)
// 128x128 tile, grid (2, 64, BATCH). Staging packs half2 k-pairs.
// ===========================================================================
__global__ __launch_bounds__(256, 2) void gemm_f16(
    const float* __restrict__ x, const float* __restrict__ Wf,
    const float* __restrict__ bias, float* __restrict__ out)
{
    __shared__ uint32_t As[2][8][132];   // [kpair][m]
    __shared__ uint32_t Bs[2][8][132];   // [kpair][n]

    const int tid = threadIdx.x;
    const int bx = blockIdx.x, by = blockIdx.y, bz = blockIdx.z;

    const float* A = x + (long long)bz * NTOK * DIM + (long long)by * 128 * DIM;
    const float* B = Wf + (long long)bz * DIM * DIM + (long long)bx * 128;
    float* C = out + (long long)bz * NTOK * DIM + (long long)by * 128 * DIM
                   + (long long)bx * 128;

    const int aRow = tid >> 2, aCol = (tid & 3) * 4, aKP = (tid & 3) * 2;
    const int bKP = tid >> 5, bCol = (tid & 31) * 4;

    const int lane = tid & 31, wid = tid >> 5;
    const int warpM = (wid >> 2) * 64;
    const int warpN = (wid & 3) * 32;
    const int g = lane >> 2, tg = lane & 3;

    float acc[4][4][4];
    #pragma unroll
    for (int i = 0; i < 4; ++i)
        #pragma unroll
        for (int j = 0; j < 4; ++j)
            #pragma unroll
            for (int c = 0; c < 4; ++c) acc[i][j][c] = 0.f;

    // prologue
    {
        float4 a0 = *(const float4*)&A[(long long)aRow * DIM + aCol];
        float4 a1 = *(const float4*)&A[(long long)(aRow + 64) * DIM + aCol];
        As[0][aKP + 0][aRow] = pack_h2(a0.x, a0.y);
        As[0][aKP + 1][aRow] = pack_h2(a0.z, a0.w);
        As[0][aKP + 0][aRow + 64] = pack_h2(a1.x, a1.y);
        As[0][aKP + 1][aRow + 64] = pack_h2(a1.z, a1.w);
        float4 b0 = *(const float4*)&B[(long long)(2 * bKP) * DIM + bCol];
        float4 b1 = *(const float4*)&B[(long long)(2 * bKP + 1) * DIM + bCol];
        uint4 u = { pack_h2(b0.x, b1.x), pack_h2(b0.y, b1.y),
                    pack_h2(b0.z, b1.z), pack_h2(b0.w, b1.w) };
        *(uint4*)&Bs[0][bKP][bCol] = u;
    }
    __syncthreads();

    for (int kt = 0; kt < 16; ++kt) {
        const int buf = kt & 1;
        float4 pa0, pa1, pb0, pb1;
        if (kt + 1 < 16) {
            const int k0 = (kt + 1) * 16;
            pa0 = *(const float4*)&A[(long long)aRow * DIM + k0 + aCol];
            pa1 = *(const float4*)&A[(long long)(aRow + 64) * DIM + k0 + aCol];
            pb0 = *(const float4*)&B[(long long)(k0 + 2 * bKP) * DIM + bCol];
            pb1 = *(const float4*)&B[(long long)(k0 + 2 * bKP + 1) * DIM + bCol];
        }

        {
            uint32_t af[4][4], bf[4][2];
            #pragma unroll
            for (int mt = 0; mt < 4; ++mt) {
                const int m = warpM + mt * 16;
                af[mt][0] = As[buf][tg][m + g];
                af[mt][1] = As[buf][tg][m + g + 8];
                af[mt][2] = As[buf][tg + 4][m + g];
                af[mt][3] = As[buf][tg + 4][m + g + 8];
            }
            #pragma unroll
            for (int nt = 0; nt < 4; ++nt) {
                const int n = warpN + nt * 8;
                bf[nt][0] = Bs[buf][tg][n + g];
                bf[nt][1] = Bs[buf][tg + 4][n + g];
            }
            #pragma unroll
            for (int mt = 0; mt < 4; ++mt)
                #pragma unroll
                for (int nt = 0; nt < 4; ++nt)
                    mma_f16(acc[mt][nt], af[mt], bf[nt]);
        }

        if (kt + 1 < 16) {
            const int nb = 1 - buf;
            As[nb][aKP + 0][aRow] = pack_h2(pa0.x, pa0.y);
            As[nb][aKP + 1][aRow] = pack_h2(pa0.z, pa0.w);
            As[nb][aKP + 0][aRow + 64] = pack_h2(pa1.x, pa1.y);
            As[nb][aKP + 1][aRow + 64] = pack_h2(pa1.z, pa1.w);
            uint4 u = { pack_h2(pb0.x, pb1.x), pack_h2(pb0.y, pb1.y),
                        pack_h2(pb0.z, pb1.z), pack_h2(pb0.w, pb1.w) };
            *(uint4*)&Bs[nb][bKP][bCol] = u;
            __syncthreads();
        }
    }

    #pragma unroll
    for (int mt = 0; mt < 4; ++mt) {
        const int r0 = warpM + mt * 16 + g;
        #pragma unroll
        for (int nt = 0; nt < 4; ++nt) {
            const int c0 = warpN + nt * 8 + 2 * tg;
            const int gcol = bx * 128 + c0;
            const float bx0 = bias[gcol], bx1 = bias[gcol + 1];
            float2 lo = { acc[mt][nt][0] + bx0, acc[mt][nt][1] + bx1 };
            float2 hi = { acc[mt][nt][2] + bx0, acc[mt][nt][3] + bx1 };
            *(float2*)&C[(long long)r0 * DIM + c0] = lo;
            *(float2*)&C[(long long)(r0 + 8) * DIM + c0] = hi;
        }
    }
}

// ---------------------------------------------------------------------------
extern "C" void kernel_launch(void* const* d_in, const int* in_sizes, int n_in,
                              void* d_out, int out_size)
{
    const float* x      = (const float*)d_in[0];  // [4, 8192, 256]
    const float* w_qkv  = (const float*)d_in[1];  // [256, 1536]
    const float* w_out  = (const float*)d_in[2];  // [512, 256]
    const float* b_out  = (const float*)d_in[3];  // [256]
    float*       out    = (float*)d_out;          // [4, 8192, 256]

    float *part, *dots, *A2, *WfP, *Wf;
    cudaGetSymbolAddress((void**)&part, g_part);
    cudaGetSymbolAddress((void**)&dots, g_dots);
    cudaGetSymbolAddress((void**)&A2,   g_A2);
    cudaGetSymbolAddress((void**)&WfP,  g_WfP);
    cudaGetSymbolAddress((void**)&Wf,   g_Wf);

    cudaFuncSetAttribute(fused_kv_dots,
                         cudaFuncAttributeMaxDynamicSharedMemorySize, FUSED_SMEM);

    // 1) fused: k/v projection + instance norm + partial dots
    fused_kv_dots<<<dim3(32, NCH), 256, FUSED_SMEM>>>(x, w_qkv, part);

    // 2) deterministic chunk reduction
    reduce_dots<<<dim3(32, 4), 256>>>(part, dots);

    // 3) A2 = blockdiag(dots) @ w_out ; Wf[b] = w_q @ A2[b] / n (split-K)
    dots_wout<<<dim3(32, 8), 256>>>(dots, w_out, A2);
    wf_gemm_splitk<<<dim3(4, 4, BATCH * KSEG), 256>>>(w_qkv, A2, WfP);
    wf_reduce<<<(BATCH * DIM * DIM) / 256, 256>>>(WfP, Wf);

    // 4) out[b] = x[b] @ Wf[b] + b_out  (fp16 k16 TC)
    gemm_f16<<<dim3(DIM / 128, NTOK / 128, BATCH), 256>>>(x, Wf, b_out, out);
}

// round 14
// speedup vs baseline: 1.5218x; 1.0199x over previous
#include <cuda_runtime.h>
#include <cuda_fp16.h>
#include <cuda_bf16.h>
#include <cstdint>

// ---------------------------------------------------------------------------
// Galerkin linear attention, restructured:
//   [fused] k,v = x @ w_{k,v} (fp16 m16n8k16 mma, fp32 accum);
//           in-register instance norm; partial dots (split-tf32 3-pass)
//   dots = sum_chunks part ; A2 = blockdiag(dots)@w_out ; Wf[b]=w_q@A2[b]/n
//   out[b] = x[b] @ Wf[b] + b_out     (fp16 m16n8k16 mma, fp32 accum)
// Round-14: KSEG 4->8 (wf split-K, 512 blocks) and reduce_dots regrid to
// (32,8). Everything else identical to the 211.5us champion.
// ---------------------------------------------------------------------------

#define BATCH   4
#define NTOK    8192
#define DIM     256
#define HEADS   8
#define DH      64
#define INNER   512
#define TCH     128                 // tokens per fused chunk
#define NCH     (NTOK / TCH)        // 64
#define KSEG    8                   // split-K segments for Wf

__device__ float g_part[32 * NCH * DH * DH];   // 33.5 MB partial dots
__device__ float g_dots[32 * DH * DH];
__device__ float g_A2[BATCH * INNER * DIM];
__device__ float g_WfP[KSEG * BATCH * DIM * DIM];
__device__ float g_Wf[BATCH * DIM * DIM];

__device__ __forceinline__ uint32_t f2tf32(float f) {
    uint32_t r;
    asm("cvt.rna.tf32.f32 %0, %1;" : "=r"(r) : "f"(f));
    return r;
}

// round-to-nearest tf32 split via integer ops (ALU pipe, not convert pipe)
__device__ __forceinline__ void split_tf32(float f, uint32_t& hi, uint32_t& lo) {
    uint32_t b = __float_as_uint(f);
    hi = (b + 0x1000u) & 0xFFFFE000u;
    lo = __float_as_uint(f - __uint_as_float(hi));
}

__device__ __forceinline__ uint32_t pack_h2(float a, float b) {
    __half2 h = __floats2half2_rn(a, b);   // a -> low half (element 0)
    return *reinterpret_cast<uint32_t*>(&h);
}

__device__ __forceinline__ void mma_tf32(float* d, const uint32_t* a, const uint32_t* b) {
    asm volatile(
        "mma.sync.aligned.m16n8k8.row.col.f32.tf32.tf32.f32 "
        "{%0,%1,%2,%3}, {%4,%5,%6,%7}, {%8,%9}, {%0,%1,%2,%3};"
        : "+f"(d[0]), "+f"(d[1]), "+f"(d[2]), "+f"(d[3])
        : "r"(a[0]), "r"(a[1]), "r"(a[2]), "r"(a[3]), "r"(b[0]), "r"(b[1]));
}

__device__ __forceinline__ void mma_f16(float* d, const uint32_t* a, const uint32_t* b) {
    asm volatile(
        "mma.sync.aligned.m16n8k16.row.col.f32.f16.f16.f32 "
        "{%0,%1,%2,%3}, {%4,%5,%6,%7}, {%8,%9}, {%0,%1,%2,%3};"
        : "+f"(d[0]), "+f"(d[1]), "+f"(d[2]), "+f"(d[3])
        : "r"(a[0]), "r"(a[1]), "r"(a[2]), "r"(a[3]), "r"(b[0]), "r"(b[1]));
}

// ===========================================================================
// Fused: k/v projection (fp16 k16 mma) + in-register instance norm +
// split-tf32 partial dots. grid(32, NCH), 256 threads, dynamic smem.
// ===========================================================================
#define PA 136
#define PB 72
#define PS 72
#define FUSED_SMEM (2 * TCH * PS * 4)   // 73728 B (>= staging)

__global__ __launch_bounds__(256, 2) void fused_kv_dots(
    const float* __restrict__ x, const float* __restrict__ w_qkv,
    float* __restrict__ part)
{
    extern __shared__ unsigned char smraw[];
    uint32_t* As = (uint32_t*)smraw;           // [2][8][PA]  (x tile, half2 kpairs)
    uint32_t* Bk = As + 2 * 8 * PA;            // [2][8][PB]
    uint32_t* Bv = Bk + 2 * 8 * PB;
    float* sk = (float*)smraw;                 // [TCH][PS] (aliases staging)
    float* sv = sk + TCH * PS;

    const int tid = threadIdx.x;
    const int bh = blockIdx.x, chunk = blockIdx.y;   // bh fastest (L2 x reuse)
    const int b = bh >> 3, h = bh & 7;

    const float* xA  = x + ((long long)b * NTOK + (long long)chunk * TCH) * DIM;
    const float* wkp = w_qkv + INNER + h * DH;        // stride 3*INNER
    const float* wvp = w_qkv + 2 * INNER + h * DH;

    const int xRow = tid >> 1, xC = (tid & 1) * 8;
    const int xKP = (tid & 1) * 4;
    const int wKP = tid >> 5;
    const int wCc = (tid & 31) * 2;

    const int lane = tid & 31, wid = tid >> 5;
    const int g = lane >> 2, tg = lane & 3;
    const bool isV = (wid >= 4);
    const int warpM = (isV ? wid - 4 : wid) * 32;

    float acc[2][8][4];
    #pragma unroll
    for (int i = 0; i < 2; ++i)
        #pragma unroll
        for (int j = 0; j < 8; ++j)
            #pragma unroll
            for (int c = 0; c < 4; ++c) acc[i][j][c] = 0.f;

    // ---- phase 1: k/v = x @ w (K=256, 16 tiles of 16, double-buffered, fp16)
    float4 pa0, pa1;
    float2 pk0, pk1, pv0, pv1;
    {
        pa0 = *(const float4*)&xA[(long long)xRow * DIM + xC];
        pa1 = *(const float4*)&xA[(long long)xRow * DIM + xC + 4];
        pk0 = *(const float2*)&wkp[(long long)(2 * wKP) * (3 * INNER) + wCc];
        pk1 = *(const float2*)&wkp[(long long)(2 * wKP + 1) * (3 * INNER) + wCc];
        pv0 = *(const float2*)&wvp[(long long)(2 * wKP) * (3 * INNER) + wCc];
        pv1 = *(const float2*)&wvp[(long long)(2 * wKP + 1) * (3 * INNER) + wCc];
    }
    As[(xKP + 0) * PA + xRow] = pack_h2(pa0.x, pa0.y);
    As[(xKP + 1) * PA + xRow] = pack_h2(pa0.z, pa0.w);
    As[(xKP + 2) * PA + xRow] = pack_h2(pa1.x, pa1.y);
    As[(xKP + 3) * PA + xRow] = pack_h2(pa1.z, pa1.w);
    {
        uint2 uk = { pack_h2(pk0.x, pk1.x), pack_h2(pk0.y, pk1.y) };
        uint2 uv = { pack_h2(pv0.x, pv1.x), pack_h2(pv0.y, pv1.y) };
        *(uint2*)&Bk[wKP * PB + wCc] = uk;
        *(uint2*)&Bv[wKP * PB + wCc] = uv;
    }
    __syncthreads();

    const uint32_t* Bsel = isV ? Bv : Bk;

    for (int kt = 0; kt < 16; ++kt) {
        const int buf = kt & 1;
        if (kt + 1 < 16) {
            const int k0 = (kt + 1) * 16;
            pa0 = *(const float4*)&xA[(long long)xRow * DIM + k0 + xC];
            pa1 = *(const float4*)&xA[(long long)xRow * DIM + k0 + xC + 4];
            pk0 = *(const float2*)&wkp[(long long)(k0 + 2 * wKP) * (3 * INNER) + wCc];
            pk1 = *(const float2*)&wkp[(long long)(k0 + 2 * wKP + 1) * (3 * INNER) + wCc];
            pv0 = *(const float2*)&wvp[(long long)(k0 + 2 * wKP) * (3 * INNER) + wCc];
            pv1 = *(const float2*)&wvp[(long long)(k0 + 2 * wKP + 1) * (3 * INNER) + wCc];
        }

        {
            uint32_t af[2][4], bf[8][2];
            #pragma unroll
            for (int mt = 0; mt < 2; ++mt) {
                const int m = warpM + mt * 16;
                af[mt][0] = As[(buf * 8 + tg) * PA + m + g];
                af[mt][1] = As[(buf * 8 + tg) * PA + m + g + 8];
                af[mt][2] = As[(buf * 8 + tg + 4) * PA + m + g];
                af[mt][3] = As[(buf * 8 + tg + 4) * PA + m + g + 8];
            }
            #pragma unroll
            for (int nt = 0; nt < 8; ++nt) {
                bf[nt][0] = Bsel[(buf * 8 + tg) * PB + nt * 8 + g];
                bf[nt][1] = Bsel[(buf * 8 + tg + 4) * PB + nt * 8 + g];
            }
            #pragma unroll
            for (int mt = 0; mt < 2; ++mt)
                #pragma unroll
                for (int nt = 0; nt < 8; ++nt)
                    mma_f16(acc[mt][nt], af[mt], bf[nt]);
        }

        if (kt + 1 < 16) {
            const int nb = 1 - buf;
            As[(nb * 8 + xKP + 0) * PA + xRow] = pack_h2(pa0.x, pa0.y);
            As[(nb * 8 + xKP + 1) * PA + xRow] = pack_h2(pa0.z, pa0.w);
            As[(nb * 8 + xKP + 2) * PA + xRow] = pack_h2(pa1.x, pa1.y);
            As[(nb * 8 + xKP + 3) * PA + xRow] = pack_h2(pa1.z, pa1.w);
            uint2 uk = { pack_h2(pk0.x, pk1.x), pack_h2(pk0.y, pk1.y) };
            uint2 uv = { pack_h2(pv0.x, pv1.x), pack_h2(pv0.y, pv1.y) };
            *(uint2*)&Bk[(nb * 8 + wKP) * PB + wCc] = uk;
            *(uint2*)&Bv[(nb * 8 + wKP) * PB + wCc] = uv;
            __syncthreads();
        }
    }

    __syncthreads();

    // ---- phase 2: in-register instance norm ----
    float* sdst = isV ? sv : sk;
    #pragma unroll
    for (int mt = 0; mt < 2; ++mt) {
        #pragma unroll
        for (int rr = 0; rr < 2; ++rr) {
            float s = 0.f, q = 0.f;
            #pragma unroll
            for (int nt = 0; nt < 8; ++nt) {
                float v0 = acc[mt][nt][2 * rr], v1 = acc[mt][nt][2 * rr + 1];
                s += v0 + v1;
                q += v0 * v0 + v1 * v1;
            }
            s += __shfl_xor_sync(0xFFFFFFFFu, s, 1);
            s += __shfl_xor_sync(0xFFFFFFFFu, s, 2);
            q += __shfl_xor_sync(0xFFFFFFFFu, q, 1);
            q += __shfl_xor_sync(0xFFFFFFFFu, q, 2);
            const float mu  = s * (1.0f / 64.0f);
            const float var = q * (1.0f / 64.0f) - mu * mu;
            const float inv = rsqrtf(var + 1e-5f);
            const int row = warpM + mt * 16 + g + rr * 8;
            #pragma unroll
            for (int nt = 0; nt < 8; ++nt) {
                float2 o = { (acc[mt][nt][2 * rr] - mu) * inv,
                             (acc[mt][nt][2 * rr + 1] - mu) * inv };
                *(float2*)&sdst[row * PS + nt * 8 + 2 * tg] = o;
            }
        }
    }
    __syncthreads();

    // ---- phase 3: partial dots = k-hat^T @ v-hat (split tf32: hh+hl+lh) ----
    const int n0 = wid * 8;
    float d[4][4];
    #pragma unroll
    for (int mt = 0; mt < 4; ++mt)
        #pragma unroll
        for (int c = 0; c < 4; ++c) d[mt][c] = 0.f;

    for (int kk = 0; kk < TCH; kk += 8) {
        uint32_t ah[4][4], al[4][4], bhv[2], blv[2];
        #pragma unroll
        for (int mt = 0; mt < 4; ++mt) {
            const int m = mt * 16;
            float f0 = sk[(kk + tg) * PS + m + g];
            float f1 = sk[(kk + tg) * PS + m + g + 8];
            float f2 = sk[(kk + tg + 4) * PS + m + g];
            float f3 = sk[(kk + tg + 4) * PS + m + g + 8];
            split_tf32(f0, ah[mt][0], al[mt][0]);
            split_tf32(f1, ah[mt][1], al[mt][1]);
            split_tf32(f2, ah[mt][2], al[mt][2]);
            split_tf32(f3, ah[mt][3], al[mt][3]);
        }
        {
            float e0 = sv[(kk + tg) * PS + n0 + g];
            float e1 = sv[(kk + tg + 4) * PS + n0 + g];
            split_tf32(e0, bhv[0], blv[0]);
            split_tf32(e1, bhv[1], blv[1]);
        }
        #pragma unroll
        for (int mt = 0; mt < 4; ++mt) mma_tf32(d[mt], ah[mt], bhv);
        #pragma unroll
        for (int mt = 0; mt < 4; ++mt) mma_tf32(d[mt], ah[mt], blv);
        #pragma unroll
        for (int mt = 0; mt < 4; ++mt) mma_tf32(d[mt], al[mt], bhv);
    }

    float* op = part + (long long)(bh * NCH + chunk) * (DH * DH);
    #pragma unroll
    for (int mt = 0; mt < 4; ++mt) {
        const int e = mt * 16 + g;
        float2 lo = { d[mt][0], d[mt][1] };
        float2 hi = { d[mt][2], d[mt][3] };
        *(float2*)&op[e * DH + n0 + 2 * tg] = lo;
        *(float2*)&op[(e + 8) * DH + n0 + 2 * tg] = hi;
    }
}

// ===========================================================================
__global__ __launch_bounds__(256) void reduce_dots(
    const float* __restrict__ part, float* __restrict__ dots)
{
    const int bh = blockIdx.x, seg = blockIdx.y;   // grid (32,8)
    #pragma unroll
    for (int j = 0; j < 2; ++j) {
        const int idx = seg * 512 + j * 256 + threadIdx.x;
        float s = 0.f;
        #pragma unroll 8
        for (int c = 0; c < NCH; ++c)
            s += part[(long long)(bh * NCH + c) * (DH * DH) + idx];
        dots[bh * DH * DH + idx] = s;
    }
}

// A2[b, h*64+e, j] = sum_f dots[b,h][e,f] * w_out[h*64+f, j]; grid (32, 8)
__global__ __launch_bounds__(256) void dots_wout(
    const float* __restrict__ dots, const float* __restrict__ w_out,
    float* __restrict__ A2)
{
    const int bh = blockIdx.x, jt = blockIdx.y;
    const int b = bh >> 3, h = bh & 7;
    __shared__ float sd[DH * DH];
    __shared__ float sw[DH][33];
    for (int i = threadIdx.x; i < DH * DH; i += 256) sd[i] = dots[bh * DH * DH + i];
    for (int i = threadIdx.x; i < DH * 32; i += 256) {
        const int f = i >> 5, j = i & 31;
        sw[f][j] = w_out[(h * DH + f) * DIM + jt * 32 + j];
    }
    __syncthreads();
    for (int idx = threadIdx.x; idx < DH * 32; idx += 256) {
        const int e = idx >> 5, j = idx & 31;
        float s = 0.f;
        #pragma unroll 8
        for (int f = 0; f < DH; ++f) s += sd[e * DH + f] * sw[f][j];
        A2[((long long)b * INNER + h * DH + e) * DIM + jt * 32 + j] = s;
    }
}

// ===========================================================================
// WfP[seg][b] = w_q[:, seg*64:(seg+1)*64] @ A2[b][seg*64:(seg+1)*64, :]
// grid (4 jt, 4 mt, BATCH*KSEG=32) = 512 blocks. 64x64 tile, BK=16, fp32.
// ===========================================================================
__global__ __launch_bounds__(256) void wf_gemm_splitk(
    const float* __restrict__ w_qkv, const float* __restrict__ A2,
    float* __restrict__ WfP)
{
    __shared__ float sA[16][68];
    __shared__ float sB[16][68];

    const int tid = threadIdx.x;
    const int m0 = blockIdx.y * 64, j0 = blockIdx.x * 64;
    const int bz = blockIdx.z;
    const int b = bz >> 3, seg = bz & 7;
    const int kbase = seg * (INNER / KSEG);          // seg*64

    const float* Bb = A2 + (long long)b * INNER * DIM;

    const int am = tid >> 2, akq = (tid & 3) * 4;
    const int bk = tid >> 4, bj = (tid & 15) * 4;
    const int ty = (tid >> 4) << 2;
    const int tx = (tid & 15) << 2;

    float acc[4][4] = {};

    for (int k0 = 0; k0 < INNER / KSEG; k0 += 16) {
        float4 a4 = *(const float4*)&w_qkv[(long long)(m0 + am) * (3 * INNER) + kbase + k0 + akq];
        sA[akq + 0][am] = a4.x;
        sA[akq + 1][am] = a4.y;
        sA[akq + 2][am] = a4.z;
        sA[akq + 3][am] = a4.w;
        float4 b4 = *(const float4*)&Bb[(long long)(kbase + k0 + bk) * DIM + j0 + bj];
        *(float4*)&sB[bk][bj] = b4;
        __syncthreads();
        #pragma unroll
        for (int kk = 0; kk < 16; ++kk) {
            float a[4], bb[4];
            #pragma unroll
            for (int i = 0; i < 4; ++i) a[i] = sA[kk][ty + i];
            #pragma unroll
            for (int j = 0; j < 4; ++j) bb[j] = sB[kk][tx + j];
            #pragma unroll
            for (int i = 0; i < 4; ++i)
                #pragma unroll
                for (int j = 0; j < 4; ++j) acc[i][j] += a[i] * bb[j];
        }
        __syncthreads();
    }

    float* C = WfP + ((long long)bz) * DIM * DIM;
    #pragma unroll
    for (int i = 0; i < 4; ++i) {
        float4 o = { acc[i][0], acc[i][1], acc[i][2], acc[i][3] };
        *(float4*)&C[(long long)(m0 + ty + i) * DIM + j0 + tx] = o;
    }
}

__global__ __launch_bounds__(256) void wf_reduce(
    const float* __restrict__ WfP, float* __restrict__ Wf)
{
    const int idx = blockIdx.x * 256 + threadIdx.x;
    const int b = idx / (DIM * DIM);
    const int r = idx % (DIM * DIM);
    float s = 0.f;
    #pragma unroll
    for (int seg = 0; seg < KSEG; ++seg)
        s += WfP[((long long)(b * KSEG + seg)) * DIM * DIM + r];
    Wf[idx] = s * (1.0f / (float)NTOK);
}

// ===========================================================================
// Final GEMM: out[b] = x[b] @ Wf[b] + b_out  (fp16 m16n8k16, fp32 accum)
// ===========================================================================
__global__ __launch_bounds__(256, 2) void gemm_f16(
    const float* __restrict__ x, const float* __restrict__ Wf,
    const float* __restrict__ bias, float* __restrict__ out)
{
    __shared__ uint32_t As[2][8][132];   // [kpair][m]
    __shared__ uint32_t Bs[2][8][132];   // [kpair][n]

    const int tid = threadIdx.x;
    const int bx = blockIdx.x, by = blockIdx.y, bz = blockIdx.z;

    const float* A = x + (long long)bz * NTOK * DIM + (long long)by * 128 * DIM;
    const float* B = Wf + (long long)bz * DIM * DIM + (long long)bx * 128;
    float* C = out + (long long)bz * NTOK * DIM + (long long)by * 128 * DIM
                   + (long long)bx * 128;

    const int aRow = tid >> 2, aCol = (tid & 3) * 4, aKP = (tid & 3) * 2;
    const int bKP = tid >> 5, bCol = (tid & 31) * 4;

    const int lane = tid & 31, wid = tid >> 5;
    const int warpM = (wid >> 2) * 64;
    const int warpN = (wid & 3) * 32;
    const int g = lane >> 2, tg = lane & 3;

    float acc[4][4][4];
    #pragma unroll
    for (int i = 0; i < 4; ++i)
        #pragma unroll
        for (int j = 0; j < 4; ++j)
            #pragma unroll
            for (int c = 0; c < 4; ++c) acc[i][j][c] = 0.f;

    // prologue
    {
        float4 a0 = *(const float4*)&A[(long long)aRow * DIM + aCol];
        float4 a1 = *(const float4*)&A[(long long)(aRow + 64) * DIM + aCol];
        As[0][aKP + 0][aRow] = pack_h2(a0.x, a0.y);
        As[0][aKP + 1][aRow] = pack_h2(a0.z, a0.w);
        As[0][aKP + 0][aRow + 64] = pack_h2(a1.x, a1.y);
        As[0][aKP + 1][aRow + 64] = pack_h2(a1.z, a1.w);
        float4 b0 = *(const float4*)&B[(long long)(2 * bKP) * DIM + bCol];
        float4 b1 = *(const float4*)&B[(long long)(2 * bKP + 1) * DIM + bCol];
        uint4 u = { pack_h2(b0.x, b1.x), pack_h2(b0.y, b1.y),
                    pack_h2(b0.z, b1.z), pack_h2(b0.w, b1.w) };
        *(uint4*)&Bs[0][bKP][bCol] = u;
    }
    __syncthreads();

    for (int kt = 0; kt < 16; ++kt) {
        const int buf = kt & 1;
        float4 pa0, pa1, pb0, pb1;
        if (kt + 1 < 16) {
            const int k0 = (kt + 1) * 16;
            pa0 = *(const float4*)&A[(long long)aRow * DIM + k0 + aCol];
            pa1 = *(const float4*)&A[(long long)(aRow + 64) * DIM + k0 + aCol];
            pb0 = *(const float4*)&B[(long long)(k0 + 2 * bKP) * DIM + bCol];
            pb1 = *(const float4*)&B[(long long)(k0 + 2 * bKP + 1) * DIM + bCol];
        }

        {
            uint32_t af[4][4], bf[4][2];
            #pragma unroll
            for (int mt = 0; mt < 4; ++mt) {
                const int m = warpM + mt * 16;
                af[mt][0] = As[buf][tg][m + g];
                af[mt][1] = As[buf][tg][m + g + 8];
                af[mt][2] = As[buf][tg + 4][m + g];
                af[mt][3] = As[buf][tg + 4][m + g + 8];
            }
            #pragma unroll
            for (int nt = 0; nt < 4; ++nt) {
                const int n = warpN + nt * 8;
                bf[nt][0] = Bs[buf][tg][n + g];
                bf[nt][1] = Bs[buf][tg + 4][n + g];
            }
            #pragma unroll
            for (int mt = 0; mt < 4; ++mt)
                #pragma unroll
                for (int nt = 0; nt < 4; ++nt)
                    mma_f16(acc[mt][nt], af[mt], bf[nt]);
        }

        if (kt + 1 < 16) {
            const int nb = 1 - buf;
            As[nb][aKP + 0][aRow] = pack_h2(pa0.x, pa0.y);
            As[nb][aKP + 1][aRow] = pack_h2(pa0.z, pa0.w);
            As[nb][aKP + 0][aRow + 64] = pack_h2(pa1.x, pa1.y);
            As[nb][aKP + 1][aRow + 64] = pack_h2(pa1.z, pa1.w);
            uint4 u = { pack_h2(pb0.x, pb1.x), pack_h2(pb0.y, pb1.y),
                        pack_h2(pb0.z, pb1.z), pack_h2(pb0.w, pb1.w) };
            *(uint4*)&Bs[nb][bKP][bCol] = u;
            __syncthreads();
        }
    }

    #pragma unroll
    for (int mt = 0; mt < 4; ++mt) {
        const int r0 = warpM + mt * 16 + g;
        #pragma unroll
        for (int nt = 0; nt < 4; ++nt) {
            const int c0 = warpN + nt * 8 + 2 * tg;
            const int gcol = bx * 128 + c0;
            const float bx0 = bias[gcol], bx1 = bias[gcol + 1];
            float2 lo = { acc[mt][nt][0] + bx0, acc[mt][nt][1] + bx1 };
            float2 hi = { acc[mt][nt][2] + bx0, acc[mt][nt][3] + bx1 };
            *(float2*)&C[(long long)r0 * DIM + c0] = lo;
            *(float2*)&C[(long long)(r0 + 8) * DIM + c0] = hi;
        }
    }
}

// ---------------------------------------------------------------------------
extern "C" void kernel_launch(void* const* d_in, const int* in_sizes, int n_in,
                              void* d_out, int out_size)
{
    const float* x      = (const float*)d_in[0];  // [4, 8192, 256]
    const float* w_qkv  = (const float*)d_in[1];  // [256, 1536]
    const float* w_out  = (const float*)d_in[2];  // [512, 256]
    const float* b_out  = (const float*)d_in[3];  // [256]
    float*       out    = (float*)d_out;          // [4, 8192, 256]

    float *part, *dots, *A2, *WfP, *Wf;
    cudaGetSymbolAddress((void**)&part, g_part);
    cudaGetSymbolAddress((void**)&dots, g_dots);
    cudaGetSymbolAddress((void**)&A2,   g_A2);
    cudaGetSymbolAddress((void**)&WfP,  g_WfP);
    cudaGetSymbolAddress((void**)&Wf,   g_Wf);

    cudaFuncSetAttribute(fused_kv_dots,
                         cudaFuncAttributeMaxDynamicSharedMemorySize, FUSED_SMEM);

    // 1) fused: k/v projection + instance norm + partial dots
    fused_kv_dots<<<dim3(32, NCH), 256, FUSED_SMEM>>>(x, w_qkv, part);

    // 2) deterministic chunk reduction
    reduce_dots<<<dim3(32, 8), 256>>>(part, dots);

    // 3) A2 = blockdiag(dots) @ w_out ; Wf[b] = w_q @ A2[b] / n (split-K x8)
    dots_wout<<<dim3(32, 8), 256>>>(dots, w_out, A2);
    wf_gemm_splitk<<<dim3(4, 4, BATCH * KSEG), 256>>>(w_qkv, A2, WfP);
    wf_reduce<<<(BATCH * DIM * DIM) / 256, 256>>>(WfP, Wf);

    // 4) out[b] = x[b] @ Wf[b] + b_out  (fp16 k16 TC)
    gemm_f16<<<dim3(DIM / 128, NTOK / 128, BATCH), 256>>>(x, Wf, b_out, out);
}

// round 15
// speedup vs baseline: 1.5703x; 1.0319x over previous
#include <cuda_runtime.h>
#include <cuda_fp16.h>
#include <cuda_bf16.h>
#include <cstdint>

// ---------------------------------------------------------------------------
// Galerkin linear attention, restructured:
//   [fused] k,v = x @ w_{k,v} (fp16 m16n8k16 mma, fp32 accum);
//           in-register instance norm; partial dots (split-tf32 3-pass)
//   dots = sum_chunks part ; A2 = blockdiag(dots)@w_out ; Wf[b]=w_q@A2[b]/n
//   out[b] = x[b] @ Wf[b] + b_out     (fp16 m16n8k16 mma, fp32 accum)
// Round-15: phase-3 warp retile (m16 x n32 per warp) removes the 8x redundant
// A-fragment loads/splits. Everything else identical to the 207.3us champion.
// ---------------------------------------------------------------------------

#define BATCH   4
#define NTOK    8192
#define DIM     256
#define HEADS   8
#define DH      64
#define INNER   512
#define TCH     128                 // tokens per fused chunk
#define NCH     (NTOK / TCH)        // 64
#define KSEG    8                   // split-K segments for Wf

__device__ float g_part[32 * NCH * DH * DH];   // 33.5 MB partial dots
__device__ float g_dots[32 * DH * DH];
__device__ float g_A2[BATCH * INNER * DIM];
__device__ float g_WfP[KSEG * BATCH * DIM * DIM];
__device__ float g_Wf[BATCH * DIM * DIM];

__device__ __forceinline__ uint32_t f2tf32(float f) {
    uint32_t r;
    asm("cvt.rna.tf32.f32 %0, %1;" : "=r"(r) : "f"(f));
    return r;
}

// round-to-nearest tf32 split via integer ops (ALU pipe, not convert pipe)
__device__ __forceinline__ void split_tf32(float f, uint32_t& hi, uint32_t& lo) {
    uint32_t b = __float_as_uint(f);
    hi = (b + 0x1000u) & 0xFFFFE000u;
    lo = __float_as_uint(f - __uint_as_float(hi));
}

__device__ __forceinline__ uint32_t pack_h2(float a, float b) {
    __half2 h = __floats2half2_rn(a, b);   // a -> low half (element 0)
    return *reinterpret_cast<uint32_t*>(&h);
}

__device__ __forceinline__ void mma_tf32(float* d, const uint32_t* a, const uint32_t* b) {
    asm volatile(
        "mma.sync.aligned.m16n8k8.row.col.f32.tf32.tf32.f32 "
        "{%0,%1,%2,%3}, {%4,%5,%6,%7}, {%8,%9}, {%0,%1,%2,%3};"
        : "+f"(d[0]), "+f"(d[1]), "+f"(d[2]), "+f"(d[3])
        : "r"(a[0]), "r"(a[1]), "r"(a[2]), "r"(a[3]), "r"(b[0]), "r"(b[1]));
}

__device__ __forceinline__ void mma_f16(float* d, const uint32_t* a, const uint32_t* b) {
    asm volatile(
        "mma.sync.aligned.m16n8k16.row.col.f32.f16.f16.f32 "
        "{%0,%1,%2,%3}, {%4,%5,%6,%7}, {%8,%9}, {%0,%1,%2,%3};"
        : "+f"(d[0]), "+f"(d[1]), "+f"(d[2]), "+f"(d[3])
        : "r"(a[0]), "r"(a[1]), "r"(a[2]), "r"(a[3]), "r"(b[0]), "r"(b[1]));
}

// ===========================================================================
// Fused: k/v projection (fp16 k16 mma) + in-register instance norm +
// split-tf32 partial dots. grid(32, NCH), 256 threads, dynamic smem.
// ===========================================================================
#define PA 136
#define PB 72
#define PS 72
#define FUSED_SMEM (2 * TCH * PS * 4)   // 73728 B (>= staging)

__global__ __launch_bounds__(256, 2) void fused_kv_dots(
    const float* __restrict__ x, const float* __restrict__ w_qkv,
    float* __restrict__ part)
{
    extern __shared__ unsigned char smraw[];
    uint32_t* As = (uint32_t*)smraw;           // [2][8][PA]  (x tile, half2 kpairs)
    uint32_t* Bk = As + 2 * 8 * PA;            // [2][8][PB]
    uint32_t* Bv = Bk + 2 * 8 * PB;
    float* sk = (float*)smraw;                 // [TCH][PS] (aliases staging)
    float* sv = sk + TCH * PS;

    const int tid = threadIdx.x;
    const int bh = blockIdx.x, chunk = blockIdx.y;   // bh fastest (L2 x reuse)
    const int b = bh >> 3, h = bh & 7;

    const float* xA  = x + ((long long)b * NTOK + (long long)chunk * TCH) * DIM;
    const float* wkp = w_qkv + INNER + h * DH;        // stride 3*INNER
    const float* wvp = w_qkv + 2 * INNER + h * DH;

    const int xRow = tid >> 1, xC = (tid & 1) * 8;
    const int xKP = (tid & 1) * 4;
    const int wKP = tid >> 5;
    const int wCc = (tid & 31) * 2;

    const int lane = tid & 31, wid = tid >> 5;
    const int g = lane >> 2, tg = lane & 3;
    const bool isV = (wid >= 4);
    const int warpM = (isV ? wid - 4 : wid) * 32;

    float acc[2][8][4];
    #pragma unroll
    for (int i = 0; i < 2; ++i)
        #pragma unroll
        for (int j = 0; j < 8; ++j)
            #pragma unroll
            for (int c = 0; c < 4; ++c) acc[i][j][c] = 0.f;

    // ---- phase 1: k/v = x @ w (K=256, 16 tiles of 16, double-buffered, fp16)
    float4 pa0, pa1;
    float2 pk0, pk1, pv0, pv1;
    {
        pa0 = *(const float4*)&xA[(long long)xRow * DIM + xC];
        pa1 = *(const float4*)&xA[(long long)xRow * DIM + xC + 4];
        pk0 = *(const float2*)&wkp[(long long)(2 * wKP) * (3 * INNER) + wCc];
        pk1 = *(const float2*)&wkp[(long long)(2 * wKP + 1) * (3 * INNER) + wCc];
        pv0 = *(const float2*)&wvp[(long long)(2 * wKP) * (3 * INNER) + wCc];
        pv1 = *(const float2*)&wvp[(long long)(2 * wKP + 1) * (3 * INNER) + wCc];
    }
    As[(xKP + 0) * PA + xRow] = pack_h2(pa0.x, pa0.y);
    As[(xKP + 1) * PA + xRow] = pack_h2(pa0.z, pa0.w);
    As[(xKP + 2) * PA + xRow] = pack_h2(pa1.x, pa1.y);
    As[(xKP + 3) * PA + xRow] = pack_h2(pa1.z, pa1.w);
    {
        uint2 uk = { pack_h2(pk0.x, pk1.x), pack_h2(pk0.y, pk1.y) };
        uint2 uv = { pack_h2(pv0.x, pv1.x), pack_h2(pv0.y, pv1.y) };
        *(uint2*)&Bk[wKP * PB + wCc] = uk;
        *(uint2*)&Bv[wKP * PB + wCc] = uv;
    }
    __syncthreads();

    const uint32_t* Bsel = isV ? Bv : Bk;

    for (int kt = 0; kt < 16; ++kt) {
        const int buf = kt & 1;
        if (kt + 1 < 16) {
            const int k0 = (kt + 1) * 16;
            pa0 = *(const float4*)&xA[(long long)xRow * DIM + k0 + xC];
            pa1 = *(const float4*)&xA[(long long)xRow * DIM + k0 + xC + 4];
            pk0 = *(const float2*)&wkp[(long long)(k0 + 2 * wKP) * (3 * INNER) + wCc];
            pk1 = *(const float2*)&wkp[(long long)(k0 + 2 * wKP + 1) * (3 * INNER) + wCc];
            pv0 = *(const float2*)&wvp[(long long)(k0 + 2 * wKP) * (3 * INNER) + wCc];
            pv1 = *(const float2*)&wvp[(long long)(k0 + 2 * wKP + 1) * (3 * INNER) + wCc];
        }

        {
            uint32_t af[2][4], bf[8][2];
            #pragma unroll
            for (int mt = 0; mt < 2; ++mt) {
                const int m = warpM + mt * 16;
                af[mt][0] = As[(buf * 8 + tg) * PA + m + g];
                af[mt][1] = As[(buf * 8 + tg) * PA + m + g + 8];
                af[mt][2] = As[(buf * 8 + tg + 4) * PA + m + g];
                af[mt][3] = As[(buf * 8 + tg + 4) * PA + m + g + 8];
            }
            #pragma unroll
            for (int nt = 0; nt < 8; ++nt) {
                bf[nt][0] = Bsel[(buf * 8 + tg) * PB + nt * 8 + g];
                bf[nt][1] = Bsel[(buf * 8 + tg + 4) * PB + nt * 8 + g];
            }
            #pragma unroll
            for (int mt = 0; mt < 2; ++mt)
                #pragma unroll
                for (int nt = 0; nt < 8; ++nt)
                    mma_f16(acc[mt][nt], af[mt], bf[nt]);
        }

        if (kt + 1 < 16) {
            const int nb = 1 - buf;
            As[(nb * 8 + xKP + 0) * PA + xRow] = pack_h2(pa0.x, pa0.y);
            As[(nb * 8 + xKP + 1) * PA + xRow] = pack_h2(pa0.z, pa0.w);
            As[(nb * 8 + xKP + 2) * PA + xRow] = pack_h2(pa1.x, pa1.y);
            As[(nb * 8 + xKP + 3) * PA + xRow] = pack_h2(pa1.z, pa1.w);
            uint2 uk = { pack_h2(pk0.x, pk1.x), pack_h2(pk0.y, pk1.y) };
            uint2 uv = { pack_h2(pv0.x, pv1.x), pack_h2(pv0.y, pv1.y) };
            *(uint2*)&Bk[(nb * 8 + wKP) * PB + wCc] = uk;
            *(uint2*)&Bv[(nb * 8 + wKP) * PB + wCc] = uv;
            __syncthreads();
        }
    }

    __syncthreads();

    // ---- phase 2: in-register instance norm ----
    float* sdst = isV ? sv : sk;
    #pragma unroll
    for (int mt = 0; mt < 2; ++mt) {
        #pragma unroll
        for (int rr = 0; rr < 2; ++rr) {
            float s = 0.f, q = 0.f;
            #pragma unroll
            for (int nt = 0; nt < 8; ++nt) {
                float v0 = acc[mt][nt][2 * rr], v1 = acc[mt][nt][2 * rr + 1];
                s += v0 + v1;
                q += v0 * v0 + v1 * v1;
            }
            s += __shfl_xor_sync(0xFFFFFFFFu, s, 1);
            s += __shfl_xor_sync(0xFFFFFFFFu, s, 2);
            q += __shfl_xor_sync(0xFFFFFFFFu, q, 1);
            q += __shfl_xor_sync(0xFFFFFFFFu, q, 2);
            const float mu  = s * (1.0f / 64.0f);
            const float var = q * (1.0f / 64.0f) - mu * mu;
            const float inv = rsqrtf(var + 1e-5f);
            const int row = warpM + mt * 16 + g + rr * 8;
            #pragma unroll
            for (int nt = 0; nt < 8; ++nt) {
                float2 o = { (acc[mt][nt][2 * rr] - mu) * inv,
                             (acc[mt][nt][2 * rr + 1] - mu) * inv };
                *(float2*)&sdst[row * PS + nt * 8 + 2 * tg] = o;
            }
        }
    }
    __syncthreads();

    // ---- phase 3: partial dots = k-hat^T @ v-hat (split tf32: hh+hl+lh) ----
    // warp tile: m-tile mw = (wid>>1)*16, n-half nh = (wid&1)*32 (4 n-tiles).
    const int mw = (wid >> 1) * 16;
    const int nh = (wid & 1) * 32;
    float d[4][4];
    #pragma unroll
    for (int nt = 0; nt < 4; ++nt)
        #pragma unroll
        for (int c = 0; c < 4; ++c) d[nt][c] = 0.f;

    for (int kk = 0; kk < TCH; kk += 8) {
        uint32_t ah[4], al[4], bhv[4][2], blv[4][2];
        {
            float f0 = sk[(kk + tg) * PS + mw + g];
            float f1 = sk[(kk + tg) * PS + mw + g + 8];
            float f2 = sk[(kk + tg + 4) * PS + mw + g];
            float f3 = sk[(kk + tg + 4) * PS + mw + g + 8];
            split_tf32(f0, ah[0], al[0]);
            split_tf32(f1, ah[1], al[1]);
            split_tf32(f2, ah[2], al[2]);
            split_tf32(f3, ah[3], al[3]);
        }
        #pragma unroll
        for (int nt = 0; nt < 4; ++nt) {
            float e0 = sv[(kk + tg) * PS + nh + nt * 8 + g];
            float e1 = sv[(kk + tg + 4) * PS + nh + nt * 8 + g];
            split_tf32(e0, bhv[nt][0], blv[nt][0]);
            split_tf32(e1, bhv[nt][1], blv[nt][1]);
        }
        #pragma unroll
        for (int nt = 0; nt < 4; ++nt) mma_tf32(d[nt], ah, bhv[nt]);
        #pragma unroll
        for (int nt = 0; nt < 4; ++nt) mma_tf32(d[nt], ah, blv[nt]);
        #pragma unroll
        for (int nt = 0; nt < 4; ++nt) mma_tf32(d[nt], al, bhv[nt]);
    }

    float* op = part + (long long)(bh * NCH + chunk) * (DH * DH);
    #pragma unroll
    for (int nt = 0; nt < 4; ++nt) {
        const int e = mw + g;
        const int c = nh + nt * 8 + 2 * tg;
        float2 lo = { d[nt][0], d[nt][1] };
        float2 hi = { d[nt][2], d[nt][3] };
        *(float2*)&op[e * DH + c] = lo;
        *(float2*)&op[(e + 8) * DH + c] = hi;
    }
}

// ===========================================================================
__global__ __launch_bounds__(256) void reduce_dots(
    const float* __restrict__ part, float* __restrict__ dots)
{
    const int bh = blockIdx.x, seg = blockIdx.y;   // grid (32,8)
    #pragma unroll
    for (int j = 0; j < 2; ++j) {
        const int idx = seg * 512 + j * 256 + threadIdx.x;
        float s = 0.f;
        #pragma unroll 8
        for (int c = 0; c < NCH; ++c)
            s += part[(long long)(bh * NCH + c) * (DH * DH) + idx];
        dots[bh * DH * DH + idx] = s;
    }
}

// A2[b, h*64+e, j] = sum_f dots[b,h][e,f] * w_out[h*64+f, j]; grid (32, 8)
__global__ __launch_bounds__(256) void dots_wout(
    const float* __restrict__ dots, const float* __restrict__ w_out,
    float* __restrict__ A2)
{
    const int bh = blockIdx.x, jt = blockIdx.y;
    const int b = bh >> 3, h = bh & 7;
    __shared__ float sd[DH * DH];
    __shared__ float sw[DH][33];
    for (int i = threadIdx.x; i < DH * DH; i += 256) sd[i] = dots[bh * DH * DH + i];
    for (int i = threadIdx.x; i < DH * 32; i += 256) {
        const int f = i >> 5, j = i & 31;
        sw[f][j] = w_out[(h * DH + f) * DIM + jt * 32 + j];
    }
    __syncthreads();
    for (int idx = threadIdx.x; idx < DH * 32; idx += 256) {
        const int e = idx >> 5, j = idx & 31;
        float s = 0.f;
        #pragma unroll 8
        for (int f = 0; f < DH; ++f) s += sd[e * DH + f] * sw[f][j];
        A2[((long long)b * INNER + h * DH + e) * DIM + jt * 32 + j] = s;
    }
}

// ===========================================================================
// WfP[seg][b] = w_q[:, seg*64:(seg+1)*64] @ A2[b][seg*64:(seg+1)*64, :]
// grid (4 jt, 4 mt, BATCH*KSEG=32) = 512 blocks. 64x64 tile, BK=16, fp32.
// ===========================================================================
__global__ __launch_bounds__(256) void wf_gemm_splitk(
    const float* __restrict__ w_qkv, const float* __restrict__ A2,
    float* __restrict__ WfP)
{
    __shared__ float sA[16][68];
    __shared__ float sB[16][68];

    const int tid = threadIdx.x;
    const int m0 = blockIdx.y * 64, j0 = blockIdx.x * 64;
    const int bz = blockIdx.z;
    const int b = bz >> 3, seg = bz & 7;
    const int kbase = seg * (INNER / KSEG);          // seg*64

    const float* Bb = A2 + (long long)b * INNER * DIM;

    const int am = tid >> 2, akq = (tid & 3) * 4;
    const int bk = tid >> 4, bj = (tid & 15) * 4;
    const int ty = (tid >> 4) << 2;
    const int tx = (tid & 15) << 2;

    float acc[4][4] = {};

    for (int k0 = 0; k0 < INNER / KSEG; k0 += 16) {
        float4 a4 = *(const float4*)&w_qkv[(long long)(m0 + am) * (3 * INNER) + kbase + k0 + akq];
        sA[akq + 0][am] = a4.x;
        sA[akq + 1][am] = a4.y;
        sA[akq + 2][am] = a4.z;
        sA[akq + 3][am] = a4.w;
        float4 b4 = *(const float4*)&Bb[(long long)(kbase + k0 + bk) * DIM + j0 + bj];
        *(float4*)&sB[bk][bj] = b4;
        __syncthreads();
        #pragma unroll
        for (int kk = 0; kk < 16; ++kk) {
            float a[4], bb[4];
            #pragma unroll
            for (int i = 0; i < 4; ++i) a[i] = sA[kk][ty + i];
            #pragma unroll
            for (int j = 0; j < 4; ++j) bb[j] = sB[kk][tx + j];
            #pragma unroll
            for (int i = 0; i < 4; ++i)
                #pragma unroll
                for (int j = 0; j < 4; ++j) acc[i][j] += a[i] * bb[j];
        }
        __syncthreads();
    }

    float* C = WfP + ((long long)bz) * DIM * DIM;
    #pragma unroll
    for (int i = 0; i < 4; ++i) {
        float4 o = { acc[i][0], acc[i][1], acc[i][2], acc[i][3] };
        *(float4*)&C[(long long)(m0 + ty + i) * DIM + j0 + tx] = o;
    }
}

__global__ __launch_bounds__(256) void wf_reduce(
    const float* __restrict__ WfP, float* __restrict__ Wf)
{
    const int idx = blockIdx.x * 256 + threadIdx.x;
    const int b = idx / (DIM * DIM);
    const int r = idx % (DIM * DIM);
    float s = 0.f;
    #pragma unroll
    for (int seg = 0; seg < KSEG; ++seg)
        s += WfP[((long long)(b * KSEG + seg)) * DIM * DIM + r];
    Wf[idx] = s * (1.0f / (float)NTOK);
}

// ===========================================================================
// Final GEMM: out[b] = x[b] @ Wf[b] + b_out  (fp16 m16n8k16, fp32 accum)
// ===========================================================================
__global__ __launch_bounds__(256, 2) void gemm_f16(
    const float* __restrict__ x, const float* __restrict__ Wf,
    const float* __restrict__ bias, float* __restrict__ out)
{
    __shared__ uint32_t As[2][8][132];   // [kpair][m]
    __shared__ uint32_t Bs[2][8][132];   // [kpair][n]

    const int tid = threadIdx.x;
    const int bx = blockIdx.x, by = blockIdx.y, bz = blockIdx.z;

    const float* A = x + (long long)bz * NTOK * DIM + (long long)by * 128 * DIM;
    const float* B = Wf + (long long)bz * DIM * DIM + (long long)bx * 128;
    float* C = out + (long long)bz * NTOK * DIM + (long long)by * 128 * DIM
                   + (long long)bx * 128;

    const int aRow = tid >> 2, aCol = (tid & 3) * 4, aKP = (tid & 3) * 2;
    const int bKP = tid >> 5, bCol = (tid & 31) * 4;

    const int lane = tid & 31, wid = tid >> 5;
    const int warpM = (wid >> 2) * 64;
    const int warpN = (wid & 3) * 32;
    const int g = lane >> 2, tg = lane & 3;

    float acc[4][4][4];
    #pragma unroll
    for (int i = 0; i < 4; ++i)
        #pragma unroll
        for (int j = 0; j < 4; ++j)
            #pragma unroll
            for (int c = 0; c < 4; ++c) acc[i][j][c] = 0.f;

    // prologue
    {
        float4 a0 = *(const float4*)&A[(long long)aRow * DIM + aCol];
        float4 a1 = *(const float4*)&A[(long long)(aRow + 64) * DIM + aCol];
        As[0][aKP + 0][aRow] = pack_h2(a0.x, a0.y);
        As[0][aKP + 1][aRow] = pack_h2(a0.z, a0.w);
        As[0][aKP + 0][aRow + 64] = pack_h2(a1.x, a1.y);
        As[0][aKP + 1][aRow + 64] = pack_h2(a1.z, a1.w);
        float4 b0 = *(const float4*)&B[(long long)(2 * bKP) * DIM + bCol];
        float4 b1 = *(const float4*)&B[(long long)(2 * bKP + 1) * DIM + bCol];
        uint4 u = { pack_h2(b0.x, b1.x), pack_h2(b0.y, b1.y),
                    pack_h2(b0.z, b1.z), pack_h2(b0.w, b1.w) };
        *(uint4*)&Bs[0][bKP][bCol] = u;
    }
    __syncthreads();

    for (int kt = 0; kt < 16; ++kt) {
        const int buf = kt & 1;
        float4 pa0, pa1, pb0, pb1;
        if (kt + 1 < 16) {
            const int k0 = (kt + 1) * 16;
            pa0 = *(const float4*)&A[(long long)aRow * DIM + k0 + aCol];
            pa1 = *(const float4*)&A[(long long)(aRow + 64) * DIM + k0 + aCol];
            pb0 = *(const float4*)&B[(long long)(k0 + 2 * bKP) * DIM + bCol];
            pb1 = *(const float4*)&B[(long long)(k0 + 2 * bKP + 1) * DIM + bCol];
        }

        {
            uint32_t af[4][4], bf[4][2];
            #pragma unroll
            for (int mt = 0; mt < 4; ++mt) {
                const int m = warpM + mt * 16;
                af[mt][0] = As[buf][tg][m + g];
                af[mt][1] = As[buf][tg][m + g + 8];
                af[mt][2] = As[buf][tg + 4][m + g];
                af[mt][3] = As[buf][tg + 4][m + g + 8];
            }
            #pragma unroll
            for (int nt = 0; nt < 4; ++nt) {
                const int n = warpN + nt * 8;
                bf[nt][0] = Bs[buf][tg][n + g];
                bf[nt][1] = Bs[buf][tg + 4][n + g];
            }
            #pragma unroll
            for (int mt = 0; mt < 4; ++mt)
                #pragma unroll
                for (int nt = 0; nt < 4; ++nt)
                    mma_f16(acc[mt][nt], af[mt], bf[nt]);
        }

        if (kt + 1 < 16) {
            const int nb = 1 - buf;
            As[nb][aKP + 0][aRow] = pack_h2(pa0.x, pa0.y);
            As[nb][aKP + 1][aRow] = pack_h2(pa0.z, pa0.w);
            As[nb][aKP + 0][aRow + 64] = pack_h2(pa1.x, pa1.y);
            As[nb][aKP + 1][aRow + 64] = pack_h2(pa1.z, pa1.w);
            uint4 u = { pack_h2(pb0.x, pb1.x), pack_h2(pb0.y, pb1.y),
                        pack_h2(pb0.z, pb1.z), pack_h2(pb0.w, pb1.w) };
            *(uint4*)&Bs[nb][bKP][bCol] = u;
            __syncthreads();
        }
    }

    #pragma unroll
    for (int mt = 0; mt < 4; ++mt) {
        const int r0 = warpM + mt * 16 + g;
        #pragma unroll
        for (int nt = 0; nt < 4; ++nt) {
            const int c0 = warpN + nt * 8 + 2 * tg;
            const int gcol = bx * 128 + c0;
            const float bx0 = bias[gcol], bx1 = bias[gcol + 1];
            float2 lo = { acc[mt][nt][0] + bx0, acc[mt][nt][1] + bx1 };
            float2 hi = { acc[mt][nt][2] + bx0, acc[mt][nt][3] + bx1 };
            *(float2*)&C[(long long)r0 * DIM + c0] = lo;
            *(float2*)&C[(long long)(r0 + 8) * DIM + c0] = hi;
        }
    }
}

// ---------------------------------------------------------------------------
extern "C" void kernel_launch(void* const* d_in, const int* in_sizes, int n_in,
                              void* d_out, int out_size)
{
    const float* x      = (const float*)d_in[0];  // [4, 8192, 256]
    const float* w_qkv  = (const float*)d_in[1];  // [256, 1536]
    const float* w_out  = (const float*)d_in[2];  // [512, 256]
    const float* b_out  = (const float*)d_in[3];  // [256]
    float*       out    = (float*)d_out;          // [4, 8192, 256]

    float *part, *dots, *A2, *WfP, *Wf;
    cudaGetSymbolAddress((void**)&part, g_part);
    cudaGetSymbolAddress((void**)&dots, g_dots);
    cudaGetSymbolAddress((void**)&A2,   g_A2);
    cudaGetSymbolAddress((void**)&WfP,  g_WfP);
    cudaGetSymbolAddress((void**)&Wf,   g_Wf);

    cudaFuncSetAttribute(fused_kv_dots,
                         cudaFuncAttributeMaxDynamicSharedMemorySize, FUSED_SMEM);

    // 1) fused: k/v projection + instance norm + partial dots
    fused_kv_dots<<<dim3(32, NCH), 256, FUSED_SMEM>>>(x, w_qkv, part);

    // 2) deterministic chunk reduction
    reduce_dots<<<dim3(32, 8), 256>>>(part, dots);

    // 3) A2 = blockdiag(dots) @ w_out ; Wf[b] = w_q @ A2[b] / n (split-K x8)
    dots_wout<<<dim3(32, 8), 256>>>(dots, w_out, A2);
    wf_gemm_splitk<<<dim3(4, 4, BATCH * KSEG), 256>>>(w_qkv, A2, WfP);
    wf_reduce<<<(BATCH * DIM * DIM) / 256, 256>>>(WfP, Wf);

    // 4) out[b] = x[b] @ Wf[b] + b_out  (fp16 k16 TC)
    gemm_f16<<<dim3(DIM / 128, NTOK / 128, BATCH), 256>>>(x, Wf, b_out, out);
}

// round 16
// speedup vs baseline: 1.6175x; 1.0300x over previous
#include <cuda_runtime.h>
#include <cuda_fp16.h>
#include <cuda_bf16.h>
#include <cstdint>

// ---------------------------------------------------------------------------
// Galerkin linear attention, restructured:
//   [fused] k,v = x @ w_{k,v} (fp16 m16n8k16 mma, fp32 accum);
//           in-register instance norm; partial dots (fp16 hi/lo 3-pass k16)
//   dots = sum_chunks part ; A2 = blockdiag(dots)@w_out ; Wf[b]=w_q@A2[b]/n
//   out[b] = x[b] @ Wf[b] + b_out     (fp16 m16n8k16 mma, fp32 accum)
// Round-16: phase-3 tf32-k8 3-pass -> fp16-k16 3-pass with conflict-free
// (token j, token j+8) k-pairing. Everything else identical to 200.9us champ.
// ---------------------------------------------------------------------------

#define BATCH   4
#define NTOK    8192
#define DIM     256
#define HEADS   8
#define DH      64
#define INNER   512
#define TCH     128                 // tokens per fused chunk
#define NCH     (NTOK / TCH)        // 64
#define KSEG    8                   // split-K segments for Wf

__device__ float g_part[32 * NCH * DH * DH];   // 33.5 MB partial dots
__device__ float g_dots[32 * DH * DH];
__device__ float g_A2[BATCH * INNER * DIM];
__device__ float g_WfP[KSEG * BATCH * DIM * DIM];
__device__ float g_Wf[BATCH * DIM * DIM];

__device__ __forceinline__ uint32_t pack_h2(float a, float b) {
    __half2 h = __floats2half2_rn(a, b);   // a -> low half (element 0)
    return *reinterpret_cast<uint32_t*>(&h);
}

// fp16 hi/lo split of a pair of floats: hi word = (f16(a), f16(b)),
// lo word = (f16(a - f16(a)), f16(b - f16(b))). a in low half.
__device__ __forceinline__ void split_h2pair(float a, float b,
                                             uint32_t& hi, uint32_t& lo) {
    __half ha = __float2half_rn(a);
    __half hb = __float2half_rn(b);
    float la = a - __half2float(ha);
    float lb = b - __half2float(hb);
    __half2 hp = __halves2half2(ha, hb);
    hi = *reinterpret_cast<uint32_t*>(&hp);
    lo = pack_h2(la, lb);
}

__device__ __forceinline__ void mma_f16(float* d, const uint32_t* a, const uint32_t* b) {
    asm volatile(
        "mma.sync.aligned.m16n8k16.row.col.f32.f16.f16.f32 "
        "{%0,%1,%2,%3}, {%4,%5,%6,%7}, {%8,%9}, {%0,%1,%2,%3};"
        : "+f"(d[0]), "+f"(d[1]), "+f"(d[2]), "+f"(d[3])
        : "r"(a[0]), "r"(a[1]), "r"(a[2]), "r"(a[3]), "r"(b[0]), "r"(b[1]));
}

// ===========================================================================
// Fused: k/v projection (fp16 k16 mma) + in-register instance norm +
// fp16 hi/lo partial dots. grid(32, NCH), 256 threads, dynamic smem.
// ===========================================================================
#define PA 136
#define PB 72
#define PS 72
#define FUSED_SMEM (2 * TCH * PS * 4)   // 73728 B (>= staging)

__global__ __launch_bounds__(256, 2) void fused_kv_dots(
    const float* __restrict__ x, const float* __restrict__ w_qkv,
    float* __restrict__ part)
{
    extern __shared__ unsigned char smraw[];
    uint32_t* As = (uint32_t*)smraw;           // [2][8][PA]  (x tile, half2 kpairs)
    uint32_t* Bk = As + 2 * 8 * PA;            // [2][8][PB]
    uint32_t* Bv = Bk + 2 * 8 * PB;
    float* sk = (float*)smraw;                 // [TCH][PS] (aliases staging)
    float* sv = sk + TCH * PS;

    const int tid = threadIdx.x;
    const int bh = blockIdx.x, chunk = blockIdx.y;   // bh fastest (L2 x reuse)
    const int b = bh >> 3, h = bh & 7;

    const float* xA  = x + ((long long)b * NTOK + (long long)chunk * TCH) * DIM;
    const float* wkp = w_qkv + INNER + h * DH;        // stride 3*INNER
    const float* wvp = w_qkv + 2 * INNER + h * DH;

    const int xRow = tid >> 1, xC = (tid & 1) * 8;
    const int xKP = (tid & 1) * 4;
    const int wKP = tid >> 5;
    const int wCc = (tid & 31) * 2;

    const int lane = tid & 31, wid = tid >> 5;
    const int g = lane >> 2, tg = lane & 3;
    const bool isV = (wid >= 4);
    const int warpM = (isV ? wid - 4 : wid) * 32;

    float acc[2][8][4];
    #pragma unroll
    for (int i = 0; i < 2; ++i)
        #pragma unroll
        for (int j = 0; j < 8; ++j)
            #pragma unroll
            for (int c = 0; c < 4; ++c) acc[i][j][c] = 0.f;

    // ---- phase 1: k/v = x @ w (K=256, 16 tiles of 16, double-buffered, fp16)
    float4 pa0, pa1;
    float2 pk0, pk1, pv0, pv1;
    {
        pa0 = *(const float4*)&xA[(long long)xRow * DIM + xC];
        pa1 = *(const float4*)&xA[(long long)xRow * DIM + xC + 4];
        pk0 = *(const float2*)&wkp[(long long)(2 * wKP) * (3 * INNER) + wCc];
        pk1 = *(const float2*)&wkp[(long long)(2 * wKP + 1) * (3 * INNER) + wCc];
        pv0 = *(const float2*)&wvp[(long long)(2 * wKP) * (3 * INNER) + wCc];
        pv1 = *(const float2*)&wvp[(long long)(2 * wKP + 1) * (3 * INNER) + wCc];
    }
    As[(xKP + 0) * PA + xRow] = pack_h2(pa0.x, pa0.y);
    As[(xKP + 1) * PA + xRow] = pack_h2(pa0.z, pa0.w);
    As[(xKP + 2) * PA + xRow] = pack_h2(pa1.x, pa1.y);
    As[(xKP + 3) * PA + xRow] = pack_h2(pa1.z, pa1.w);
    {
        uint2 uk = { pack_h2(pk0.x, pk1.x), pack_h2(pk0.y, pk1.y) };
        uint2 uv = { pack_h2(pv0.x, pv1.x), pack_h2(pv0.y, pv1.y) };
        *(uint2*)&Bk[wKP * PB + wCc] = uk;
        *(uint2*)&Bv[wKP * PB + wCc] = uv;
    }
    __syncthreads();

    const uint32_t* Bsel = isV ? Bv : Bk;

    for (int kt = 0; kt < 16; ++kt) {
        const int buf = kt & 1;
        if (kt + 1 < 16) {
            const int k0 = (kt + 1) * 16;
            pa0 = *(const float4*)&xA[(long long)xRow * DIM + k0 + xC];
            pa1 = *(const float4*)&xA[(long long)xRow * DIM + k0 + xC + 4];
            pk0 = *(const float2*)&wkp[(long long)(k0 + 2 * wKP) * (3 * INNER) + wCc];
            pk1 = *(const float2*)&wkp[(long long)(k0 + 2 * wKP + 1) * (3 * INNER) + wCc];
            pv0 = *(const float2*)&wvp[(long long)(k0 + 2 * wKP) * (3 * INNER) + wCc];
            pv1 = *(const float2*)&wvp[(long long)(k0 + 2 * wKP + 1) * (3 * INNER) + wCc];
        }

        {
            uint32_t af[2][4], bf[8][2];
            #pragma unroll
            for (int mt = 0; mt < 2; ++mt) {
                const int m = warpM + mt * 16;
                af[mt][0] = As[(buf * 8 + tg) * PA + m + g];
                af[mt][1] = As[(buf * 8 + tg) * PA + m + g + 8];
                af[mt][2] = As[(buf * 8 + tg + 4) * PA + m + g];
                af[mt][3] = As[(buf * 8 + tg + 4) * PA + m + g + 8];
            }
            #pragma unroll
            for (int nt = 0; nt < 8; ++nt) {
                bf[nt][0] = Bsel[(buf * 8 + tg) * PB + nt * 8 + g];
                bf[nt][1] = Bsel[(buf * 8 + tg + 4) * PB + nt * 8 + g];
            }
            #pragma unroll
            for (int mt = 0; mt < 2; ++mt)
                #pragma unroll
                for (int nt = 0; nt < 8; ++nt)
                    mma_f16(acc[mt][nt], af[mt], bf[nt]);
        }

        if (kt + 1 < 16) {
            const int nb = 1 - buf;
            As[(nb * 8 + xKP + 0) * PA + xRow] = pack_h2(pa0.x, pa0.y);
            As[(nb * 8 + xKP + 1) * PA + xRow] = pack_h2(pa0.z, pa0.w);
            As[(nb * 8 + xKP + 2) * PA + xRow] = pack_h2(pa1.x, pa1.y);
            As[(nb * 8 + xKP + 3) * PA + xRow] = pack_h2(pa1.z, pa1.w);
            uint2 uk = { pack_h2(pk0.x, pk1.x), pack_h2(pk0.y, pk1.y) };
            uint2 uv = { pack_h2(pv0.x, pv1.x), pack_h2(pv0.y, pv1.y) };
            *(uint2*)&Bk[(nb * 8 + wKP) * PB + wCc] = uk;
            *(uint2*)&Bv[(nb * 8 + wKP) * PB + wCc] = uv;
            __syncthreads();
        }
    }

    __syncthreads();

    // ---- phase 2: in-register instance norm ----
    float* sdst = isV ? sv : sk;
    #pragma unroll
    for (int mt = 0; mt < 2; ++mt) {
        #pragma unroll
        for (int rr = 0; rr < 2; ++rr) {
            float s = 0.f, q = 0.f;
            #pragma unroll
            for (int nt = 0; nt < 8; ++nt) {
                float v0 = acc[mt][nt][2 * rr], v1 = acc[mt][nt][2 * rr + 1];
                s += v0 + v1;
                q += v0 * v0 + v1 * v1;
            }
            s += __shfl_xor_sync(0xFFFFFFFFu, s, 1);
            s += __shfl_xor_sync(0xFFFFFFFFu, s, 2);
            q += __shfl_xor_sync(0xFFFFFFFFu, q, 1);
            q += __shfl_xor_sync(0xFFFFFFFFu, q, 2);
            const float mu  = s * (1.0f / 64.0f);
            const float var = q * (1.0f / 64.0f) - mu * mu;
            const float inv = rsqrtf(var + 1e-5f);
            const int row = warpM + mt * 16 + g + rr * 8;
            #pragma unroll
            for (int nt = 0; nt < 8; ++nt) {
                float2 o = { (acc[mt][nt][2 * rr] - mu) * inv,
                             (acc[mt][nt][2 * rr + 1] - mu) * inv };
                *(float2*)&sdst[row * PS + nt * 8 + 2 * tg] = o;
            }
        }
    }
    __syncthreads();

    // ---- phase 3: partial dots = k-hat^T @ v-hat (fp16 hi/lo 3-pass, k16) --
    // warp tile: m-tile mw = (wid>>1)*16, n-half nh = (wid&1)*32.
    // k-pairing: kpair j = (token kk+j, token kk+j+8)  [conflict-free rows]
    const int mw = (wid >> 1) * 16;
    const int nh = (wid & 1) * 32;
    float d[4][4];
    #pragma unroll
    for (int nt = 0; nt < 4; ++nt)
        #pragma unroll
        for (int c = 0; c < 4; ++c) d[nt][c] = 0.f;

    for (int kk = 0; kk < TCH; kk += 16) {
        uint32_t ah[4], al[4], bhv[4][2], blv[4][2];
        {
            float t0 = sk[(kk + tg) * PS + mw + g];
            float t1 = sk[(kk + tg + 8) * PS + mw + g];
            float t2 = sk[(kk + tg) * PS + mw + g + 8];
            float t3 = sk[(kk + tg + 8) * PS + mw + g + 8];
            float t4 = sk[(kk + tg + 4) * PS + mw + g];
            float t5 = sk[(kk + tg + 12) * PS + mw + g];
            float t6 = sk[(kk + tg + 4) * PS + mw + g + 8];
            float t7 = sk[(kk + tg + 12) * PS + mw + g + 8];
            split_h2pair(t0, t1, ah[0], al[0]);
            split_h2pair(t2, t3, ah[1], al[1]);
            split_h2pair(t4, t5, ah[2], al[2]);
            split_h2pair(t6, t7, ah[3], al[3]);
        }
        #pragma unroll
        for (int nt = 0; nt < 4; ++nt) {
            const int c = nh + nt * 8 + g;
            split_h2pair(sv[(kk + tg) * PS + c], sv[(kk + tg + 8) * PS + c],
                         bhv[nt][0], blv[nt][0]);
            split_h2pair(sv[(kk + tg + 4) * PS + c], sv[(kk + tg + 12) * PS + c],
                         bhv[nt][1], blv[nt][1]);
        }
        #pragma unroll
        for (int nt = 0; nt < 4; ++nt) mma_f16(d[nt], ah, bhv[nt]);
        #pragma unroll
        for (int nt = 0; nt < 4; ++nt) mma_f16(d[nt], ah, blv[nt]);
        #pragma unroll
        for (int nt = 0; nt < 4; ++nt) mma_f16(d[nt], al, bhv[nt]);
    }

    float* op = part + (long long)(bh * NCH + chunk) * (DH * DH);
    #pragma unroll
    for (int nt = 0; nt < 4; ++nt) {
        const int e = mw + g;
        const int c = nh + nt * 8 + 2 * tg;
        float2 lo = { d[nt][0], d[nt][1] };
        float2 hi = { d[nt][2], d[nt][3] };
        *(float2*)&op[e * DH + c] = lo;
        *(float2*)&op[(e + 8) * DH + c] = hi;
    }
}

// ===========================================================================
__global__ __launch_bounds__(256) void reduce_dots(
    const float* __restrict__ part, float* __restrict__ dots)
{
    const int bh = blockIdx.x, seg = blockIdx.y;   // grid (32,8)
    #pragma unroll
    for (int j = 0; j < 2; ++j) {
        const int idx = seg * 512 + j * 256 + threadIdx.x;
        float s = 0.f;
        #pragma unroll 8
        for (int c = 0; c < NCH; ++c)
            s += part[(long long)(bh * NCH + c) * (DH * DH) + idx];
        dots[bh * DH * DH + idx] = s;
    }
}

// A2[b, h*64+e, j] = sum_f dots[b,h][e,f] * w_out[h*64+f, j]; grid (32, 8)
__global__ __launch_bounds__(256) void dots_wout(
    const float* __restrict__ dots, const float* __restrict__ w_out,
    float* __restrict__ A2)
{
    const int bh = blockIdx.x, jt = blockIdx.y;
    const int b = bh >> 3, h = bh & 7;
    __shared__ float sd[DH * DH];
    __shared__ float sw[DH][33];
    for (int i = threadIdx.x; i < DH * DH; i += 256) sd[i] = dots[bh * DH * DH + i];
    for (int i = threadIdx.x; i < DH * 32; i += 256) {
        const int f = i >> 5, j = i & 31;
        sw[f][j] = w_out[(h * DH + f) * DIM + jt * 32 + j];
    }
    __syncthreads();
    for (int idx = threadIdx.x; idx < DH * 32; idx += 256) {
        const int e = idx >> 5, j = idx & 31;
        float s = 0.f;
        #pragma unroll 8
        for (int f = 0; f < DH; ++f) s += sd[e * DH + f] * sw[f][j];
        A2[((long long)b * INNER + h * DH + e) * DIM + jt * 32 + j] = s;
    }
}

// ===========================================================================
// WfP[seg][b] = w_q[:, seg*64:(seg+1)*64] @ A2[b][seg*64:(seg+1)*64, :]
// grid (4 jt, 4 mt, BATCH*KSEG=32) = 512 blocks. 64x64 tile, BK=16, fp32.
// ===========================================================================
__global__ __launch_bounds__(256) void wf_gemm_splitk(
    const float* __restrict__ w_qkv, const float* __restrict__ A2,
    float* __restrict__ WfP)
{
    __shared__ float sA[16][68];
    __shared__ float sB[16][68];

    const int tid = threadIdx.x;
    const int m0 = blockIdx.y * 64, j0 = blockIdx.x * 64;
    const int bz = blockIdx.z;
    const int b = bz >> 3, seg = bz & 7;
    const int kbase = seg * (INNER / KSEG);          // seg*64

    const float* Bb = A2 + (long long)b * INNER * DIM;

    const int am = tid >> 2, akq = (tid & 3) * 4;
    const int bk = tid >> 4, bj = (tid & 15) * 4;
    const int ty = (tid >> 4) << 2;
    const int tx = (tid & 15) << 2;

    float acc[4][4] = {};

    for (int k0 = 0; k0 < INNER / KSEG; k0 += 16) {
        float4 a4 = *(const float4*)&w_qkv[(long long)(m0 + am) * (3 * INNER) + kbase + k0 + akq];
        sA[akq + 0][am] = a4.x;
        sA[akq + 1][am] = a4.y;
        sA[akq + 2][am] = a4.z;
        sA[akq + 3][am] = a4.w;
        float4 b4 = *(const float4*)&Bb[(long long)(kbase + k0 + bk) * DIM + j0 + bj];
        *(float4*)&sB[bk][bj] = b4;
        __syncthreads();
        #pragma unroll
        for (int kk = 0; kk < 16; ++kk) {
            float a[4], bb[4];
            #pragma unroll
            for (int i = 0; i < 4; ++i) a[i] = sA[kk][ty + i];
            #pragma unroll
            for (int j = 0; j < 4; ++j) bb[j] = sB[kk][tx + j];
            #pragma unroll
            for (int i = 0; i < 4; ++i)
                #pragma unroll
                for (int j = 0; j < 4; ++j) acc[i][j] += a[i] * bb[j];
        }
        __syncthreads();
    }

    float* C = WfP + ((long long)bz) * DIM * DIM;
    #pragma unroll
    for (int i = 0; i < 4; ++i) {
        float4 o = { acc[i][0], acc[i][1], acc[i][2], acc[i][3] };
        *(float4*)&C[(long long)(m0 + ty + i) * DIM + j0 + tx] = o;
    }
}

__global__ __launch_bounds__(256) void wf_reduce(
    const float* __restrict__ WfP, float* __restrict__ Wf)
{
    const int idx = blockIdx.x * 256 + threadIdx.x;
    const int b = idx / (DIM * DIM);
    const int r = idx % (DIM * DIM);
    float s = 0.f;
    #pragma unroll
    for (int seg = 0; seg < KSEG; ++seg)
        s += WfP[((long long)(b * KSEG + seg)) * DIM * DIM + r];
    Wf[idx] = s * (1.0f / (float)NTOK);
}

// ===========================================================================
// Final GEMM: out[b] = x[b] @ Wf[b] + b_out  (fp16 m16n8k16, fp32 accum)
// ===========================================================================
__global__ __launch_bounds__(256, 2) void gemm_f16(
    const float* __restrict__ x, const float* __restrict__ Wf,
    const float* __restrict__ bias, float* __restrict__ out)
{
    __shared__ uint32_t As[2][8][132];   // [kpair][m]
    __shared__ uint32_t Bs[2][8][132];   // [kpair][n]

    const int tid = threadIdx.x;
    const int bx = blockIdx.x, by = blockIdx.y, bz = blockIdx.z;

    const float* A = x + (long long)bz * NTOK * DIM + (long long)by * 128 * DIM;
    const float* B = Wf + (long long)bz * DIM * DIM + (long long)bx * 128;
    float* C = out + (long long)bz * NTOK * DIM + (long long)by * 128 * DIM
                   + (long long)bx * 128;

    const int aRow = tid >> 2, aCol = (tid & 3) * 4, aKP = (tid & 3) * 2;
    const int bKP = tid >> 5, bCol = (tid & 31) * 4;

    const int lane = tid & 31, wid = tid >> 5;
    const int warpM = (wid >> 2) * 64;
    const int warpN = (wid & 3) * 32;
    const int g = lane >> 2, tg = lane & 3;

    float acc[4][4][4];
    #pragma unroll
    for (int i = 0; i < 4; ++i)
        #pragma unroll
        for (int j = 0; j < 4; ++j)
            #pragma unroll
            for (int c = 0; c < 4; ++c) acc[i][j][c] = 0.f;

    // prologue
    {
        float4 a0 = *(const float4*)&A[(long long)aRow * DIM + aCol];
        float4 a1 = *(const float4*)&A[(long long)(aRow + 64) * DIM + aCol];
        As[0][aKP + 0][aRow] = pack_h2(a0.x, a0.y);
        As[0][aKP + 1][aRow] = pack_h2(a0.z, a0.w);
        As[0][aKP + 0][aRow + 64] = pack_h2(a1.x, a1.y);
        As[0][aKP + 1][aRow + 64] = pack_h2(a1.z, a1.w);
        float4 b0 = *(const float4*)&B[(long long)(2 * bKP) * DIM + bCol];
        float4 b1 = *(const float4*)&B[(long long)(2 * bKP + 1) * DIM + bCol];
        uint4 u = { pack_h2(b0.x, b1.x), pack_h2(b0.y, b1.y),
                    pack_h2(b0.z, b1.z), pack_h2(b0.w, b1.w) };
        *(uint4*)&Bs[0][bKP][bCol] = u;
    }
    __syncthreads();

    for (int kt = 0; kt < 16; ++kt) {
        const int buf = kt & 1;
        float4 pa0, pa1, pb0, pb1;
        if (kt + 1 < 16) {
            const int k0 = (kt + 1) * 16;
            pa0 = *(const float4*)&A[(long long)aRow * DIM + k0 + aCol];
            pa1 = *(const float4*)&A[(long long)(aRow + 64) * DIM + k0 + aCol];
            pb0 = *(const float4*)&B[(long long)(k0 + 2 * bKP) * DIM + bCol];
            pb1 = *(const float4*)&B[(long long)(k0 + 2 * bKP + 1) * DIM + bCol];
        }

        {
            uint32_t af[4][4], bf[4][2];
            #pragma unroll
            for (int mt = 0; mt < 4; ++mt) {
                const int m = warpM + mt * 16;
                af[mt][0] = As[buf][tg][m + g];
                af[mt][1] = As[buf][tg][m + g + 8];
                af[mt][2] = As[buf][tg + 4][m + g];
                af[mt][3] = As[buf][tg + 4][m + g + 8];
            }
            #pragma unroll
            for (int nt = 0; nt < 4; ++nt) {
                const int n = warpN + nt * 8;
                bf[nt][0] = Bs[buf][tg][n + g];
                bf[nt][1] = Bs[buf][tg + 4][n + g];
            }
            #pragma unroll
            for (int mt = 0; mt < 4; ++mt)
                #pragma unroll
                for (int nt = 0; nt < 4; ++nt)
                    mma_f16(acc[mt][nt], af[mt], bf[nt]);
        }

        if (kt + 1 < 16) {
            const int nb = 1 - buf;
            As[nb][aKP + 0][aRow] = pack_h2(pa0.x, pa0.y);
            As[nb][aKP + 1][aRow] = pack_h2(pa0.z, pa0.w);
            As[nb][aKP + 0][aRow + 64] = pack_h2(pa1.x, pa1.y);
            As[nb][aKP + 1][aRow + 64] = pack_h2(pa1.z, pa1.w);
            uint4 u = { pack_h2(pb0.x, pb1.x), pack_h2(pb0.y, pb1.y),
                        pack_h2(pb0.z, pb1.z), pack_h2(pb0.w, pb1.w) };
            *(uint4*)&Bs[nb][bKP][bCol] = u;
            __syncthreads();
        }
    }

    #pragma unroll
    for (int mt = 0; mt < 4; ++mt) {
        const int r0 = warpM + mt * 16 + g;
        #pragma unroll
        for (int nt = 0; nt < 4; ++nt) {
            const int c0 = warpN + nt * 8 + 2 * tg;
            const int gcol = bx * 128 + c0;
            const float bx0 = bias[gcol], bx1 = bias[gcol + 1];
            float2 lo = { acc[mt][nt][0] + bx0, acc[mt][nt][1] + bx1 };
            float2 hi = { acc[mt][nt][2] + bx0, acc[mt][nt][3] + bx1 };
            *(float2*)&C[(long long)r0 * DIM + c0] = lo;
            *(float2*)&C[(long long)(r0 + 8) * DIM + c0] = hi;
        }
    }
}

// ---------------------------------------------------------------------------
extern "C" void kernel_launch(void* const* d_in, const int* in_sizes, int n_in,
                              void* d_out, int out_size)
{
    const float* x      = (const float*)d_in[0];  // [4, 8192, 256]
    const float* w_qkv  = (const float*)d_in[1];  // [256, 1536]
    const float* w_out  = (const float*)d_in[2];  // [512, 256]
    const float* b_out  = (const float*)d_in[3];  // [256]
    float*       out    = (float*)d_out;          // [4, 8192, 256]

    float *part, *dots, *A2, *WfP, *Wf;
    cudaGetSymbolAddress((void**)&part, g_part);
    cudaGetSymbolAddress((void**)&dots, g_dots);
    cudaGetSymbolAddress((void**)&A2,   g_A2);
    cudaGetSymbolAddress((void**)&WfP,  g_WfP);
    cudaGetSymbolAddress((void**)&Wf,   g_Wf);

    cudaFuncSetAttribute(fused_kv_dots,
                         cudaFuncAttributeMaxDynamicSharedMemorySize, FUSED_SMEM);

    // 1) fused: k/v projection + instance norm + partial dots
    fused_kv_dots<<<dim3(32, NCH), 256, FUSED_SMEM>>>(x, w_qkv, part);

    // 2) deterministic chunk reduction
    reduce_dots<<<dim3(32, 8), 256>>>(part, dots);

    // 3) A2 = blockdiag(dots) @ w_out ; Wf[b] = w_q @ A2[b] / n (split-K x8)
    dots_wout<<<dim3(32, 8), 256>>>(dots, w_out, A2);
    wf_gemm_splitk<<<dim3(4, 4, BATCH * KSEG), 256>>>(w_qkv, A2, WfP);
    wf_reduce<<<(BATCH * DIM * DIM) / 256, 256>>>(WfP, Wf);

    // 4) out[b] = x[b] @ Wf[b] + b_out  (fp16 k16 TC)
    gemm_f16<<<dim3(DIM / 128, NTOK / 128, BATCH), 256>>>(x, Wf, b_out, out);
}